// round 6
// baseline (speedup 1.0000x reference)
#include <cuda_runtime.h>
#include <cuda_fp16.h>
#include <math.h>
#include <cstdint>

// ---------------- problem constants ----------------
#define Vv   30522
#define Hh   768
#define Ll   12
#define FFf  3072
#define NHh  12
#define DHh  64
#define Bb   32
#define Ss   128
#define NLl  10000
#define NTOK (Bb*Ss)          // 4096
#define QKVN (3*Hh)           // 2304
#define EPS_LN  1e-12f
#define EPS_COS 1e-8f

// transposed fp16 weight layout per layer (element offsets)
#define OFF_O   (QKVN*Hh)             // after packed qkv [2304][768]
#define OFF_W1  (OFF_O + Hh*Hh)       // [3072][768]
#define OFF_W2  (OFF_W1 + Hh*FFf)     // [768][3072]
#define LSTRIDE (OFF_W2 + FFf*Hh)     // 7,077,888

// ---------------- device scratch ----------------
__device__ __half g_wth[Ll*LSTRIDE];           // fp16 weights, transposed [N][K]
__device__ float  g_bqkv[Ll*QKVN];

__device__ float  g_x  [NTOK*Hh];
__device__ __half g_xhi[NTOK*Hh];
__device__ __half g_xlo[NTOK*Hh];
__device__ float  g_qkv[NTOK*QKVN];
__device__ __half g_chi[NTOK*Hh];
__device__ __half g_clo[NTOK*Hh];
__device__ __half g_hhi[NTOK*FFf];
__device__ __half g_hlo[NTOK*FFf];
__device__ float  g_y  [NTOK*Hh];
__device__ float g_mbias[NTOK];
__device__ float g_cls[Bb*Hh];
__device__ float g_cn [Bb];
__device__ unsigned long long g_best[Bb];

// ---------------- PTX helpers (compute_100-safe) ----------------
__device__ __forceinline__ uint32_t smem_u32(const void* p) {
    uint32_t a;
    asm("{ .reg .u64 t; cvta.to.shared.u64 t, %1; cvt.u32.u64 %0, t; }" : "=r"(a) : "l"(p));
    return a;
}
__device__ __forceinline__ void cp_async16(uint32_t dst, const void* src) {
    asm volatile("cp.async.cg.shared.global [%0], [%1], 16;" :: "r"(dst), "l"(src) : "memory");
}
#define CP_COMMIT() asm volatile("cp.async.commit_group;" ::: "memory")
#define CP_WAIT(n)  asm volatile("cp.async.wait_group %0;" :: "n"(n) : "memory")

__device__ __forceinline__ void ldsm4(uint32_t& r0, uint32_t& r1, uint32_t& r2, uint32_t& r3,
                                      uint32_t addr) {
    asm volatile("ldmatrix.sync.aligned.m8n8.x4.shared.b16 {%0,%1,%2,%3}, [%4];"
                 : "=r"(r0), "=r"(r1), "=r"(r2), "=r"(r3) : "r"(addr));
}
__device__ __forceinline__ void mma16816(float* c, uint32_t a0, uint32_t a1, uint32_t a2,
                                         uint32_t a3, uint32_t b0, uint32_t b1) {
    asm volatile(
        "mma.sync.aligned.m16n8k16.row.col.f32.f16.f16.f32 "
        "{%0,%1,%2,%3}, {%4,%5,%6,%7}, {%8,%9}, {%0,%1,%2,%3};"
        : "+f"(c[0]), "+f"(c[1]), "+f"(c[2]), "+f"(c[3])
        : "r"(a0), "r"(a1), "r"(a2), "r"(a3), "r"(b0), "r"(b1));
}

// ---------------- misc helpers ----------------
__device__ __forceinline__ float blk_sum256(float v, volatile float* sred) {
    int lane = threadIdx.x & 31, w = threadIdx.x >> 5;
    #pragma unroll
    for (int o = 16; o > 0; o >>= 1) v += __shfl_down_sync(0xffffffffu, v, o);
    if (lane == 0) sred[w] = v;
    __syncthreads();
    if (threadIdx.x == 0) {
        float s = 0.f;
        #pragma unroll
        for (int i = 0; i < 8; i++) s += sred[i];
        sred[8] = s;
    }
    __syncthreads();
    float r = sred[8];
    __syncthreads();
    return r;
}
__device__ __forceinline__ float gelu_tanh(float x) {
    float x3 = x * x * x;
    float t = tanhf(0.7978845608028654f * (x + 0.044715f * x3));
    return 0.5f * x * (1.0f + t);
}
__device__ __forceinline__ unsigned long long pack_key(float c, int l) {
    unsigned u = __float_as_uint(c);
    u = (u & 0x80000000u) ? ~u : (u | 0x80000000u);
    return ((unsigned long long)u << 32) | (unsigned long long)(0xFFFFFFFFu - (unsigned)l);
}
__device__ __forceinline__ void split_store_h(float v, __half* hi, __half* lo) {
    __half h = __float2half(v);
    *hi = h;
    *lo = __float2half(v - __half2float(h));
}
__device__ __forceinline__ unsigned pack2h(float v0, float v1) {
    __half h0 = __float2half(v0), h1 = __float2half(v1);
    return (unsigned)__half_as_ushort(h0) | ((unsigned)__half_as_ushort(h1) << 16);
}

// ---------------- weight transpose to fp16 ----------------
// 4 matrices of [L][768][768]: Wq, Wk, Wv (packed qkv), Wo
__global__ void wsplit4_kernel(const float* __restrict__ W0, const float* __restrict__ W1m,
                               const float* __restrict__ W2m, const float* __restrict__ W3m) {
    __shared__ float t[32][33];
    int z = blockIdx.z;
    int m = z & 3, l = z >> 2;
    const float* Ws = (m == 0 ? W0 : m == 1 ? W1m : m == 2 ? W2m : W3m) + (size_t)l * Hh * Hh;
    long dstOff = (m < 3) ? (long)m * Hh * Hh : (long)OFF_O;
    __half* th = g_wth + (size_t)l * LSTRIDE + dstOff;
    int n = blockIdx.x * 32 + threadIdx.x;
    #pragma unroll
    for (int i = 0; i < 4; i++) {
        int k = blockIdx.y * 32 + threadIdx.y + i * 8;
        t[threadIdx.y + i * 8][threadIdx.x] = Ws[(size_t)k * Hh + n];
    }
    __syncthreads();
    int k2 = blockIdx.y * 32 + threadIdx.x;
    #pragma unroll
    for (int i = 0; i < 4; i++) {
        int n2 = blockIdx.x * 32 + threadIdx.y + i * 8;
        th[(size_t)n2 * Hh + k2] = __float2half(t[threadIdx.x][threadIdx.y + i * 8]);
    }
}

// generic: W [L][K][N] -> g_wth + l*LSTRIDE + dstOff as [N][K] fp16
__global__ void wsplit_kernel(const float* __restrict__ W, long dstOff, int K, int N) {
    __shared__ float t[32][33];
    int l = blockIdx.z;
    const float* Ws = W + (size_t)l * K * N;
    __half* th = g_wth + (size_t)l * LSTRIDE + dstOff;
    int n = blockIdx.x * 32 + threadIdx.x;
    #pragma unroll
    for (int i = 0; i < 4; i++) {
        int k = blockIdx.y * 32 + threadIdx.y + i * 8;
        t[threadIdx.y + i * 8][threadIdx.x] = Ws[(size_t)k * N + n];
    }
    __syncthreads();
    int k2 = blockIdx.y * 32 + threadIdx.x;
    #pragma unroll
    for (int i = 0; i < 4; i++) {
        int n2 = blockIdx.x * 32 + threadIdx.y + i * 8;
        th[(size_t)n2 * K + k2] = __float2half(t[threadIdx.x][threadIdx.y + i * 8]);
    }
}

__global__ void pack_bias_kernel(const float* __restrict__ bq, const float* __restrict__ bk,
                                 const float* __restrict__ bv) {
    int l = blockIdx.x, j = threadIdx.x;
    g_bqkv[l * QKVN + j]          = bq[l * Hh + j];
    g_bqkv[l * QKVN + Hh + j]     = bk[l * Hh + j];
    g_bqkv[l * QKVN + 2 * Hh + j] = bv[l * Hh + j];
}

// ---------------- embeddings + LN + mask bias ----------------
__global__ void embed_ln_kernel(const int* __restrict__ ids, const int* __restrict__ tys,
                                const float* __restrict__ word, const float* __restrict__ pos,
                                const float* __restrict__ typ,
                                const float* __restrict__ eg, const float* __restrict__ eb) {
    __shared__ float sred[9];
    int t = blockIdx.x;
    int s = t & (Ss - 1);
    int id = ids[t], ty = tys[t];
    float v[3];
    float loc = 0.f;
    #pragma unroll
    for (int i = 0; i < 3; i++) {
        int j = threadIdx.x + i * 256;
        v[i] = word[(size_t)id * Hh + j] + pos[(size_t)s * Hh + j] + typ[(size_t)ty * Hh + j];
        loc += v[i];
    }
    float mu = blk_sum256(loc, sred) * (1.0f / Hh);
    float l2 = 0.f;
    #pragma unroll
    for (int i = 0; i < 3; i++) { float d = v[i] - mu; l2 += d * d; }
    float var = blk_sum256(l2, sred) * (1.0f / Hh);
    float rstd = rsqrtf(var + EPS_LN);
    #pragma unroll
    for (int i = 0; i < 3; i++) {
        int j = threadIdx.x + i * 256;
        size_t idx = (size_t)t * Hh + j;
        float o = (v[i] - mu) * rstd * eg[j] + eb[j];
        g_x[idx] = o;
        split_store_h(o, &g_xhi[idx], &g_xlo[idx]);
    }
    if (threadIdx.x == 0) g_mbias[t] = (id > 0) ? 0.f : -10000.0f;
}

// ---------------- residual add + LN (in place on x), fused fp16 split ----------------
__global__ void add_ln_kernel(float* __restrict__ x, const float* __restrict__ y,
                              const float* __restrict__ g, const float* __restrict__ b) {
    __shared__ float sred[9];
    size_t base = (size_t)blockIdx.x * Hh;
    float v[3];
    float loc = 0.f;
    #pragma unroll
    for (int i = 0; i < 3; i++) {
        int j = threadIdx.x + i * 256;
        v[i] = x[base + j] + y[base + j];
        loc += v[i];
    }
    float mu = blk_sum256(loc, sred) * (1.0f / Hh);
    float l2 = 0.f;
    #pragma unroll
    for (int i = 0; i < 3; i++) { float d = v[i] - mu; l2 += d * d; }
    float var = blk_sum256(l2, sred) * (1.0f / Hh);
    float rstd = rsqrtf(var + EPS_LN);
    #pragma unroll
    for (int i = 0; i < 3; i++) {
        int j = threadIdx.x + i * 256;
        float o = (v[i] - mu) * rstd * g[j] + b[j];
        x[base + j] = o;
        split_store_h(o, &g_xhi[base + j], &g_xlo[base + j]);
    }
}

// ---------------- HMMA 2-term fp16 GEMM: C[4096, N] = (Ah+Al) @ Bh^T + bias ----------------
// A: hi/lo fp16 [M][K] (activations, exact to 2^-22); B: fp16 [N][K] (weights).
// CTA 128x128, K-chunk 32, 3-stage cp.async pipeline (one __syncthreads per chunk),
// 8 warps (warp tile 64x32), 2 CTAs/SM.
#define GT_TILE  (128 * 80)        // bytes per sub-tile (32 fp16 cols padded to 80B rows)
#define GT_STAGE (3 * GT_TILE)     // Ah | Al | Bh = 30720
#define NSTAGE   3
#define GSMEM    (NSTAGE * GT_STAGE)   // 92160
template <int OUTMODE>
__global__ void __launch_bounds__(256, 2) gemm_mma(
    const __half* __restrict__ Ahi, const __half* __restrict__ Alo,
    const __half* __restrict__ Bh,
    const float* __restrict__ bias,
    float* __restrict__ Cf, __half* __restrict__ Chi, __half* __restrict__ Clo,
    int K, int ldc)
{
    extern __shared__ char sm[];
    const uint32_t sb = smem_u32(sm);
    int tid = threadIdx.x, lane = tid & 31, wid = tid >> 5;
    int wm = wid >> 2, wn = wid & 3;              // warp tile rows wm*64, cols wn*32
    int m0 = blockIdx.y * 128, n0 = blockIdx.x * 128;

    // ldmatrix lane offsets
    int q = lane >> 3, r = lane & 7;
    uint32_t aLane = (uint32_t)(((q & 1) * 8 + r) * 80 + (q >> 1) * 16);
    uint32_t bLane = (uint32_t)(((q >> 1) * 8 + r) * 80 + (q & 1) * 16);

    float acc[4][4][4];
    #pragma unroll
    for (int mi = 0; mi < 4; mi++)
        #pragma unroll
        for (int ni = 0; ni < 4; ni++)
            #pragma unroll
            for (int e = 0; e < 4; e++) acc[mi][ni][e] = 0.f;

    int nchunk = K >> 5;

    // loader: 1536 x 16B per stage; 6 per thread
    auto load_stage = [&](int c) {
        int k0 = c << 5;
        uint32_t base = sb + (uint32_t)(c % NSTAGE) * GT_STAGE;
        #pragma unroll
        for (int i = 0; i < 6; i++) {
            int lin = tid + i * 256;              // 0..1535
            int tile = lin >> 9;                  // 0=Ah 1=Al 2=Bh
            int within = lin & 511;
            int row = within >> 2, seg = within & 3;
            uint32_t dst = base + (uint32_t)tile * GT_TILE + (uint32_t)(row * 80 + seg * 16);
            const __half* src;
            if (tile == 0)      src = Ahi + (size_t)(m0 + row) * K + k0 + seg * 8;
            else if (tile == 1) src = Alo + (size_t)(m0 + row) * K + k0 + seg * 8;
            else                src = Bh  + (size_t)(n0 + row) * K + k0 + seg * 8;
            cp_async16(dst, src);
        }
    };

    // prefetch stages 0 and 1
    load_stage(0); CP_COMMIT();
    load_stage(1); CP_COMMIT();

    for (int c = 0; c < nchunk; c++) {
        CP_WAIT(1);                 // stage c complete
        __syncthreads();            // all warps done with stage c-1 (overwritten below)
        if (c + 2 < nchunk) load_stage(c + 2);
        CP_COMMIT();                // commit (possibly empty) keeps group count exact

        uint32_t base = sb + (uint32_t)(c % NSTAGE) * GT_STAGE;
        uint32_t aBaseH = base + (uint32_t)((wm * 64) * 80) + aLane;
        uint32_t aBaseL = aBaseH + GT_TILE;
        uint32_t bBase  = base + 2 * GT_TILE + (uint32_t)((wn * 32) * 80) + bLane;

        #pragma unroll
        for (int ks = 0; ks < 2; ks++) {
            uint32_t ko = (uint32_t)(ks * 32);
            uint32_t ah[4][4], al[4][4], bf[2][4];
            #pragma unroll
            for (int mi = 0; mi < 4; mi++)
                ldsm4(ah[mi][0], ah[mi][1], ah[mi][2], ah[mi][3],
                      aBaseH + (uint32_t)(mi * 16 * 80) + ko);
            #pragma unroll
            for (int mi = 0; mi < 4; mi++)
                ldsm4(al[mi][0], al[mi][1], al[mi][2], al[mi][3],
                      aBaseL + (uint32_t)(mi * 16 * 80) + ko);
            #pragma unroll
            for (int p = 0; p < 2; p++)
                ldsm4(bf[p][0], bf[p][1], bf[p][2], bf[p][3],
                      bBase + (uint32_t)(p * 16 * 80) + ko);
            #pragma unroll
            for (int mi = 0; mi < 4; mi++)
                #pragma unroll
                for (int ni = 0; ni < 4; ni++) {
                    int p = ni >> 1, su = ni & 1;
                    mma16816(acc[mi][ni], ah[mi][0], ah[mi][1], ah[mi][2], ah[mi][3],
                             bf[p][su * 2], bf[p][su * 2 + 1]);
                }
            #pragma unroll
            for (int mi = 0; mi < 4; mi++)
                #pragma unroll
                for (int ni = 0; ni < 4; ni++) {
                    int p = ni >> 1, su = ni & 1;
                    mma16816(acc[mi][ni], al[mi][0], al[mi][1], al[mi][2], al[mi][3],
                             bf[p][su * 2], bf[p][su * 2 + 1]);
                }
        }
        __syncwarp();
    }

    // ---------------- epilogue ----------------
    int rbase = m0 + wm * 64 + (lane >> 2);
    int cbase = n0 + wn * 32 + (lane & 3) * 2;
    #pragma unroll
    for (int mi = 0; mi < 4; mi++) {
        #pragma unroll
        for (int ni = 0; ni < 4; ni++) {
            int row = rbase + mi * 16;
            int col = cbase + ni * 8;
            float b0 = bias[col], b1 = bias[col + 1];
            float v0 = acc[mi][ni][0] + b0, v1 = acc[mi][ni][1] + b1;
            float v2 = acc[mi][ni][2] + b0, v3 = acc[mi][ni][3] + b1;
            if (OUTMODE == 0) {
                *(float2*)(Cf + (size_t)row * ldc + col)       = make_float2(v0, v1);
                *(float2*)(Cf + (size_t)(row + 8) * ldc + col) = make_float2(v2, v3);
            } else {
                v0 = gelu_tanh(v0); v1 = gelu_tanh(v1);
                v2 = gelu_tanh(v2); v3 = gelu_tanh(v3);
                __half h0 = __float2half(v0), h1 = __float2half(v1);
                __half h2 = __float2half(v2), h3 = __float2half(v3);
                *(unsigned*)(Chi + (size_t)row * ldc + col) =
                    (unsigned)__half_as_ushort(h0) | ((unsigned)__half_as_ushort(h1) << 16);
                *(unsigned*)(Clo + (size_t)row * ldc + col) =
                    pack2h(v0 - __half2float(h0), v1 - __half2float(h1));
                *(unsigned*)(Chi + (size_t)(row + 8) * ldc + col) =
                    (unsigned)__half_as_ushort(h2) | ((unsigned)__half_as_ushort(h3) << 16);
                *(unsigned*)(Clo + (size_t)(row + 8) * ldc + col) =
                    pack2h(v2 - __half2float(h2), v3 - __half2float(h3));
            }
        }
    }
}

// ---------------- attention: one-pass, scores cached in smem ----------------
#define ATTN_SMEM ((2*Ss*DHh + Ss*129 + Ss) * (int)sizeof(float))
__global__ void __launch_bounds__(128) attn_kernel(const float* __restrict__ Qkv,
                                                   const float* __restrict__ bias,
                                                   __half* __restrict__ chi,
                                                   __half* __restrict__ clo) {
    extern __shared__ float smf[];
    float* Ks = smf;
    float* Vs = smf + Ss * DHh;
    float* S  = smf + 2 * Ss * DHh;
    float* biasS = S + Ss * 129;
    int bn = blockIdx.x;
    int b = bn / NHh, n = bn % NHh;
    int tid = threadIdx.x;
    const float scale = 0.125f;

    #pragma unroll
    for (int i = 0; i < 16; i++) {
        int linr = tid + i * 128;
        int j = linr >> 4, c4 = (linr & 15) * 4;
        size_t rowb = (size_t)(b * Ss + j) * QKVN + n * DHh + c4;
        *(float4*)&Ks[j * DHh + c4] = *(const float4*)(Qkv + rowb + Hh);
        *(float4*)&Vs[j * DHh + c4] = *(const float4*)(Qkv + rowb + 2 * Hh);
    }
    biasS[tid] = bias[b * Ss + tid];
    __syncthreads();

    int qi = tid;
    float Qr[DHh];
    const float4* qp = (const float4*)(Qkv + (size_t)(b * Ss + qi) * QKVN + n * DHh);
    #pragma unroll
    for (int i = 0; i < 16; i++) {
        float4 v4 = qp[i];
        Qr[i * 4 + 0] = v4.x; Qr[i * 4 + 1] = v4.y; Qr[i * 4 + 2] = v4.z; Qr[i * 4 + 3] = v4.w;
    }

    float* Srow = S + qi * 129;
    float m = -1e30f;
    #pragma unroll 1
    for (int j = 0; j < Ss; j += 4) {
        const float* k0 = Ks + j * DHh;
        float s0 = 0.f, s1 = 0.f, s2 = 0.f, s3 = 0.f;
        #pragma unroll
        for (int d = 0; d < DHh; d++) {
            float qd = Qr[d];
            s0 = fmaf(qd, k0[d], s0);
            s1 = fmaf(qd, k0[DHh + d], s1);
            s2 = fmaf(qd, k0[2 * DHh + d], s2);
            s3 = fmaf(qd, k0[3 * DHh + d], s3);
        }
        s0 = fmaf(s0, scale, biasS[j]);
        s1 = fmaf(s1, scale, biasS[j + 1]);
        s2 = fmaf(s2, scale, biasS[j + 2]);
        s3 = fmaf(s3, scale, biasS[j + 3]);
        Srow[j] = s0; Srow[j + 1] = s1; Srow[j + 2] = s2; Srow[j + 3] = s3;
        m = fmaxf(m, fmaxf(fmaxf(s0, s1), fmaxf(s2, s3)));
    }
    float lsum = 0.f;
    #pragma unroll 4
    for (int j = 0; j < Ss; j++) {
        float p = __expf(Srow[j] - m);
        Srow[j] = p;
        lsum += p;
    }
    float inv_l = 1.0f / lsum;

    float acc[DHh];
    #pragma unroll
    for (int d = 0; d < DHh; d++) acc[d] = 0.f;
    #pragma unroll 1
    for (int j = 0; j < Ss; j++) {
        float p = Srow[j];
        const float* vr = Vs + j * DHh;
        #pragma unroll
        for (int d = 0; d < DHh; d++) acc[d] = fmaf(p, vr[d], acc[d]);
    }
    size_t obase = (size_t)(b * Ss + qi) * Hh + n * DHh;
    #pragma unroll
    for (int d = 0; d < DHh; d += 2) {
        float v0 = acc[d] * inv_l, v1 = acc[d + 1] * inv_l;
        __half h0 = __float2half(v0), h1 = __float2half(v1);
        *(unsigned*)(chi + obase + d) =
            (unsigned)__half_as_ushort(h0) | ((unsigned)__half_as_ushort(h1) << 16);
        *(unsigned*)(clo + obase + d) =
            pack2h(v0 - __half2float(h0), v1 - __half2float(h1));
    }
}

// ---------------- CLS extraction + norm ----------------
__global__ void cls_kernel() {
    __shared__ float sred[9];
    int b = blockIdx.x;
    float loc = 0.f;
    #pragma unroll
    for (int i = 0; i < 3; i++) {
        int j = threadIdx.x + i * 256;
        float v = g_x[(size_t)(b * Ss) * Hh + j];
        g_cls[b * Hh + j] = v;
        loc += v * v;
    }
    float s = blk_sum256(loc, sred);
    if (threadIdx.x == 0) g_cn[b] = fmaxf(sqrtf(s), EPS_COS);
}

__global__ void reset_best_kernel() {
    if (threadIdx.x < Bb) g_best[threadIdx.x] = 0ull;
}

// ---------------- cosine + per-block argmax reduction ----------------
__global__ void __launch_bounds__(128) cos_kernel(const float* __restrict__ lab,
                                                  float* __restrict__ out) {
    __shared__ float clsS[Bb][33];
    __shared__ float sInvCn[Bb];
    int l = blockIdx.x * 128 + threadIdx.x;
    bool valid = (l < NLl);
    if (threadIdx.x < Bb) sInvCn[threadIdx.x] = 1.0f / g_cn[threadIdx.x];

    float acc[Bb];
    #pragma unroll
    for (int bb = 0; bb < Bb; bb++) acc[bb] = 0.f;

    for (int k0 = 0; k0 < Hh; k0 += 32) {
        #pragma unroll
        for (int i = 0; i < 8; i++) {
            int idx = threadIdx.x + i * 128;
            int bb = idx >> 5, kk = idx & 31;
            clsS[bb][kk] = g_cls[bb * Hh + k0 + kk];
        }
        __syncthreads();
        if (valid) {
            float lv[32];
            const float4* lp = (const float4*)(lab + (size_t)l * Hh + k0);
            #pragma unroll
            for (int i = 0; i < 8; i++) {
                float4 v4 = lp[i];
                lv[i * 4] = v4.x; lv[i * 4 + 1] = v4.y; lv[i * 4 + 2] = v4.z; lv[i * 4 + 3] = v4.w;
            }
            #pragma unroll
            for (int bb = 0; bb < Bb; bb++) {
                float a = acc[bb];
                #pragma unroll
                for (int kk = 0; kk < 32; kk++) a = fmaf(clsS[bb][kk], lv[kk], a);
                acc[bb] = a;
            }
        }
        __syncthreads();
    }

    float invl = 0.f;
    if (valid) {
        float s = 0.f;
        const float4* lp = (const float4*)(lab + (size_t)l * Hh);
        #pragma unroll 4
        for (int i = 0; i < Hh / 4; i++) {
            float4 v4 = lp[i];
            s += v4.x * v4.x + v4.y * v4.y + v4.z * v4.z + v4.w * v4.w;
        }
        invl = 1.0f / fmaxf(sqrtf(s), EPS_COS);
    }

    int lane = threadIdx.x & 31;
    #pragma unroll 1
    for (int bb = 0; bb < Bb; bb++) {
        unsigned long long key = 0ull;
        if (valid) {
            float c = acc[bb] * invl * sInvCn[bb];
            out[(size_t)bb * NLl + l] = c;
            key = pack_key(c, l);
        }
        #pragma unroll
        for (int o = 16; o > 0; o >>= 1) {
            unsigned long long other = __shfl_down_sync(0xffffffffu, key, o);
            key = (other > key) ? other : key;
        }
        if (lane == 0) atomicMax(&g_best[bb], key);
    }
}

__global__ void ids_out_kernel(float* __restrict__ out) {
    int b = threadIdx.x;
    if (b < Bb) {
        unsigned idpart = (unsigned)(g_best[b] & 0xFFFFFFFFull);
        out[(size_t)Bb * NLl + b] = (float)(0xFFFFFFFFu - idpart);
    }
}

// ---------------- host orchestration ----------------
extern "C" void kernel_launch(void* const* d_in, const int* in_sizes, int n_in,
                              void* d_out, int out_size) {
    const int*   ids  = (const int*)d_in[0];
    const int*   tys  = (const int*)d_in[1];
    const float* word = (const float*)d_in[2];
    const float* pos  = (const float*)d_in[3];
    const float* typ  = (const float*)d_in[4];
    const float* eg   = (const float*)d_in[5];
    const float* eb   = (const float*)d_in[6];
    const float* Wq   = (const float*)d_in[7];
    const float* bq   = (const float*)d_in[8];
    const float* Wk   = (const float*)d_in[9];
    const float* bk   = (const float*)d_in[10];
    const float* Wv   = (const float*)d_in[11];
    const float* bv   = (const float*)d_in[12];
    const float* Wo   = (const float*)d_in[13];
    const float* bo   = (const float*)d_in[14];
    const float* g1   = (const float*)d_in[15];
    const float* be1  = (const float*)d_in[16];
    const float* W1   = (const float*)d_in[17];
    const float* b1   = (const float*)d_in[18];
    const float* W2   = (const float*)d_in[19];
    const float* b2   = (const float*)d_in[20];
    const float* g2   = (const float*)d_in[21];
    const float* be2  = (const float*)d_in[22];
    const float* lab  = (const float*)d_in[23];
    float* out = (float*)d_out;

    float *px, *py, *pqkv, *pmbias, *pbqkv;
    __half *pxhi, *pxlo, *pchi, *pclo, *phhi, *phlo, *pwth;
    cudaGetSymbolAddress((void**)&px,    g_x);
    cudaGetSymbolAddress((void**)&py,    g_y);
    cudaGetSymbolAddress((void**)&pqkv,  g_qkv);
    cudaGetSymbolAddress((void**)&pmbias,g_mbias);
    cudaGetSymbolAddress((void**)&pbqkv, g_bqkv);
    cudaGetSymbolAddress((void**)&pxhi,  g_xhi);
    cudaGetSymbolAddress((void**)&pxlo,  g_xlo);
    cudaGetSymbolAddress((void**)&pchi,  g_chi);
    cudaGetSymbolAddress((void**)&pclo,  g_clo);
    cudaGetSymbolAddress((void**)&phhi,  g_hhi);
    cudaGetSymbolAddress((void**)&phlo,  g_hlo);
    cudaGetSymbolAddress((void**)&pwth,  g_wth);

    cudaFuncSetAttribute(attn_kernel, cudaFuncAttributeMaxDynamicSharedMemorySize, ATTN_SMEM);
    cudaFuncSetAttribute(gemm_mma<0>, cudaFuncAttributeMaxDynamicSharedMemorySize, GSMEM);
    cudaFuncSetAttribute(gemm_mma<1>, cudaFuncAttributeMaxDynamicSharedMemorySize, GSMEM);

    // minimal prefix before the first GEMM so the ncu capture window lands on it:
    // wsplit4(1), embed(2), pack_bias(3), QKV-GEMM(4) ...
    dim3 tb(32, 8);
    wsplit4_kernel<<<dim3(24, 24, 48), tb>>>(Wq, Wk, Wv, Wo);                 // 1
    embed_ln_kernel<<<NTOK, 256>>>(ids, tys, word, pos, typ, eg, eb);         // 2
    pack_bias_kernel<<<Ll, Hh>>>(bq, bk, bv);                                 // 3

    for (int l = 0; l < Ll; l++) {
        size_t wl = (size_t)l * LSTRIDE;
        gemm_mma<0><<<dim3(QKVN / 128, 32), 256, GSMEM>>>(                    // 4 on l==0
            pxhi, pxlo, pwth + wl, pbqkv + l * QKVN,
            pqkv, nullptr, nullptr, Hh, QKVN);
        attn_kernel<<<Bb * NHh, 128, ATTN_SMEM>>>(pqkv, pmbias, pchi, pclo);
        if (l == 0) {
            // W1/W2 transposes are only needed from the first FFN onward
            wsplit_kernel<<<dim3(FFf / 32, Hh / 32, Ll), tb>>>(W1, OFF_W1, Hh, FFf);
            wsplit_kernel<<<dim3(Hh / 32, FFf / 32, Ll), tb>>>(W2, OFF_W2, FFf, Hh);
        }
        gemm_mma<0><<<dim3(Hh / 128, 32), 256, GSMEM>>>(
            pchi, pclo, pwth + wl + OFF_O, bo + (size_t)l * Hh,
            py, nullptr, nullptr, Hh, Hh);
        add_ln_kernel<<<NTOK, 256>>>(px, py, g1 + (size_t)l * Hh, be1 + (size_t)l * Hh);
        gemm_mma<1><<<dim3(FFf / 128, 32), 256, GSMEM>>>(
            pxhi, pxlo, pwth + wl + OFF_W1, b1 + (size_t)l * FFf,
            nullptr, phhi, phlo, Hh, FFf);
        gemm_mma<0><<<dim3(Hh / 128, 32), 256, GSMEM>>>(
            phhi, phlo, pwth + wl + OFF_W2, b2 + (size_t)l * Hh,
            py, nullptr, nullptr, FFf, Hh);
        add_ln_kernel<<<NTOK, 256>>>(px, py, g2 + (size_t)l * Hh, be2 + (size_t)l * Hh);
    }

    cls_kernel<<<Bb, 256>>>();
    reset_best_kernel<<<1, 32>>>();
    cos_kernel<<<(NLl + 127) / 128, 128>>>(lab, out);
    if (out_size >= Bb * NLl + Bb) ids_out_kernel<<<1, 32>>>(out);
}

// round 7
// speedup vs baseline: 1.1273x; 1.1273x over previous
#include <cuda_runtime.h>
#include <cuda_fp16.h>
#include <math.h>
#include <cstdint>

// ---------------- problem constants ----------------
#define Vv   30522
#define Hh   768
#define Ll   12
#define FFf  3072
#define NHh  12
#define DHh  64
#define Bb   32
#define Ss   128
#define NLl  10000
#define NTOK (Bb*Ss)          // 4096
#define QKVN (3*Hh)           // 2304
#define EPS_LN  1e-12f
#define EPS_COS 1e-8f

// transposed fp16 weight layout per layer (element offsets)
#define OFF_O   (QKVN*Hh)             // after packed qkv [2304][768]
#define OFF_W1  (OFF_O + Hh*Hh)       // [3072][768]
#define OFF_W2  (OFF_W1 + Hh*FFf)     // [768][3072]
#define LSTRIDE (OFF_W2 + FFf*Hh)     // 7,077,888

// ---------------- device scratch ----------------
__device__ __half g_wth[Ll*LSTRIDE];           // fp16 weights, transposed [N][K]
__device__ float  g_bqkv[Ll*QKVN];

__device__ float  g_x  [NTOK*Hh];
__device__ __half g_xhi[NTOK*Hh];
__device__ __half g_xlo[NTOK*Hh];
__device__ float  g_qkv[NTOK*QKVN];
__device__ __half g_chi[NTOK*Hh];
__device__ __half g_clo[NTOK*Hh];
__device__ __half g_hhi[NTOK*FFf];
__device__ __half g_hlo[NTOK*FFf];
__device__ float  g_y  [NTOK*Hh];
__device__ float g_mbias[NTOK];
__device__ float g_cls[Bb*Hh];
__device__ float g_cn [Bb];
__device__ unsigned long long g_best[Bb];

// ---------------- PTX helpers (compute_100-safe) ----------------
__device__ __forceinline__ uint32_t smem_u32(const void* p) {
    uint32_t a;
    asm("{ .reg .u64 t; cvta.to.shared.u64 t, %1; cvt.u32.u64 %0, t; }" : "=r"(a) : "l"(p));
    return a;
}
__device__ __forceinline__ void cp_async16(uint32_t dst, const void* src) {
    asm volatile("cp.async.cg.shared.global [%0], [%1], 16;" :: "r"(dst), "l"(src) : "memory");
}
#define CP_COMMIT() asm volatile("cp.async.commit_group;" ::: "memory")
#define CP_WAIT(n)  asm volatile("cp.async.wait_group %0;" :: "n"(n) : "memory")

__device__ __forceinline__ void ldsm4(uint32_t& r0, uint32_t& r1, uint32_t& r2, uint32_t& r3,
                                      uint32_t addr) {
    asm volatile("ldmatrix.sync.aligned.m8n8.x4.shared.b16 {%0,%1,%2,%3}, [%4];"
                 : "=r"(r0), "=r"(r1), "=r"(r2), "=r"(r3) : "r"(addr));
}
__device__ __forceinline__ void mma16816(float* c, uint32_t a0, uint32_t a1, uint32_t a2,
                                         uint32_t a3, uint32_t b0, uint32_t b1) {
    asm volatile(
        "mma.sync.aligned.m16n8k16.row.col.f32.f16.f16.f32 "
        "{%0,%1,%2,%3}, {%4,%5,%6,%7}, {%8,%9}, {%0,%1,%2,%3};"
        : "+f"(c[0]), "+f"(c[1]), "+f"(c[2]), "+f"(c[3])
        : "r"(a0), "r"(a1), "r"(a2), "r"(a3), "r"(b0), "r"(b1));
}

// ---------------- misc helpers ----------------
__device__ __forceinline__ float blk_sum256(float v, volatile float* sred) {
    int lane = threadIdx.x & 31, w = threadIdx.x >> 5;
    #pragma unroll
    for (int o = 16; o > 0; o >>= 1) v += __shfl_down_sync(0xffffffffu, v, o);
    if (lane == 0) sred[w] = v;
    __syncthreads();
    if (threadIdx.x == 0) {
        float s = 0.f;
        #pragma unroll
        for (int i = 0; i < 8; i++) s += sred[i];
        sred[8] = s;
    }
    __syncthreads();
    float r = sred[8];
    __syncthreads();
    return r;
}
__device__ __forceinline__ float gelu_tanh(float x) {
    float x3 = x * x * x;
    float t = tanhf(0.7978845608028654f * (x + 0.044715f * x3));
    return 0.5f * x * (1.0f + t);
}
__device__ __forceinline__ unsigned long long pack_key(float c, int l) {
    unsigned u = __float_as_uint(c);
    u = (u & 0x80000000u) ? ~u : (u | 0x80000000u);
    return ((unsigned long long)u << 32) | (unsigned long long)(0xFFFFFFFFu - (unsigned)l);
}
__device__ __forceinline__ void split_store_h(float v, __half* hi, __half* lo) {
    __half h = __float2half(v);
    *hi = h;
    *lo = __float2half(v - __half2float(h));
}
__device__ __forceinline__ unsigned pack2h(float v0, float v1) {
    __half h0 = __float2half(v0), h1 = __float2half(v1);
    return (unsigned)__half_as_ushort(h0) | ((unsigned)__half_as_ushort(h1) << 16);
}

// ---------------- weight transpose to fp16 ----------------
// 4 matrices of [L][768][768]: Wq, Wk, Wv (packed qkv), Wo
__global__ void wsplit4_kernel(const float* __restrict__ W0, const float* __restrict__ W1m,
                               const float* __restrict__ W2m, const float* __restrict__ W3m) {
    __shared__ float t[32][33];
    int z = blockIdx.z;
    int m = z & 3, l = z >> 2;
    const float* Ws = (m == 0 ? W0 : m == 1 ? W1m : m == 2 ? W2m : W3m) + (size_t)l * Hh * Hh;
    long dstOff = (m < 3) ? (long)m * Hh * Hh : (long)OFF_O;
    __half* th = g_wth + (size_t)l * LSTRIDE + dstOff;
    int n = blockIdx.x * 32 + threadIdx.x;
    #pragma unroll
    for (int i = 0; i < 4; i++) {
        int k = blockIdx.y * 32 + threadIdx.y + i * 8;
        t[threadIdx.y + i * 8][threadIdx.x] = Ws[(size_t)k * Hh + n];
    }
    __syncthreads();
    int k2 = blockIdx.y * 32 + threadIdx.x;
    #pragma unroll
    for (int i = 0; i < 4; i++) {
        int n2 = blockIdx.x * 32 + threadIdx.y + i * 8;
        th[(size_t)n2 * Hh + k2] = __float2half(t[threadIdx.x][threadIdx.y + i * 8]);
    }
}

// generic: W [L][K][N] -> g_wth + l*LSTRIDE + dstOff as [N][K] fp16
__global__ void wsplit_kernel(const float* __restrict__ W, long dstOff, int K, int N) {
    __shared__ float t[32][33];
    int l = blockIdx.z;
    const float* Ws = W + (size_t)l * K * N;
    __half* th = g_wth + (size_t)l * LSTRIDE + dstOff;
    int n = blockIdx.x * 32 + threadIdx.x;
    #pragma unroll
    for (int i = 0; i < 4; i++) {
        int k = blockIdx.y * 32 + threadIdx.y + i * 8;
        t[threadIdx.y + i * 8][threadIdx.x] = Ws[(size_t)k * N + n];
    }
    __syncthreads();
    int k2 = blockIdx.y * 32 + threadIdx.x;
    #pragma unroll
    for (int i = 0; i < 4; i++) {
        int n2 = blockIdx.x * 32 + threadIdx.y + i * 8;
        th[(size_t)n2 * K + k2] = __float2half(t[threadIdx.x][threadIdx.y + i * 8]);
    }
}

__global__ void pack_bias_kernel(const float* __restrict__ bq, const float* __restrict__ bk,
                                 const float* __restrict__ bv) {
    int l = blockIdx.x, j = threadIdx.x;
    g_bqkv[l * QKVN + j]          = bq[l * Hh + j];
    g_bqkv[l * QKVN + Hh + j]     = bk[l * Hh + j];
    g_bqkv[l * QKVN + 2 * Hh + j] = bv[l * Hh + j];
}

// ---------------- embeddings + LN + mask bias ----------------
__global__ void embed_ln_kernel(const int* __restrict__ ids, const int* __restrict__ tys,
                                const float* __restrict__ word, const float* __restrict__ pos,
                                const float* __restrict__ typ,
                                const float* __restrict__ eg, const float* __restrict__ eb) {
    __shared__ float sred[9];
    int t = blockIdx.x;
    int s = t & (Ss - 1);
    int id = ids[t], ty = tys[t];
    float v[3];
    float loc = 0.f;
    #pragma unroll
    for (int i = 0; i < 3; i++) {
        int j = threadIdx.x + i * 256;
        v[i] = word[(size_t)id * Hh + j] + pos[(size_t)s * Hh + j] + typ[(size_t)ty * Hh + j];
        loc += v[i];
    }
    float mu = blk_sum256(loc, sred) * (1.0f / Hh);
    float l2 = 0.f;
    #pragma unroll
    for (int i = 0; i < 3; i++) { float d = v[i] - mu; l2 += d * d; }
    float var = blk_sum256(l2, sred) * (1.0f / Hh);
    float rstd = rsqrtf(var + EPS_LN);
    #pragma unroll
    for (int i = 0; i < 3; i++) {
        int j = threadIdx.x + i * 256;
        size_t idx = (size_t)t * Hh + j;
        float o = (v[i] - mu) * rstd * eg[j] + eb[j];
        g_x[idx] = o;
        split_store_h(o, &g_xhi[idx], &g_xlo[idx]);
    }
    if (threadIdx.x == 0) g_mbias[t] = (id > 0) ? 0.f : -10000.0f;
}

// ---------------- residual add + LN (in place on x), fused fp16 split ----------------
__global__ void add_ln_kernel(float* __restrict__ x, const float* __restrict__ y,
                              const float* __restrict__ g, const float* __restrict__ b) {
    __shared__ float sred[9];
    size_t base = (size_t)blockIdx.x * Hh;
    float v[3];
    float loc = 0.f;
    #pragma unroll
    for (int i = 0; i < 3; i++) {
        int j = threadIdx.x + i * 256;
        v[i] = x[base + j] + y[base + j];
        loc += v[i];
    }
    float mu = blk_sum256(loc, sred) * (1.0f / Hh);
    float l2 = 0.f;
    #pragma unroll
    for (int i = 0; i < 3; i++) { float d = v[i] - mu; l2 += d * d; }
    float var = blk_sum256(l2, sred) * (1.0f / Hh);
    float rstd = rsqrtf(var + EPS_LN);
    #pragma unroll
    for (int i = 0; i < 3; i++) {
        int j = threadIdx.x + i * 256;
        float o = (v[i] - mu) * rstd * g[j] + b[j];
        x[base + j] = o;
        split_store_h(o, &g_xhi[base + j], &g_xlo[base + j]);
    }
}

// ---------------- HMMA 2-term fp16 GEMM: C[4096, N] = (Ah+Al) @ Bh^T + bias ----------------
// A: hi/lo fp16 [M][K] (activations, exact to 2^-22); B: fp16 [N][K] (weights).
// CTA 128x128, K-chunk 64 (rows 144B: 64 fp16 + 16B pad, conflict-free ldsm),
// 2-stage cp.async double buffer, 8 warps (warp tile 64x32), 2 CTAs/SM.
#define GT_ROW   144
#define GT_TILE  (128 * GT_ROW)        // 18432 B per sub-tile
#define GT_STAGE (3 * GT_TILE)         // Ah | Al | Bh = 55296
#define GSMEM    (2 * GT_STAGE)        // 110592
template <int OUTMODE>
__global__ void __launch_bounds__(256, 2) gemm_mma(
    const __half* __restrict__ Ahi, const __half* __restrict__ Alo,
    const __half* __restrict__ Bh,
    const float* __restrict__ bias,
    float* __restrict__ Cf, __half* __restrict__ Chi, __half* __restrict__ Clo,
    int K, int ldc)
{
    extern __shared__ char sm[];
    const uint32_t sb = smem_u32(sm);
    int tid = threadIdx.x, lane = tid & 31, wid = tid >> 5;
    int wm = wid >> 2, wn = wid & 3;              // warp tile rows wm*64, cols wn*32
    int m0 = blockIdx.y * 128, n0 = blockIdx.x * 128;

    // ldmatrix lane offsets (row stride 144B)
    int q = lane >> 3, r = lane & 7;
    uint32_t aLane = (uint32_t)(((q & 1) * 8 + r) * GT_ROW + (q >> 1) * 16);
    uint32_t bLane = (uint32_t)(((q >> 1) * 8 + r) * GT_ROW + (q & 1) * 16);

    float acc[4][4][4];
    #pragma unroll
    for (int mi = 0; mi < 4; mi++)
        #pragma unroll
        for (int ni = 0; ni < 4; ni++)
            #pragma unroll
            for (int e = 0; e < 4; e++) acc[mi][ni][e] = 0.f;

    int nchunk = K >> 6;                          // K-chunk = 64

    // loader: 3 tiles x 128 rows x 8 segs of 16B = 3072 cp.async; 12 per thread
    auto load_stage = [&](int c) {
        int k0 = c << 6;
        uint32_t base = sb + (uint32_t)(c & 1) * GT_STAGE;
        #pragma unroll
        for (int i = 0; i < 12; i++) {
            int lin = tid + i * 256;              // 0..3071
            int tile = lin >> 10;                 // 0=Ah 1=Al 2=Bh
            int within = lin & 1023;
            int row = within >> 3, seg = within & 7;
            uint32_t dst = base + (uint32_t)tile * GT_TILE + (uint32_t)(row * GT_ROW + seg * 16);
            const __half* src;
            if (tile == 0)      src = Ahi + (size_t)(m0 + row) * K + k0 + seg * 8;
            else if (tile == 1) src = Alo + (size_t)(m0 + row) * K + k0 + seg * 8;
            else                src = Bh  + (size_t)(n0 + row) * K + k0 + seg * 8;
            cp_async16(dst, src);
        }
    };

    load_stage(0);
    CP_COMMIT();

    for (int c = 0; c < nchunk; c++) {
        if (c + 1 < nchunk) { load_stage(c + 1); CP_COMMIT(); CP_WAIT(1); }
        else { CP_WAIT(0); }
        __syncthreads();

        uint32_t base = sb + (uint32_t)(c & 1) * GT_STAGE;
        uint32_t aBaseH = base + (uint32_t)((wm * 64) * GT_ROW) + aLane;
        uint32_t aBaseL = aBaseH + GT_TILE;
        uint32_t bBase  = base + 2 * GT_TILE + (uint32_t)((wn * 32) * GT_ROW) + bLane;

        #pragma unroll
        for (int ks = 0; ks < 4; ks++) {
            uint32_t ko = (uint32_t)(ks * 32);
            uint32_t ah[4][4], al[4][4], bf[2][4];
            #pragma unroll
            for (int mi = 0; mi < 4; mi++)
                ldsm4(ah[mi][0], ah[mi][1], ah[mi][2], ah[mi][3],
                      aBaseH + (uint32_t)(mi * 16 * GT_ROW) + ko);
            #pragma unroll
            for (int mi = 0; mi < 4; mi++)
                ldsm4(al[mi][0], al[mi][1], al[mi][2], al[mi][3],
                      aBaseL + (uint32_t)(mi * 16 * GT_ROW) + ko);
            #pragma unroll
            for (int p = 0; p < 2; p++)
                ldsm4(bf[p][0], bf[p][1], bf[p][2], bf[p][3],
                      bBase + (uint32_t)(p * 16 * GT_ROW) + ko);
            #pragma unroll
            for (int mi = 0; mi < 4; mi++)
                #pragma unroll
                for (int ni = 0; ni < 4; ni++) {
                    int p = ni >> 1, su = ni & 1;
                    mma16816(acc[mi][ni], ah[mi][0], ah[mi][1], ah[mi][2], ah[mi][3],
                             bf[p][su * 2], bf[p][su * 2 + 1]);
                }
            #pragma unroll
            for (int mi = 0; mi < 4; mi++)
                #pragma unroll
                for (int ni = 0; ni < 4; ni++) {
                    int p = ni >> 1, su = ni & 1;
                    mma16816(acc[mi][ni], al[mi][0], al[mi][1], al[mi][2], al[mi][3],
                             bf[p][su * 2], bf[p][su * 2 + 1]);
                }
        }
        __syncthreads();
    }

    // ---------------- epilogue ----------------
    int rbase = m0 + wm * 64 + (lane >> 2);
    int cbase = n0 + wn * 32 + (lane & 3) * 2;
    #pragma unroll
    for (int mi = 0; mi < 4; mi++) {
        #pragma unroll
        for (int ni = 0; ni < 4; ni++) {
            int row = rbase + mi * 16;
            int col = cbase + ni * 8;
            float b0 = bias[col], b1 = bias[col + 1];
            float v0 = acc[mi][ni][0] + b0, v1 = acc[mi][ni][1] + b1;
            float v2 = acc[mi][ni][2] + b0, v3 = acc[mi][ni][3] + b1;
            if (OUTMODE == 0) {
                *(float2*)(Cf + (size_t)row * ldc + col)       = make_float2(v0, v1);
                *(float2*)(Cf + (size_t)(row + 8) * ldc + col) = make_float2(v2, v3);
            } else {
                v0 = gelu_tanh(v0); v1 = gelu_tanh(v1);
                v2 = gelu_tanh(v2); v3 = gelu_tanh(v3);
                __half h0 = __float2half(v0), h1 = __float2half(v1);
                __half h2 = __float2half(v2), h3 = __float2half(v3);
                *(unsigned*)(Chi + (size_t)row * ldc + col) =
                    (unsigned)__half_as_ushort(h0) | ((unsigned)__half_as_ushort(h1) << 16);
                *(unsigned*)(Clo + (size_t)row * ldc + col) =
                    pack2h(v0 - __half2float(h0), v1 - __half2float(h1));
                *(unsigned*)(Chi + (size_t)(row + 8) * ldc + col) =
                    (unsigned)__half_as_ushort(h2) | ((unsigned)__half_as_ushort(h3) << 16);
                *(unsigned*)(Clo + (size_t)(row + 8) * ldc + col) =
                    pack2h(v2 - __half2float(h2), v3 - __half2float(h3));
            }
        }
    }
}

// ---------------- attention: one-pass, scores cached in smem ----------------
#define ATTN_SMEM ((2*Ss*DHh + Ss*129 + Ss) * (int)sizeof(float))
__global__ void __launch_bounds__(128) attn_kernel(const float* __restrict__ Qkv,
                                                   const float* __restrict__ bias,
                                                   __half* __restrict__ chi,
                                                   __half* __restrict__ clo) {
    extern __shared__ float smf[];
    float* Ks = smf;
    float* Vs = smf + Ss * DHh;
    float* S  = smf + 2 * Ss * DHh;
    float* biasS = S + Ss * 129;
    int bn = blockIdx.x;
    int b = bn / NHh, n = bn % NHh;
    int tid = threadIdx.x;
    const float scale = 0.125f;

    #pragma unroll
    for (int i = 0; i < 16; i++) {
        int linr = tid + i * 128;
        int j = linr >> 4, c4 = (linr & 15) * 4;
        size_t rowb = (size_t)(b * Ss + j) * QKVN + n * DHh + c4;
        *(float4*)&Ks[j * DHh + c4] = *(const float4*)(Qkv + rowb + Hh);
        *(float4*)&Vs[j * DHh + c4] = *(const float4*)(Qkv + rowb + 2 * Hh);
    }
    biasS[tid] = bias[b * Ss + tid];
    __syncthreads();

    int qi = tid;
    float Qr[DHh];
    const float4* qp = (const float4*)(Qkv + (size_t)(b * Ss + qi) * QKVN + n * DHh);
    #pragma unroll
    for (int i = 0; i < 16; i++) {
        float4 v4 = qp[i];
        Qr[i * 4 + 0] = v4.x; Qr[i * 4 + 1] = v4.y; Qr[i * 4 + 2] = v4.z; Qr[i * 4 + 3] = v4.w;
    }

    float* Srow = S + qi * 129;
    float m = -1e30f;
    #pragma unroll 1
    for (int j = 0; j < Ss; j += 4) {
        const float* k0 = Ks + j * DHh;
        float s0 = 0.f, s1 = 0.f, s2 = 0.f, s3 = 0.f;
        #pragma unroll
        for (int d = 0; d < DHh; d++) {
            float qd = Qr[d];
            s0 = fmaf(qd, k0[d], s0);
            s1 = fmaf(qd, k0[DHh + d], s1);
            s2 = fmaf(qd, k0[2 * DHh + d], s2);
            s3 = fmaf(qd, k0[3 * DHh + d], s3);
        }
        s0 = fmaf(s0, scale, biasS[j]);
        s1 = fmaf(s1, scale, biasS[j + 1]);
        s2 = fmaf(s2, scale, biasS[j + 2]);
        s3 = fmaf(s3, scale, biasS[j + 3]);
        Srow[j] = s0; Srow[j + 1] = s1; Srow[j + 2] = s2; Srow[j + 3] = s3;
        m = fmaxf(m, fmaxf(fmaxf(s0, s1), fmaxf(s2, s3)));
    }
    float lsum = 0.f;
    #pragma unroll 4
    for (int j = 0; j < Ss; j++) {
        float p = __expf(Srow[j] - m);
        Srow[j] = p;
        lsum += p;
    }
    float inv_l = 1.0f / lsum;

    float acc[DHh];
    #pragma unroll
    for (int d = 0; d < DHh; d++) acc[d] = 0.f;
    #pragma unroll 1
    for (int j = 0; j < Ss; j++) {
        float p = Srow[j];
        const float* vr = Vs + j * DHh;
        #pragma unroll
        for (int d = 0; d < DHh; d++) acc[d] = fmaf(p, vr[d], acc[d]);
    }
    size_t obase = (size_t)(b * Ss + qi) * Hh + n * DHh;
    #pragma unroll
    for (int d = 0; d < DHh; d += 2) {
        float v0 = acc[d] * inv_l, v1 = acc[d + 1] * inv_l;
        __half h0 = __float2half(v0), h1 = __float2half(v1);
        *(unsigned*)(chi + obase + d) =
            (unsigned)__half_as_ushort(h0) | ((unsigned)__half_as_ushort(h1) << 16);
        *(unsigned*)(clo + obase + d) =
            pack2h(v0 - __half2float(h0), v1 - __half2float(h1));
    }
}

// ---------------- CLS extraction + norm ----------------
__global__ void cls_kernel() {
    __shared__ float sred[9];
    int b = blockIdx.x;
    float loc = 0.f;
    #pragma unroll
    for (int i = 0; i < 3; i++) {
        int j = threadIdx.x + i * 256;
        float v = g_x[(size_t)(b * Ss) * Hh + j];
        g_cls[b * Hh + j] = v;
        loc += v * v;
    }
    float s = blk_sum256(loc, sred);
    if (threadIdx.x == 0) g_cn[b] = fmaxf(sqrtf(s), EPS_COS);
}

__global__ void reset_best_kernel() {
    if (threadIdx.x < Bb) g_best[threadIdx.x] = 0ull;
}

// ---------------- cosine + per-block argmax reduction ----------------
__global__ void __launch_bounds__(128) cos_kernel(const float* __restrict__ lab,
                                                  float* __restrict__ out) {
    __shared__ float clsS[Bb][33];
    __shared__ float sInvCn[Bb];
    int l = blockIdx.x * 128 + threadIdx.x;
    bool valid = (l < NLl);
    if (threadIdx.x < Bb) sInvCn[threadIdx.x] = 1.0f / g_cn[threadIdx.x];

    float acc[Bb];
    #pragma unroll
    for (int bb = 0; bb < Bb; bb++) acc[bb] = 0.f;

    for (int k0 = 0; k0 < Hh; k0 += 32) {
        #pragma unroll
        for (int i = 0; i < 8; i++) {
            int idx = threadIdx.x + i * 128;
            int bb = idx >> 5, kk = idx & 31;
            clsS[bb][kk] = g_cls[bb * Hh + k0 + kk];
        }
        __syncthreads();
        if (valid) {
            float lv[32];
            const float4* lp = (const float4*)(lab + (size_t)l * Hh + k0);
            #pragma unroll
            for (int i = 0; i < 8; i++) {
                float4 v4 = lp[i];
                lv[i * 4] = v4.x; lv[i * 4 + 1] = v4.y; lv[i * 4 + 2] = v4.z; lv[i * 4 + 3] = v4.w;
            }
            #pragma unroll
            for (int bb = 0; bb < Bb; bb++) {
                float a = acc[bb];
                #pragma unroll
                for (int kk = 0; kk < 32; kk++) a = fmaf(clsS[bb][kk], lv[kk], a);
                acc[bb] = a;
            }
        }
        __syncthreads();
    }

    float invl = 0.f;
    if (valid) {
        float s = 0.f;
        const float4* lp = (const float4*)(lab + (size_t)l * Hh);
        #pragma unroll 4
        for (int i = 0; i < Hh / 4; i++) {
            float4 v4 = lp[i];
            s += v4.x * v4.x + v4.y * v4.y + v4.z * v4.z + v4.w * v4.w;
        }
        invl = 1.0f / fmaxf(sqrtf(s), EPS_COS);
    }

    int lane = threadIdx.x & 31;
    #pragma unroll 1
    for (int bb = 0; bb < Bb; bb++) {
        unsigned long long key = 0ull;
        if (valid) {
            float c = acc[bb] * invl * sInvCn[bb];
            out[(size_t)bb * NLl + l] = c;
            key = pack_key(c, l);
        }
        #pragma unroll
        for (int o = 16; o > 0; o >>= 1) {
            unsigned long long other = __shfl_down_sync(0xffffffffu, key, o);
            key = (other > key) ? other : key;
        }
        if (lane == 0) atomicMax(&g_best[bb], key);
    }
}

__global__ void ids_out_kernel(float* __restrict__ out) {
    int b = threadIdx.x;
    if (b < Bb) {
        unsigned idpart = (unsigned)(g_best[b] & 0xFFFFFFFFull);
        out[(size_t)Bb * NLl + b] = (float)(0xFFFFFFFFu - idpart);
    }
}

// ---------------- host orchestration ----------------
extern "C" void kernel_launch(void* const* d_in, const int* in_sizes, int n_in,
                              void* d_out, int out_size) {
    const int*   ids  = (const int*)d_in[0];
    const int*   tys  = (const int*)d_in[1];
    const float* word = (const float*)d_in[2];
    const float* pos  = (const float*)d_in[3];
    const float* typ  = (const float*)d_in[4];
    const float* eg   = (const float*)d_in[5];
    const float* eb   = (const float*)d_in[6];
    const float* Wq   = (const float*)d_in[7];
    const float* bq   = (const float*)d_in[8];
    const float* Wk   = (const float*)d_in[9];
    const float* bk   = (const float*)d_in[10];
    const float* Wv   = (const float*)d_in[11];
    const float* bv   = (const float*)d_in[12];
    const float* Wo   = (const float*)d_in[13];
    const float* bo   = (const float*)d_in[14];
    const float* g1   = (const float*)d_in[15];
    const float* be1  = (const float*)d_in[16];
    const float* W1   = (const float*)d_in[17];
    const float* b1   = (const float*)d_in[18];
    const float* W2   = (const float*)d_in[19];
    const float* b2   = (const float*)d_in[20];
    const float* g2   = (const float*)d_in[21];
    const float* be2  = (const float*)d_in[22];
    const float* lab  = (const float*)d_in[23];
    float* out = (float*)d_out;

    float *px, *py, *pqkv, *pmbias, *pbqkv;
    __half *pxhi, *pxlo, *pchi, *pclo, *phhi, *phlo, *pwth;
    cudaGetSymbolAddress((void**)&px,    g_x);
    cudaGetSymbolAddress((void**)&py,    g_y);
    cudaGetSymbolAddress((void**)&pqkv,  g_qkv);
    cudaGetSymbolAddress((void**)&pmbias,g_mbias);
    cudaGetSymbolAddress((void**)&pbqkv, g_bqkv);
    cudaGetSymbolAddress((void**)&pxhi,  g_xhi);
    cudaGetSymbolAddress((void**)&pxlo,  g_xlo);
    cudaGetSymbolAddress((void**)&pchi,  g_chi);
    cudaGetSymbolAddress((void**)&pclo,  g_clo);
    cudaGetSymbolAddress((void**)&phhi,  g_hhi);
    cudaGetSymbolAddress((void**)&phlo,  g_hlo);
    cudaGetSymbolAddress((void**)&pwth,  g_wth);

    cudaFuncSetAttribute(attn_kernel, cudaFuncAttributeMaxDynamicSharedMemorySize, ATTN_SMEM);
    cudaFuncSetAttribute(gemm_mma<0>, cudaFuncAttributeMaxDynamicSharedMemorySize, GSMEM);
    cudaFuncSetAttribute(gemm_mma<1>, cudaFuncAttributeMaxDynamicSharedMemorySize, GSMEM);

    // minimal prefix before the first GEMM so the ncu capture window lands on it:
    // wsplit4(1), embed(2), pack_bias(3), QKV-GEMM(4) ...
    dim3 tb(32, 8);
    wsplit4_kernel<<<dim3(24, 24, 48), tb>>>(Wq, Wk, Wv, Wo);                 // 1
    embed_ln_kernel<<<NTOK, 256>>>(ids, tys, word, pos, typ, eg, eb);         // 2
    pack_bias_kernel<<<Ll, Hh>>>(bq, bk, bv);                                 // 3

    for (int l = 0; l < Ll; l++) {
        size_t wl = (size_t)l * LSTRIDE;
        gemm_mma<0><<<dim3(QKVN / 128, 32), 256, GSMEM>>>(                    // 4 on l==0
            pxhi, pxlo, pwth + wl, pbqkv + l * QKVN,
            pqkv, nullptr, nullptr, Hh, QKVN);
        attn_kernel<<<Bb * NHh, 128, ATTN_SMEM>>>(pqkv, pmbias, pchi, pclo);
        if (l == 0) {
            // W1/W2 transposes are only needed from the first FFN onward
            wsplit_kernel<<<dim3(FFf / 32, Hh / 32, Ll), tb>>>(W1, OFF_W1, Hh, FFf);
            wsplit_kernel<<<dim3(Hh / 32, FFf / 32, Ll), tb>>>(W2, OFF_W2, FFf, Hh);
        }
        gemm_mma<0><<<dim3(Hh / 128, 32), 256, GSMEM>>>(
            pchi, pclo, pwth + wl + OFF_O, bo + (size_t)l * Hh,
            py, nullptr, nullptr, Hh, Hh);
        add_ln_kernel<<<NTOK, 256>>>(px, py, g1 + (size_t)l * Hh, be1 + (size_t)l * Hh);
        gemm_mma<1><<<dim3(FFf / 128, 32), 256, GSMEM>>>(
            pxhi, pxlo, pwth + wl + OFF_W1, b1 + (size_t)l * FFf,
            nullptr, phhi, phlo, Hh, FFf);
        gemm_mma<0><<<dim3(Hh / 128, 32), 256, GSMEM>>>(
            phhi, phlo, pwth + wl + OFF_W2, b2 + (size_t)l * Hh,
            py, nullptr, nullptr, FFf, Hh);
        add_ln_kernel<<<NTOK, 256>>>(px, py, g2 + (size_t)l * Hh, be2 + (size_t)l * Hh);
    }

    cls_kernel<<<Bb, 256>>>();
    reset_best_kernel<<<1, 32>>>();
    cos_kernel<<<(NLl + 127) / 128, 128>>>(lab, out);
    if (out_size >= Bb * NLl + Bb) ids_out_kernel<<<1, 32>>>(out);
}

// round 8
// speedup vs baseline: 1.1891x; 1.0548x over previous
#include <cuda_runtime.h>
#include <cuda_fp16.h>
#include <math.h>
#include <cstdint>

// ---------------- problem constants ----------------
#define Vv   30522
#define Hh   768
#define Ll   12
#define FFf  3072
#define NHh  12
#define DHh  64
#define Bb   32
#define Ss   128
#define NLl  10000
#define NTOK (Bb*Ss)          // 4096
#define QKVN (3*Hh)           // 2304
#define EPS_LN  1e-12f
#define EPS_COS 1e-8f

// transposed fp16 weight layout per layer (element offsets)
#define OFF_O   (QKVN*Hh)             // after packed qkv [2304][768]
#define OFF_W1  (OFF_O + Hh*Hh)       // [3072][768]
#define OFF_W2  (OFF_W1 + Hh*FFf)     // [768][3072]
#define LSTRIDE (OFF_W2 + FFf*Hh)     // 7,077,888

// ---------------- device scratch ----------------
__device__ __half g_wth[Ll*LSTRIDE];           // fp16 weights, transposed [N][K]
__device__ float  g_bqkv[Ll*QKVN];
__device__ float  g_zeros[Hh];                 // stays zero (module-load zero-init)

__device__ float  g_x  [NTOK*Hh];
__device__ __half g_xhi[NTOK*Hh];
__device__ __half g_xlo[NTOK*Hh];
__device__ float  g_qkv[NTOK*QKVN];
__device__ __half g_chi[NTOK*Hh];
__device__ __half g_clo[NTOK*Hh];
__device__ __half g_hhi[NTOK*FFf];
__device__ __half g_hlo[NTOK*FFf];
__device__ float  g_y  [NTOK*Hh];
__device__ float  g_y2 [NTOK*Hh];
__device__ float g_mbias[NTOK];
__device__ float g_cls[Bb*Hh];
__device__ float g_cn [Bb];
__device__ unsigned long long g_best[Bb];

// ---------------- PTX helpers (compute_100-safe) ----------------
__device__ __forceinline__ uint32_t smem_u32(const void* p) {
    uint32_t a;
    asm("{ .reg .u64 t; cvta.to.shared.u64 t, %1; cvt.u32.u64 %0, t; }" : "=r"(a) : "l"(p));
    return a;
}
__device__ __forceinline__ void cp_async16(uint32_t dst, const void* src) {
    asm volatile("cp.async.cg.shared.global [%0], [%1], 16;" :: "r"(dst), "l"(src) : "memory");
}
#define CP_COMMIT() asm volatile("cp.async.commit_group;" ::: "memory")
#define CP_WAIT(n)  asm volatile("cp.async.wait_group %0;" :: "n"(n) : "memory")

__device__ __forceinline__ void ldsm4(uint32_t& r0, uint32_t& r1, uint32_t& r2, uint32_t& r3,
                                      uint32_t addr) {
    asm volatile("ldmatrix.sync.aligned.m8n8.x4.shared.b16 {%0,%1,%2,%3}, [%4];"
                 : "=r"(r0), "=r"(r1), "=r"(r2), "=r"(r3) : "r"(addr));
}
__device__ __forceinline__ void mma16816(float* c, uint32_t a0, uint32_t a1, uint32_t a2,
                                         uint32_t a3, uint32_t b0, uint32_t b1) {
    asm volatile(
        "mma.sync.aligned.m16n8k16.row.col.f32.f16.f16.f32 "
        "{%0,%1,%2,%3}, {%4,%5,%6,%7}, {%8,%9}, {%0,%1,%2,%3};"
        : "+f"(c[0]), "+f"(c[1]), "+f"(c[2]), "+f"(c[3])
        : "r"(a0), "r"(a1), "r"(a2), "r"(a3), "r"(b0), "r"(b1));
}

// ---------------- misc helpers ----------------
__device__ __forceinline__ float blk_sum256(float v, volatile float* sred) {
    int lane = threadIdx.x & 31, w = threadIdx.x >> 5;
    #pragma unroll
    for (int o = 16; o > 0; o >>= 1) v += __shfl_down_sync(0xffffffffu, v, o);
    if (lane == 0) sred[w] = v;
    __syncthreads();
    if (threadIdx.x == 0) {
        float s = 0.f;
        #pragma unroll
        for (int i = 0; i < 8; i++) s += sred[i];
        sred[8] = s;
    }
    __syncthreads();
    float r = sred[8];
    __syncthreads();
    return r;
}
__device__ __forceinline__ float gelu_tanh(float x) {
    float x3 = x * x * x;
    float t = tanhf(0.7978845608028654f * (x + 0.044715f * x3));
    return 0.5f * x * (1.0f + t);
}
__device__ __forceinline__ unsigned long long pack_key(float c, int l) {
    unsigned u = __float_as_uint(c);
    u = (u & 0x80000000u) ? ~u : (u | 0x80000000u);
    return ((unsigned long long)u << 32) | (unsigned long long)(0xFFFFFFFFu - (unsigned)l);
}
__device__ __forceinline__ void split_store_h(float v, __half* hi, __half* lo) {
    __half h = __float2half(v);
    *hi = h;
    *lo = __float2half(v - __half2float(h));
}
__device__ __forceinline__ unsigned pack2h(float v0, float v1) {
    __half h0 = __float2half(v0), h1 = __float2half(v1);
    return (unsigned)__half_as_ushort(h0) | ((unsigned)__half_as_ushort(h1) << 16);
}

// ---------------- weight transpose to fp16 ----------------
__global__ void wsplit4_kernel(const float* __restrict__ W0, const float* __restrict__ W1m,
                               const float* __restrict__ W2m, const float* __restrict__ W3m) {
    __shared__ float t[32][33];
    int z = blockIdx.z;
    int m = z & 3, l = z >> 2;
    const float* Ws = (m == 0 ? W0 : m == 1 ? W1m : m == 2 ? W2m : W3m) + (size_t)l * Hh * Hh;
    long dstOff = (m < 3) ? (long)m * Hh * Hh : (long)OFF_O;
    __half* th = g_wth + (size_t)l * LSTRIDE + dstOff;
    int n = blockIdx.x * 32 + threadIdx.x;
    #pragma unroll
    for (int i = 0; i < 4; i++) {
        int k = blockIdx.y * 32 + threadIdx.y + i * 8;
        t[threadIdx.y + i * 8][threadIdx.x] = Ws[(size_t)k * Hh + n];
    }
    __syncthreads();
    int k2 = blockIdx.y * 32 + threadIdx.x;
    #pragma unroll
    for (int i = 0; i < 4; i++) {
        int n2 = blockIdx.x * 32 + threadIdx.y + i * 8;
        th[(size_t)n2 * Hh + k2] = __float2half(t[threadIdx.x][threadIdx.y + i * 8]);
    }
}

__global__ void wsplit_kernel(const float* __restrict__ W, long dstOff, int K, int N) {
    __shared__ float t[32][33];
    int l = blockIdx.z;
    const float* Ws = W + (size_t)l * K * N;
    __half* th = g_wth + (size_t)l * LSTRIDE + dstOff;
    int n = blockIdx.x * 32 + threadIdx.x;
    #pragma unroll
    for (int i = 0; i < 4; i++) {
        int k = blockIdx.y * 32 + threadIdx.y + i * 8;
        t[threadIdx.y + i * 8][threadIdx.x] = Ws[(size_t)k * N + n];
    }
    __syncthreads();
    int k2 = blockIdx.y * 32 + threadIdx.x;
    #pragma unroll
    for (int i = 0; i < 4; i++) {
        int n2 = blockIdx.x * 32 + threadIdx.y + i * 8;
        th[(size_t)n2 * K + k2] = __float2half(t[threadIdx.x][threadIdx.y + i * 8]);
    }
}

__global__ void pack_bias_kernel(const float* __restrict__ bq, const float* __restrict__ bk,
                                 const float* __restrict__ bv) {
    int l = blockIdx.x, j = threadIdx.x;
    g_bqkv[l * QKVN + j]          = bq[l * Hh + j];
    g_bqkv[l * QKVN + Hh + j]     = bk[l * Hh + j];
    g_bqkv[l * QKVN + 2 * Hh + j] = bv[l * Hh + j];
}

// ---------------- embeddings + LN + mask bias ----------------
__global__ void embed_ln_kernel(const int* __restrict__ ids, const int* __restrict__ tys,
                                const float* __restrict__ word, const float* __restrict__ pos,
                                const float* __restrict__ typ,
                                const float* __restrict__ eg, const float* __restrict__ eb) {
    __shared__ float sred[9];
    int t = blockIdx.x;
    int s = t & (Ss - 1);
    int id = ids[t], ty = tys[t];
    float v[3];
    float loc = 0.f;
    #pragma unroll
    for (int i = 0; i < 3; i++) {
        int j = threadIdx.x + i * 256;
        v[i] = word[(size_t)id * Hh + j] + pos[(size_t)s * Hh + j] + typ[(size_t)ty * Hh + j];
        loc += v[i];
    }
    float mu = blk_sum256(loc, sred) * (1.0f / Hh);
    float l2 = 0.f;
    #pragma unroll
    for (int i = 0; i < 3; i++) { float d = v[i] - mu; l2 += d * d; }
    float var = blk_sum256(l2, sred) * (1.0f / Hh);
    float rstd = rsqrtf(var + EPS_LN);
    #pragma unroll
    for (int i = 0; i < 3; i++) {
        int j = threadIdx.x + i * 256;
        size_t idx = (size_t)t * Hh + j;
        float o = (v[i] - mu) * rstd * eg[j] + eb[j];
        g_x[idx] = o;
        split_store_h(o, &g_xhi[idx], &g_xlo[idx]);
    }
    if (threadIdx.x == 0) g_mbias[t] = (id > 0) ? 0.f : -10000.0f;
}

// ---------------- residual add (3-way) + LN (in place on x), fused fp16 split ----------------
__global__ void add_ln3_kernel(float* __restrict__ x, const float* __restrict__ y,
                               const float* __restrict__ y2,
                               const float* __restrict__ g, const float* __restrict__ b) {
    __shared__ float sred[9];
    size_t base = (size_t)blockIdx.x * Hh;
    float v[3];
    float loc = 0.f;
    #pragma unroll
    for (int i = 0; i < 3; i++) {
        int j = threadIdx.x + i * 256;
        v[i] = x[base + j] + y[base + j] + y2[base + j];
        loc += v[i];
    }
    float mu = blk_sum256(loc, sred) * (1.0f / Hh);
    float l2 = 0.f;
    #pragma unroll
    for (int i = 0; i < 3; i++) { float d = v[i] - mu; l2 += d * d; }
    float var = blk_sum256(l2, sred) * (1.0f / Hh);
    float rstd = rsqrtf(var + EPS_LN);
    #pragma unroll
    for (int i = 0; i < 3; i++) {
        int j = threadIdx.x + i * 256;
        float o = (v[i] - mu) * rstd * g[j] + b[j];
        x[base + j] = o;
        split_store_h(o, &g_xhi[base + j], &g_xlo[base + j]);
    }
}

// ---------------- HMMA 2-term fp16 GEMM: C[4096, N] = (Ah+Al) @ Bh^T + bias ----------------
// Supports K-split via gridDim.z: block z computes K range [z*Klen, (z+1)*Klen),
// z=0 writes Cf with bias, z=1 writes Cf2 with zero bias (summed later in add_ln3).
// CTA 128x128, K-chunk 64 (rows 144B), 2-stage cp.async, 8 warps, 2 CTAs/SM.
#define GT_ROW   144
#define GT_TILE  (128 * GT_ROW)        // 18432 B per sub-tile
#define GT_STAGE (3 * GT_TILE)         // Ah | Al | Bh = 55296
#define GSMEM    (2 * GT_STAGE)        // 110592
template <int OUTMODE>
__global__ void __launch_bounds__(256, 2) gemm_mma(
    const __half* __restrict__ Ahi, const __half* __restrict__ Alo,
    const __half* __restrict__ Bh,
    const float* __restrict__ bias,
    float* __restrict__ Cf, float* __restrict__ Cf2,
    __half* __restrict__ Chi, __half* __restrict__ Clo,
    int Kfull, int Klen, int ldc)
{
    extern __shared__ char sm[];
    const uint32_t sb = smem_u32(sm);
    int tid = threadIdx.x, lane = tid & 31, wid = tid >> 5;
    int wm = wid >> 2, wn = wid & 3;              // warp tile rows wm*64, cols wn*32
    int m0 = blockIdx.y * 128, n0 = blockIdx.x * 128;
    int kz = blockIdx.z;
    int kbase = kz * Klen;
    const float* bsel = (OUTMODE == 0 && kz) ? g_zeros : bias;
    float* csel = (OUTMODE == 0 && kz) ? Cf2 : Cf;

    // ldmatrix lane offsets (row stride 144B)
    int q = lane >> 3, r = lane & 7;
    uint32_t aLane = (uint32_t)(((q & 1) * 8 + r) * GT_ROW + (q >> 1) * 16);
    uint32_t bLane = (uint32_t)(((q >> 1) * 8 + r) * GT_ROW + (q & 1) * 16);

    float acc[4][4][4];
    #pragma unroll
    for (int mi = 0; mi < 4; mi++)
        #pragma unroll
        for (int ni = 0; ni < 4; ni++)
            #pragma unroll
            for (int e = 0; e < 4; e++) acc[mi][ni][e] = 0.f;

    int nchunk = Klen >> 6;                       // K-chunk = 64

    // loader: 3 tiles x 128 rows x 8 segs of 16B = 3072 cp.async; 12 per thread
    auto load_stage = [&](int c) {
        int k0 = kbase + (c << 6);
        uint32_t base = sb + (uint32_t)(c & 1) * GT_STAGE;
        #pragma unroll
        for (int i = 0; i < 12; i++) {
            int lin = tid + i * 256;              // 0..3071
            int tile = lin >> 10;                 // 0=Ah 1=Al 2=Bh
            int within = lin & 1023;
            int row = within >> 3, seg = within & 7;
            uint32_t dst = base + (uint32_t)tile * GT_TILE + (uint32_t)(row * GT_ROW + seg * 16);
            const __half* src;
            if (tile == 0)      src = Ahi + (size_t)(m0 + row) * Kfull + k0 + seg * 8;
            else if (tile == 1) src = Alo + (size_t)(m0 + row) * Kfull + k0 + seg * 8;
            else                src = Bh  + (size_t)(n0 + row) * Kfull + k0 + seg * 8;
            cp_async16(dst, src);
        }
    };

    load_stage(0);
    CP_COMMIT();

    for (int c = 0; c < nchunk; c++) {
        if (c + 1 < nchunk) { load_stage(c + 1); CP_COMMIT(); CP_WAIT(1); }
        else { CP_WAIT(0); }
        __syncthreads();

        uint32_t base = sb + (uint32_t)(c & 1) * GT_STAGE;
        uint32_t aBaseH = base + (uint32_t)((wm * 64) * GT_ROW) + aLane;
        uint32_t aBaseL = aBaseH + GT_TILE;
        uint32_t bBase  = base + 2 * GT_TILE + (uint32_t)((wn * 32) * GT_ROW) + bLane;

        #pragma unroll
        for (int ks = 0; ks < 4; ks++) {
            uint32_t ko = (uint32_t)(ks * 32);
            uint32_t ah[4][4], al[4][4], bf[2][4];
            #pragma unroll
            for (int mi = 0; mi < 4; mi++)
                ldsm4(ah[mi][0], ah[mi][1], ah[mi][2], ah[mi][3],
                      aBaseH + (uint32_t)(mi * 16 * GT_ROW) + ko);
            #pragma unroll
            for (int mi = 0; mi < 4; mi++)
                ldsm4(al[mi][0], al[mi][1], al[mi][2], al[mi][3],
                      aBaseL + (uint32_t)(mi * 16 * GT_ROW) + ko);
            #pragma unroll
            for (int p = 0; p < 2; p++)
                ldsm4(bf[p][0], bf[p][1], bf[p][2], bf[p][3],
                      bBase + (uint32_t)(p * 16 * GT_ROW) + ko);
            #pragma unroll
            for (int mi = 0; mi < 4; mi++)
                #pragma unroll
                for (int ni = 0; ni < 4; ni++) {
                    int p = ni >> 1, su = ni & 1;
                    mma16816(acc[mi][ni], ah[mi][0], ah[mi][1], ah[mi][2], ah[mi][3],
                             bf[p][su * 2], bf[p][su * 2 + 1]);
                }
            #pragma unroll
            for (int mi = 0; mi < 4; mi++)
                #pragma unroll
                for (int ni = 0; ni < 4; ni++) {
                    int p = ni >> 1, su = ni & 1;
                    mma16816(acc[mi][ni], al[mi][0], al[mi][1], al[mi][2], al[mi][3],
                             bf[p][su * 2], bf[p][su * 2 + 1]);
                }
        }
        __syncthreads();
    }

    // ---------------- epilogue ----------------
    int rbase = m0 + wm * 64 + (lane >> 2);
    int cbase = n0 + wn * 32 + (lane & 3) * 2;
    #pragma unroll
    for (int mi = 0; mi < 4; mi++) {
        #pragma unroll
        for (int ni = 0; ni < 4; ni++) {
            int row = rbase + mi * 16;
            int col = cbase + ni * 8;
            float b0 = bsel[col], b1 = bsel[col + 1];
            float v0 = acc[mi][ni][0] + b0, v1 = acc[mi][ni][1] + b1;
            float v2 = acc[mi][ni][2] + b0, v3 = acc[mi][ni][3] + b1;
            if (OUTMODE == 0) {
                *(float2*)(csel + (size_t)row * ldc + col)       = make_float2(v0, v1);
                *(float2*)(csel + (size_t)(row + 8) * ldc + col) = make_float2(v2, v3);
            } else {
                v0 = gelu_tanh(v0); v1 = gelu_tanh(v1);
                v2 = gelu_tanh(v2); v3 = gelu_tanh(v3);
                __half h0 = __float2half(v0), h1 = __float2half(v1);
                __half h2 = __float2half(v2), h3 = __float2half(v3);
                *(unsigned*)(Chi + (size_t)row * ldc + col) =
                    (unsigned)__half_as_ushort(h0) | ((unsigned)__half_as_ushort(h1) << 16);
                *(unsigned*)(Clo + (size_t)row * ldc + col) =
                    pack2h(v0 - __half2float(h0), v1 - __half2float(h1));
                *(unsigned*)(Chi + (size_t)(row + 8) * ldc + col) =
                    (unsigned)__half_as_ushort(h2) | ((unsigned)__half_as_ushort(h3) << 16);
                *(unsigned*)(Clo + (size_t)(row + 8) * ldc + col) =
                    pack2h(v2 - __half2float(h2), v3 - __half2float(h3));
            }
        }
    }
}

// ---------------- attention: one-pass, scores cached in smem ----------------
#define ATTN_SMEM ((2*Ss*DHh + Ss*129 + Ss) * (int)sizeof(float))
__global__ void __launch_bounds__(128) attn_kernel(const float* __restrict__ Qkv,
                                                   const float* __restrict__ bias,
                                                   __half* __restrict__ chi,
                                                   __half* __restrict__ clo) {
    extern __shared__ float smf[];
    float* Ks = smf;
    float* Vs = smf + Ss * DHh;
    float* S  = smf + 2 * Ss * DHh;
    float* biasS = S + Ss * 129;
    int bn = blockIdx.x;
    int b = bn / NHh, n = bn % NHh;
    int tid = threadIdx.x;
    const float scale = 0.125f;

    #pragma unroll
    for (int i = 0; i < 16; i++) {
        int linr = tid + i * 128;
        int j = linr >> 4, c4 = (linr & 15) * 4;
        size_t rowb = (size_t)(b * Ss + j) * QKVN + n * DHh + c4;
        *(float4*)&Ks[j * DHh + c4] = *(const float4*)(Qkv + rowb + Hh);
        *(float4*)&Vs[j * DHh + c4] = *(const float4*)(Qkv + rowb + 2 * Hh);
    }
    biasS[tid] = bias[b * Ss + tid];
    __syncthreads();

    int qi = tid;
    float Qr[DHh];
    const float4* qp = (const float4*)(Qkv + (size_t)(b * Ss + qi) * QKVN + n * DHh);
    #pragma unroll
    for (int i = 0; i < 16; i++) {
        float4 v4 = qp[i];
        Qr[i * 4 + 0] = v4.x; Qr[i * 4 + 1] = v4.y; Qr[i * 4 + 2] = v4.z; Qr[i * 4 + 3] = v4.w;
    }

    float* Srow = S + qi * 129;
    float m = -1e30f;
    #pragma unroll 1
    for (int j = 0; j < Ss; j += 4) {
        const float* k0 = Ks + j * DHh;
        float s0 = 0.f, s1 = 0.f, s2 = 0.f, s3 = 0.f;
        #pragma unroll
        for (int d = 0; d < DHh; d++) {
            float qd = Qr[d];
            s0 = fmaf(qd, k0[d], s0);
            s1 = fmaf(qd, k0[DHh + d], s1);
            s2 = fmaf(qd, k0[2 * DHh + d], s2);
            s3 = fmaf(qd, k0[3 * DHh + d], s3);
        }
        s0 = fmaf(s0, scale, biasS[j]);
        s1 = fmaf(s1, scale, biasS[j + 1]);
        s2 = fmaf(s2, scale, biasS[j + 2]);
        s3 = fmaf(s3, scale, biasS[j + 3]);
        Srow[j] = s0; Srow[j + 1] = s1; Srow[j + 2] = s2; Srow[j + 3] = s3;
        m = fmaxf(m, fmaxf(fmaxf(s0, s1), fmaxf(s2, s3)));
    }
    float lsum = 0.f;
    #pragma unroll 4
    for (int j = 0; j < Ss; j++) {
        float p = __expf(Srow[j] - m);
        Srow[j] = p;
        lsum += p;
    }
    float inv_l = 1.0f / lsum;

    float acc[DHh];
    #pragma unroll
    for (int d = 0; d < DHh; d++) acc[d] = 0.f;
    #pragma unroll 1
    for (int j = 0; j < Ss; j++) {
        float p = Srow[j];
        const float* vr = Vs + j * DHh;
        #pragma unroll
        for (int d = 0; d < DHh; d++) acc[d] = fmaf(p, vr[d], acc[d]);
    }
    size_t obase = (size_t)(b * Ss + qi) * Hh + n * DHh;
    #pragma unroll
    for (int d = 0; d < DHh; d += 2) {
        float v0 = acc[d] * inv_l, v1 = acc[d + 1] * inv_l;
        __half h0 = __float2half(v0), h1 = __float2half(v1);
        *(unsigned*)(chi + obase + d) =
            (unsigned)__half_as_ushort(h0) | ((unsigned)__half_as_ushort(h1) << 16);
        *(unsigned*)(clo + obase + d) =
            pack2h(v0 - __half2float(h0), v1 - __half2float(h1));
    }
}

// ---------------- CLS extraction + norm ----------------
__global__ void cls_kernel() {
    __shared__ float sred[9];
    int b = blockIdx.x;
    float loc = 0.f;
    #pragma unroll
    for (int i = 0; i < 3; i++) {
        int j = threadIdx.x + i * 256;
        float v = g_x[(size_t)(b * Ss) * Hh + j];
        g_cls[b * Hh + j] = v;
        loc += v * v;
    }
    float s = blk_sum256(loc, sred);
    if (threadIdx.x == 0) g_cn[b] = fmaxf(sqrtf(s), EPS_COS);
}

__global__ void reset_best_kernel() {
    if (threadIdx.x < Bb) g_best[threadIdx.x] = 0ull;
}

// ---------------- cosine + per-block argmax reduction ----------------
__global__ void __launch_bounds__(128) cos_kernel(const float* __restrict__ lab,
                                                  float* __restrict__ out) {
    __shared__ float clsS[Bb][33];
    __shared__ float sInvCn[Bb];
    int l = blockIdx.x * 128 + threadIdx.x;
    bool valid = (l < NLl);
    if (threadIdx.x < Bb) sInvCn[threadIdx.x] = 1.0f / g_cn[threadIdx.x];

    float acc[Bb];
    #pragma unroll
    for (int bb = 0; bb < Bb; bb++) acc[bb] = 0.f;

    for (int k0 = 0; k0 < Hh; k0 += 32) {
        #pragma unroll
        for (int i = 0; i < 8; i++) {
            int idx = threadIdx.x + i * 128;
            int bb = idx >> 5, kk = idx & 31;
            clsS[bb][kk] = g_cls[bb * Hh + k0 + kk];
        }
        __syncthreads();
        if (valid) {
            float lv[32];
            const float4* lp = (const float4*)(lab + (size_t)l * Hh + k0);
            #pragma unroll
            for (int i = 0; i < 8; i++) {
                float4 v4 = lp[i];
                lv[i * 4] = v4.x; lv[i * 4 + 1] = v4.y; lv[i * 4 + 2] = v4.z; lv[i * 4 + 3] = v4.w;
            }
            #pragma unroll
            for (int bb = 0; bb < Bb; bb++) {
                float a = acc[bb];
                #pragma unroll
                for (int kk = 0; kk < 32; kk++) a = fmaf(clsS[bb][kk], lv[kk], a);
                acc[bb] = a;
            }
        }
        __syncthreads();
    }

    float invl = 0.f;
    if (valid) {
        float s = 0.f;
        const float4* lp = (const float4*)(lab + (size_t)l * Hh);
        #pragma unroll 4
        for (int i = 0; i < Hh / 4; i++) {
            float4 v4 = lp[i];
            s += v4.x * v4.x + v4.y * v4.y + v4.z * v4.z + v4.w * v4.w;
        }
        invl = 1.0f / fmaxf(sqrtf(s), EPS_COS);
    }

    int lane = threadIdx.x & 31;
    #pragma unroll 1
    for (int bb = 0; bb < Bb; bb++) {
        unsigned long long key = 0ull;
        if (valid) {
            float c = acc[bb] * invl * sInvCn[bb];
            out[(size_t)bb * NLl + l] = c;
            key = pack_key(c, l);
        }
        #pragma unroll
        for (int o = 16; o > 0; o >>= 1) {
            unsigned long long other = __shfl_down_sync(0xffffffffu, key, o);
            key = (other > key) ? other : key;
        }
        if (lane == 0) atomicMax(&g_best[bb], key);
    }
}

__global__ void ids_out_kernel(float* __restrict__ out) {
    int b = threadIdx.x;
    if (b < Bb) {
        unsigned idpart = (unsigned)(g_best[b] & 0xFFFFFFFFull);
        out[(size_t)Bb * NLl + b] = (float)(0xFFFFFFFFu - idpart);
    }
}

// ---------------- host orchestration ----------------
extern "C" void kernel_launch(void* const* d_in, const int* in_sizes, int n_in,
                              void* d_out, int out_size) {
    const int*   ids  = (const int*)d_in[0];
    const int*   tys  = (const int*)d_in[1];
    const float* word = (const float*)d_in[2];
    const float* pos  = (const float*)d_in[3];
    const float* typ  = (const float*)d_in[4];
    const float* eg   = (const float*)d_in[5];
    const float* eb   = (const float*)d_in[6];
    const float* Wq   = (const float*)d_in[7];
    const float* bq   = (const float*)d_in[8];
    const float* Wk   = (const float*)d_in[9];
    const float* bk   = (const float*)d_in[10];
    const float* Wv   = (const float*)d_in[11];
    const float* bv   = (const float*)d_in[12];
    const float* Wo   = (const float*)d_in[13];
    const float* bo   = (const float*)d_in[14];
    const float* g1   = (const float*)d_in[15];
    const float* be1  = (const float*)d_in[16];
    const float* W1   = (const float*)d_in[17];
    const float* b1   = (const float*)d_in[18];
    const float* W2   = (const float*)d_in[19];
    const float* b2   = (const float*)d_in[20];
    const float* g2   = (const float*)d_in[21];
    const float* be2  = (const float*)d_in[22];
    const float* lab  = (const float*)d_in[23];
    float* out = (float*)d_out;

    float *px, *py, *py2, *pqkv, *pmbias, *pbqkv;
    __half *pxhi, *pxlo, *pchi, *pclo, *phhi, *phlo, *pwth;
    cudaGetSymbolAddress((void**)&px,    g_x);
    cudaGetSymbolAddress((void**)&py,    g_y);
    cudaGetSymbolAddress((void**)&py2,   g_y2);
    cudaGetSymbolAddress((void**)&pqkv,  g_qkv);
    cudaGetSymbolAddress((void**)&pmbias,g_mbias);
    cudaGetSymbolAddress((void**)&pbqkv, g_bqkv);
    cudaGetSymbolAddress((void**)&pxhi,  g_xhi);
    cudaGetSymbolAddress((void**)&pxlo,  g_xlo);
    cudaGetSymbolAddress((void**)&pchi,  g_chi);
    cudaGetSymbolAddress((void**)&pclo,  g_clo);
    cudaGetSymbolAddress((void**)&phhi,  g_hhi);
    cudaGetSymbolAddress((void**)&phlo,  g_hlo);
    cudaGetSymbolAddress((void**)&pwth,  g_wth);

    cudaFuncSetAttribute(attn_kernel, cudaFuncAttributeMaxDynamicSharedMemorySize, ATTN_SMEM);
    cudaFuncSetAttribute(gemm_mma<0>, cudaFuncAttributeMaxDynamicSharedMemorySize, GSMEM);
    cudaFuncSetAttribute(gemm_mma<1>, cudaFuncAttributeMaxDynamicSharedMemorySize, GSMEM);

    // minimal prefix before the first GEMM so the ncu capture window lands on it:
    // wsplit4(1), embed(2), pack_bias(3), QKV-GEMM(4) ...
    dim3 tb(32, 8);
    wsplit4_kernel<<<dim3(24, 24, 48), tb>>>(Wq, Wk, Wv, Wo);                 // 1
    embed_ln_kernel<<<NTOK, 256>>>(ids, tys, word, pos, typ, eg, eb);         // 2
    pack_bias_kernel<<<Ll, Hh>>>(bq, bk, bv);                                 // 3

    for (int l = 0; l < Ll; l++) {
        size_t wl = (size_t)l * LSTRIDE;
        // QKV: full K, single output
        gemm_mma<0><<<dim3(QKVN / 128, 32, 1), 256, GSMEM>>>(                 // 4 on l==0
            pxhi, pxlo, pwth + wl, pbqkv + l * QKVN,
            pqkv, nullptr, nullptr, nullptr, Hh, Hh, QKVN);
        attn_kernel<<<Bb * NHh, 128, ATTN_SMEM>>>(pqkv, pmbias, pchi, pclo);
        if (l == 0) {
            wsplit_kernel<<<dim3(FFf / 32, Hh / 32, Ll), tb>>>(W1, OFF_W1, Hh, FFf);
            wsplit_kernel<<<dim3(Hh / 32, FFf / 32, Ll), tb>>>(W2, OFF_W2, FFf, Hh);
        }
        // O projection: split-K=2 (z=0 -> y with bias, z=1 -> y2 zero-bias)
        gemm_mma<0><<<dim3(Hh / 128, 32, 2), 256, GSMEM>>>(
            pchi, pclo, pwth + wl + OFF_O, bo + (size_t)l * Hh,
            py, py2, nullptr, nullptr, Hh, Hh / 2, Hh);
        add_ln3_kernel<<<NTOK, 256>>>(px, py, py2,
                                      g1 + (size_t)l * Hh, be1 + (size_t)l * Hh);
        // FFN up + GELU: full K
        gemm_mma<1><<<dim3(FFf / 128, 32, 1), 256, GSMEM>>>(
            pxhi, pxlo, pwth + wl + OFF_W1, b1 + (size_t)l * FFf,
            nullptr, nullptr, phhi, phlo, Hh, Hh, FFf);
        // FFN down: split-K=2
        gemm_mma<0><<<dim3(Hh / 128, 32, 2), 256, GSMEM>>>(
            phhi, phlo, pwth + wl + OFF_W2, b2 + (size_t)l * Hh,
            py, py2, nullptr, nullptr, FFf, FFf / 2, Hh);
        add_ln3_kernel<<<NTOK, 256>>>(px, py, py2,
                                      g2 + (size_t)l * Hh, be2 + (size_t)l * Hh);
    }

    cls_kernel<<<Bb, 256>>>();
    reset_best_kernel<<<1, 32>>>();
    cos_kernel<<<(NLl + 127) / 128, 128>>>(lab, out);
    if (out_size >= Bb * NLl + Bb) ids_out_kernel<<<1, 32>>>(out);
}

// round 9
// speedup vs baseline: 1.1911x; 1.0017x over previous
#include <cuda_runtime.h>
#include <cuda_fp16.h>
#include <math.h>
#include <cstdint>

// ---------------- problem constants ----------------
#define Vv   30522
#define Hh   768
#define Ll   12
#define FFf  3072
#define NHh  12
#define DHh  64
#define Bb   32
#define Ss   128
#define NLl  10000
#define NTOK (Bb*Ss)          // 4096
#define QKVN (3*Hh)           // 2304
#define EPS_LN  1e-12f
#define EPS_COS 1e-8f

// transposed fp16 weight layout per layer (element offsets)
#define OFF_O   (QKVN*Hh)             // after packed qkv [2304][768]
#define OFF_W1  (OFF_O + Hh*Hh)       // [3072][768]
#define OFF_W2  (OFF_W1 + Hh*FFf)     // [768][3072]
#define LSTRIDE (OFF_W2 + FFf*Hh)     // 7,077,888

// ---------------- device scratch ----------------
__device__ __half g_wth[Ll*LSTRIDE];           // fp16 weights, transposed [N][K]
__device__ float  g_bqkv[Ll*QKVN];
__device__ float  g_zeros[Hh];                 // stays zero (module-load zero-init)

__device__ float  g_x  [NTOK*Hh];
__device__ __half g_xhi[NTOK*Hh];
__device__ __half g_xlo[NTOK*Hh];
__device__ float  g_qkv[NTOK*QKVN];
__device__ __half g_chi[NTOK*Hh];
__device__ __half g_clo[NTOK*Hh];
__device__ __half g_hhi[NTOK*FFf];
__device__ __half g_hlo[NTOK*FFf];
__device__ float  g_y  [NTOK*Hh];
__device__ float  g_y2 [NTOK*Hh];
__device__ float g_mbias[NTOK];
__device__ float g_cls[Bb*Hh];
__device__ float g_cn [Bb];
__device__ unsigned long long g_best[Bb];

// ---------------- PTX helpers (compute_100-safe) ----------------
__device__ __forceinline__ uint32_t smem_u32(const void* p) {
    uint32_t a;
    asm("{ .reg .u64 t; cvta.to.shared.u64 t, %1; cvt.u32.u64 %0, t; }" : "=r"(a) : "l"(p));
    return a;
}
__device__ __forceinline__ void cp_async16(uint32_t dst, const void* src) {
    asm volatile("cp.async.cg.shared.global [%0], [%1], 16;" :: "r"(dst), "l"(src) : "memory");
}
#define CP_COMMIT() asm volatile("cp.async.commit_group;" ::: "memory")
#define CP_WAIT(n)  asm volatile("cp.async.wait_group %0;" :: "n"(n) : "memory")

__device__ __forceinline__ void ldsm4(uint32_t& r0, uint32_t& r1, uint32_t& r2, uint32_t& r3,
                                      uint32_t addr) {
    asm volatile("ldmatrix.sync.aligned.m8n8.x4.shared.b16 {%0,%1,%2,%3}, [%4];"
                 : "=r"(r0), "=r"(r1), "=r"(r2), "=r"(r3) : "r"(addr));
}
__device__ __forceinline__ void mma16816(float* c, uint32_t a0, uint32_t a1, uint32_t a2,
                                         uint32_t a3, uint32_t b0, uint32_t b1) {
    asm volatile(
        "mma.sync.aligned.m16n8k16.row.col.f32.f16.f16.f32 "
        "{%0,%1,%2,%3}, {%4,%5,%6,%7}, {%8,%9}, {%0,%1,%2,%3};"
        : "+f"(c[0]), "+f"(c[1]), "+f"(c[2]), "+f"(c[3])
        : "r"(a0), "r"(a1), "r"(a2), "r"(a3), "r"(b0), "r"(b1));
}

// ---------------- misc helpers ----------------
__device__ __forceinline__ float blk_sum256(float v, volatile float* sred) {
    int lane = threadIdx.x & 31, w = threadIdx.x >> 5;
    #pragma unroll
    for (int o = 16; o > 0; o >>= 1) v += __shfl_down_sync(0xffffffffu, v, o);
    if (lane == 0) sred[w] = v;
    __syncthreads();
    if (threadIdx.x == 0) {
        float s = 0.f;
        #pragma unroll
        for (int i = 0; i < 8; i++) s += sred[i];
        sred[8] = s;
    }
    __syncthreads();
    float r = sred[8];
    __syncthreads();
    return r;
}
__device__ __forceinline__ float gelu_tanh(float x) {
    float x3 = x * x * x;
    float t = tanhf(0.7978845608028654f * (x + 0.044715f * x3));
    return 0.5f * x * (1.0f + t);
}
__device__ __forceinline__ unsigned long long pack_key(float c, int l) {
    unsigned u = __float_as_uint(c);
    u = (u & 0x80000000u) ? ~u : (u | 0x80000000u);
    return ((unsigned long long)u << 32) | (unsigned long long)(0xFFFFFFFFu - (unsigned)l);
}
__device__ __forceinline__ void split_store_h(float v, __half* hi, __half* lo) {
    __half h = __float2half(v);
    *hi = h;
    *lo = __float2half(v - __half2float(h));
}
__device__ __forceinline__ unsigned pack2h(float v0, float v1) {
    __half h0 = __float2half(v0), h1 = __float2half(v1);
    return (unsigned)__half_as_ushort(h0) | ((unsigned)__half_as_ushort(h1) << 16);
}

// ---------------- weight transpose to fp16 ----------------
__global__ void wsplit4_kernel(const float* __restrict__ W0, const float* __restrict__ W1m,
                               const float* __restrict__ W2m, const float* __restrict__ W3m) {
    __shared__ float t[32][33];
    int z = blockIdx.z;
    int m = z & 3, l = z >> 2;
    const float* Ws = (m == 0 ? W0 : m == 1 ? W1m : m == 2 ? W2m : W3m) + (size_t)l * Hh * Hh;
    long dstOff = (m < 3) ? (long)m * Hh * Hh : (long)OFF_O;
    __half* th = g_wth + (size_t)l * LSTRIDE + dstOff;
    int n = blockIdx.x * 32 + threadIdx.x;
    #pragma unroll
    for (int i = 0; i < 4; i++) {
        int k = blockIdx.y * 32 + threadIdx.y + i * 8;
        t[threadIdx.y + i * 8][threadIdx.x] = Ws[(size_t)k * Hh + n];
    }
    __syncthreads();
    int k2 = blockIdx.y * 32 + threadIdx.x;
    #pragma unroll
    for (int i = 0; i < 4; i++) {
        int n2 = blockIdx.x * 32 + threadIdx.y + i * 8;
        th[(size_t)n2 * Hh + k2] = __float2half(t[threadIdx.x][threadIdx.y + i * 8]);
    }
}

__global__ void wsplit_kernel(const float* __restrict__ W, long dstOff, int K, int N) {
    __shared__ float t[32][33];
    int l = blockIdx.z;
    const float* Ws = W + (size_t)l * K * N;
    __half* th = g_wth + (size_t)l * LSTRIDE + dstOff;
    int n = blockIdx.x * 32 + threadIdx.x;
    #pragma unroll
    for (int i = 0; i < 4; i++) {
        int k = blockIdx.y * 32 + threadIdx.y + i * 8;
        t[threadIdx.y + i * 8][threadIdx.x] = Ws[(size_t)k * N + n];
    }
    __syncthreads();
    int k2 = blockIdx.y * 32 + threadIdx.x;
    #pragma unroll
    for (int i = 0; i < 4; i++) {
        int n2 = blockIdx.x * 32 + threadIdx.y + i * 8;
        th[(size_t)n2 * K + k2] = __float2half(t[threadIdx.x][threadIdx.y + i * 8]);
    }
}

__global__ void pack_bias_kernel(const float* __restrict__ bq, const float* __restrict__ bk,
                                 const float* __restrict__ bv) {
    int l = blockIdx.x, j = threadIdx.x;
    g_bqkv[l * QKVN + j]          = bq[l * Hh + j];
    g_bqkv[l * QKVN + Hh + j]     = bk[l * Hh + j];
    g_bqkv[l * QKVN + 2 * Hh + j] = bv[l * Hh + j];
}

// ---------------- embeddings + LN + mask bias ----------------
__global__ void embed_ln_kernel(const int* __restrict__ ids, const int* __restrict__ tys,
                                const float* __restrict__ word, const float* __restrict__ pos,
                                const float* __restrict__ typ,
                                const float* __restrict__ eg, const float* __restrict__ eb) {
    __shared__ float sred[9];
    int t = blockIdx.x;
    int s = t & (Ss - 1);
    int id = ids[t], ty = tys[t];
    float v[3];
    float loc = 0.f;
    #pragma unroll
    for (int i = 0; i < 3; i++) {
        int j = threadIdx.x + i * 256;
        v[i] = word[(size_t)id * Hh + j] + pos[(size_t)s * Hh + j] + typ[(size_t)ty * Hh + j];
        loc += v[i];
    }
    float mu = blk_sum256(loc, sred) * (1.0f / Hh);
    float l2 = 0.f;
    #pragma unroll
    for (int i = 0; i < 3; i++) { float d = v[i] - mu; l2 += d * d; }
    float var = blk_sum256(l2, sred) * (1.0f / Hh);
    float rstd = rsqrtf(var + EPS_LN);
    #pragma unroll
    for (int i = 0; i < 3; i++) {
        int j = threadIdx.x + i * 256;
        size_t idx = (size_t)t * Hh + j;
        float o = (v[i] - mu) * rstd * eg[j] + eb[j];
        g_x[idx] = o;
        split_store_h(o, &g_xhi[idx], &g_xlo[idx]);
    }
    if (threadIdx.x == 0) g_mbias[t] = (id > 0) ? 0.f : -10000.0f;
}

// ---------------- residual add (3-way) + LN (in place on x), fused fp16 split ----------------
__global__ void add_ln3_kernel(float* __restrict__ x, const float* __restrict__ y,
                               const float* __restrict__ y2,
                               const float* __restrict__ g, const float* __restrict__ b) {
    __shared__ float sred[9];
    size_t base = (size_t)blockIdx.x * Hh;
    float v[3];
    float loc = 0.f;
    #pragma unroll
    for (int i = 0; i < 3; i++) {
        int j = threadIdx.x + i * 256;
        v[i] = x[base + j] + y[base + j] + y2[base + j];
        loc += v[i];
    }
    float mu = blk_sum256(loc, sred) * (1.0f / Hh);
    float l2 = 0.f;
    #pragma unroll
    for (int i = 0; i < 3; i++) { float d = v[i] - mu; l2 += d * d; }
    float var = blk_sum256(l2, sred) * (1.0f / Hh);
    float rstd = rsqrtf(var + EPS_LN);
    #pragma unroll
    for (int i = 0; i < 3; i++) {
        int j = threadIdx.x + i * 256;
        float o = (v[i] - mu) * rstd * g[j] + b[j];
        x[base + j] = o;
        split_store_h(o, &g_xhi[base + j], &g_xlo[base + j]);
    }
}

// ---------------- HMMA 2-term fp16 GEMM: C[4096, N] = (Ah+Al) @ Bh^T + bias ----------------
// Supports K-split via gridDim.z: block z computes K range [z*Klen, (z+1)*Klen),
// z=0 writes Cf with bias, z=1 writes Cf2 with zero bias (summed later in add_ln3).
// CTA 128x128, K-chunk 64 (rows 144B), 2-stage cp.async, 8 warps, 2 CTAs/SM.
#define GT_ROW   144
#define GT_TILE  (128 * GT_ROW)        // 18432 B per sub-tile
#define GT_STAGE (3 * GT_TILE)         // Ah | Al | Bh = 55296
#define GSMEM    (2 * GT_STAGE)        // 110592
template <int OUTMODE>
__global__ void __launch_bounds__(256, 2) gemm_mma(
    const __half* __restrict__ Ahi, const __half* __restrict__ Alo,
    const __half* __restrict__ Bh,
    const float* __restrict__ bias,
    float* __restrict__ Cf, float* __restrict__ Cf2,
    __half* __restrict__ Chi, __half* __restrict__ Clo,
    int Kfull, int Klen, int ldc)
{
    extern __shared__ char sm[];
    const uint32_t sb = smem_u32(sm);
    int tid = threadIdx.x, lane = tid & 31, wid = tid >> 5;
    int wm = wid >> 2, wn = wid & 3;              // warp tile rows wm*64, cols wn*32
    int m0 = blockIdx.y * 128, n0 = blockIdx.x * 128;
    int kz = blockIdx.z;
    int kbase = kz * Klen;
    const float* bsel = (OUTMODE == 0 && kz) ? g_zeros : bias;
    float* csel = (OUTMODE == 0 && kz) ? Cf2 : Cf;

    // ldmatrix lane offsets (row stride 144B)
    int q = lane >> 3, r = lane & 7;
    uint32_t aLane = (uint32_t)(((q & 1) * 8 + r) * GT_ROW + (q >> 1) * 16);
    uint32_t bLane = (uint32_t)(((q >> 1) * 8 + r) * GT_ROW + (q & 1) * 16);

    float acc[4][4][4];
    #pragma unroll
    for (int mi = 0; mi < 4; mi++)
        #pragma unroll
        for (int ni = 0; ni < 4; ni++)
            #pragma unroll
            for (int e = 0; e < 4; e++) acc[mi][ni][e] = 0.f;

    int nchunk = Klen >> 6;                       // K-chunk = 64

    // loader: 3 tiles x 128 rows x 8 segs of 16B = 3072 cp.async; 12 per thread
    auto load_stage = [&](int c) {
        int k0 = kbase + (c << 6);
        uint32_t base = sb + (uint32_t)(c & 1) * GT_STAGE;
        #pragma unroll
        for (int i = 0; i < 12; i++) {
            int lin = tid + i * 256;              // 0..3071
            int tile = lin >> 10;                 // 0=Ah 1=Al 2=Bh
            int within = lin & 1023;
            int row = within >> 3, seg = within & 7;
            uint32_t dst = base + (uint32_t)tile * GT_TILE + (uint32_t)(row * GT_ROW + seg * 16);
            const __half* src;
            if (tile == 0)      src = Ahi + (size_t)(m0 + row) * Kfull + k0 + seg * 8;
            else if (tile == 1) src = Alo + (size_t)(m0 + row) * Kfull + k0 + seg * 8;
            else                src = Bh  + (size_t)(n0 + row) * Kfull + k0 + seg * 8;
            cp_async16(dst, src);
        }
    };

    load_stage(0);
    CP_COMMIT();

    for (int c = 0; c < nchunk; c++) {
        if (c + 1 < nchunk) { load_stage(c + 1); CP_COMMIT(); CP_WAIT(1); }
        else { CP_WAIT(0); }
        __syncthreads();

        uint32_t base = sb + (uint32_t)(c & 1) * GT_STAGE;
        uint32_t aBaseH = base + (uint32_t)((wm * 64) * GT_ROW) + aLane;
        uint32_t aBaseL = aBaseH + GT_TILE;
        uint32_t bBase  = base + 2 * GT_TILE + (uint32_t)((wn * 32) * GT_ROW) + bLane;

        #pragma unroll
        for (int ks = 0; ks < 4; ks++) {
            uint32_t ko = (uint32_t)(ks * 32);
            uint32_t ah[4][4], al[4][4], bf[2][4];
            #pragma unroll
            for (int mi = 0; mi < 4; mi++)
                ldsm4(ah[mi][0], ah[mi][1], ah[mi][2], ah[mi][3],
                      aBaseH + (uint32_t)(mi * 16 * GT_ROW) + ko);
            #pragma unroll
            for (int mi = 0; mi < 4; mi++)
                ldsm4(al[mi][0], al[mi][1], al[mi][2], al[mi][3],
                      aBaseL + (uint32_t)(mi * 16 * GT_ROW) + ko);
            #pragma unroll
            for (int p = 0; p < 2; p++)
                ldsm4(bf[p][0], bf[p][1], bf[p][2], bf[p][3],
                      bBase + (uint32_t)(p * 16 * GT_ROW) + ko);
            #pragma unroll
            for (int mi = 0; mi < 4; mi++)
                #pragma unroll
                for (int ni = 0; ni < 4; ni++) {
                    int p = ni >> 1, su = ni & 1;
                    mma16816(acc[mi][ni], ah[mi][0], ah[mi][1], ah[mi][2], ah[mi][3],
                             bf[p][su * 2], bf[p][su * 2 + 1]);
                }
            #pragma unroll
            for (int mi = 0; mi < 4; mi++)
                #pragma unroll
                for (int ni = 0; ni < 4; ni++) {
                    int p = ni >> 1, su = ni & 1;
                    mma16816(acc[mi][ni], al[mi][0], al[mi][1], al[mi][2], al[mi][3],
                             bf[p][su * 2], bf[p][su * 2 + 1]);
                }
        }
        __syncthreads();
    }

    // ---------------- epilogue ----------------
    int rbase = m0 + wm * 64 + (lane >> 2);
    int cbase = n0 + wn * 32 + (lane & 3) * 2;
    #pragma unroll
    for (int mi = 0; mi < 4; mi++) {
        #pragma unroll
        for (int ni = 0; ni < 4; ni++) {
            int row = rbase + mi * 16;
            int col = cbase + ni * 8;
            float b0 = bsel[col], b1 = bsel[col + 1];
            float v0 = acc[mi][ni][0] + b0, v1 = acc[mi][ni][1] + b1;
            float v2 = acc[mi][ni][2] + b0, v3 = acc[mi][ni][3] + b1;
            if (OUTMODE == 0) {
                *(float2*)(csel + (size_t)row * ldc + col)       = make_float2(v0, v1);
                *(float2*)(csel + (size_t)(row + 8) * ldc + col) = make_float2(v2, v3);
            } else {
                v0 = gelu_tanh(v0); v1 = gelu_tanh(v1);
                v2 = gelu_tanh(v2); v3 = gelu_tanh(v3);
                __half h0 = __float2half(v0), h1 = __float2half(v1);
                __half h2 = __float2half(v2), h3 = __float2half(v3);
                *(unsigned*)(Chi + (size_t)row * ldc + col) =
                    (unsigned)__half_as_ushort(h0) | ((unsigned)__half_as_ushort(h1) << 16);
                *(unsigned*)(Clo + (size_t)row * ldc + col) =
                    pack2h(v0 - __half2float(h0), v1 - __half2float(h1));
                *(unsigned*)(Chi + (size_t)(row + 8) * ldc + col) =
                    (unsigned)__half_as_ushort(h2) | ((unsigned)__half_as_ushort(h3) << 16);
                *(unsigned*)(Clo + (size_t)(row + 8) * ldc + col) =
                    pack2h(v2 - __half2float(h2), v3 - __half2float(h3));
            }
        }
    }
}

// ---------------- attention: one-pass, scores cached in smem ----------------
#define ATTN_SMEM ((2*Ss*DHh + Ss*129 + Ss) * (int)sizeof(float))
__global__ void __launch_bounds__(128) attn_kernel(const float* __restrict__ Qkv,
                                                   const float* __restrict__ bias,
                                                   __half* __restrict__ chi,
                                                   __half* __restrict__ clo) {
    extern __shared__ float smf[];
    float* Ks = smf;
    float* Vs = smf + Ss * DHh;
    float* S  = smf + 2 * Ss * DHh;
    float* biasS = S + Ss * 129;
    int bn = blockIdx.x;
    int b = bn / NHh, n = bn % NHh;
    int tid = threadIdx.x;
    const float scale = 0.125f;

    #pragma unroll
    for (int i = 0; i < 16; i++) {
        int linr = tid + i * 128;
        int j = linr >> 4, c4 = (linr & 15) * 4;
        size_t rowb = (size_t)(b * Ss + j) * QKVN + n * DHh + c4;
        *(float4*)&Ks[j * DHh + c4] = *(const float4*)(Qkv + rowb + Hh);
        *(float4*)&Vs[j * DHh + c4] = *(const float4*)(Qkv + rowb + 2 * Hh);
    }
    biasS[tid] = bias[b * Ss + tid];
    __syncthreads();

    int qi = tid;
    float Qr[DHh];
    const float4* qp = (const float4*)(Qkv + (size_t)(b * Ss + qi) * QKVN + n * DHh);
    #pragma unroll
    for (int i = 0; i < 16; i++) {
        float4 v4 = qp[i];
        Qr[i * 4 + 0] = v4.x; Qr[i * 4 + 1] = v4.y; Qr[i * 4 + 2] = v4.z; Qr[i * 4 + 3] = v4.w;
    }

    float* Srow = S + qi * 129;
    float m = -1e30f;
    #pragma unroll 1
    for (int j = 0; j < Ss; j += 4) {
        const float* k0 = Ks + j * DHh;
        float s0 = 0.f, s1 = 0.f, s2 = 0.f, s3 = 0.f;
        #pragma unroll
        for (int d = 0; d < DHh; d++) {
            float qd = Qr[d];
            s0 = fmaf(qd, k0[d], s0);
            s1 = fmaf(qd, k0[DHh + d], s1);
            s2 = fmaf(qd, k0[2 * DHh + d], s2);
            s3 = fmaf(qd, k0[3 * DHh + d], s3);
        }
        s0 = fmaf(s0, scale, biasS[j]);
        s1 = fmaf(s1, scale, biasS[j + 1]);
        s2 = fmaf(s2, scale, biasS[j + 2]);
        s3 = fmaf(s3, scale, biasS[j + 3]);
        Srow[j] = s0; Srow[j + 1] = s1; Srow[j + 2] = s2; Srow[j + 3] = s3;
        m = fmaxf(m, fmaxf(fmaxf(s0, s1), fmaxf(s2, s3)));
    }
    float lsum = 0.f;
    #pragma unroll 4
    for (int j = 0; j < Ss; j++) {
        float p = __expf(Srow[j] - m);
        Srow[j] = p;
        lsum += p;
    }
    float inv_l = 1.0f / lsum;

    float acc[DHh];
    #pragma unroll
    for (int d = 0; d < DHh; d++) acc[d] = 0.f;
    #pragma unroll 1
    for (int j = 0; j < Ss; j++) {
        float p = Srow[j];
        const float* vr = Vs + j * DHh;
        #pragma unroll
        for (int d = 0; d < DHh; d++) acc[d] = fmaf(p, vr[d], acc[d]);
    }
    size_t obase = (size_t)(b * Ss + qi) * Hh + n * DHh;
    #pragma unroll
    for (int d = 0; d < DHh; d += 2) {
        float v0 = acc[d] * inv_l, v1 = acc[d + 1] * inv_l;
        __half h0 = __float2half(v0), h1 = __float2half(v1);
        *(unsigned*)(chi + obase + d) =
            (unsigned)__half_as_ushort(h0) | ((unsigned)__half_as_ushort(h1) << 16);
        *(unsigned*)(clo + obase + d) =
            pack2h(v0 - __half2float(h0), v1 - __half2float(h1));
    }
}

// ---------------- CLS extraction + norm ----------------
__global__ void cls_kernel() {
    __shared__ float sred[9];
    int b = blockIdx.x;
    float loc = 0.f;
    #pragma unroll
    for (int i = 0; i < 3; i++) {
        int j = threadIdx.x + i * 256;
        float v = g_x[(size_t)(b * Ss) * Hh + j];
        g_cls[b * Hh + j] = v;
        loc += v * v;
    }
    float s = blk_sum256(loc, sred);
    if (threadIdx.x == 0) g_cn[b] = fmaxf(sqrtf(s), EPS_COS);
}

__global__ void reset_best_kernel() {
    if (threadIdx.x < Bb) g_best[threadIdx.x] = 0ull;
}

// ---------------- cosine + per-block argmax reduction ----------------
__global__ void __launch_bounds__(128) cos_kernel(const float* __restrict__ lab,
                                                  float* __restrict__ out) {
    __shared__ float clsS[Bb][33];
    __shared__ float sInvCn[Bb];
    int l = blockIdx.x * 128 + threadIdx.x;
    bool valid = (l < NLl);
    if (threadIdx.x < Bb) sInvCn[threadIdx.x] = 1.0f / g_cn[threadIdx.x];

    float acc[Bb];
    #pragma unroll
    for (int bb = 0; bb < Bb; bb++) acc[bb] = 0.f;

    for (int k0 = 0; k0 < Hh; k0 += 32) {
        #pragma unroll
        for (int i = 0; i < 8; i++) {
            int idx = threadIdx.x + i * 128;
            int bb = idx >> 5, kk = idx & 31;
            clsS[bb][kk] = g_cls[bb * Hh + k0 + kk];
        }
        __syncthreads();
        if (valid) {
            float lv[32];
            const float4* lp = (const float4*)(lab + (size_t)l * Hh + k0);
            #pragma unroll
            for (int i = 0; i < 8; i++) {
                float4 v4 = lp[i];
                lv[i * 4] = v4.x; lv[i * 4 + 1] = v4.y; lv[i * 4 + 2] = v4.z; lv[i * 4 + 3] = v4.w;
            }
            #pragma unroll
            for (int bb = 0; bb < Bb; bb++) {
                float a = acc[bb];
                #pragma unroll
                for (int kk = 0; kk < 32; kk++) a = fmaf(clsS[bb][kk], lv[kk], a);
                acc[bb] = a;
            }
        }
        __syncthreads();
    }

    float invl = 0.f;
    if (valid) {
        float s = 0.f;
        const float4* lp = (const float4*)(lab + (size_t)l * Hh);
        #pragma unroll 4
        for (int i = 0; i < Hh / 4; i++) {
            float4 v4 = lp[i];
            s += v4.x * v4.x + v4.y * v4.y + v4.z * v4.z + v4.w * v4.w;
        }
        invl = 1.0f / fmaxf(sqrtf(s), EPS_COS);
    }

    int lane = threadIdx.x & 31;
    #pragma unroll 1
    for (int bb = 0; bb < Bb; bb++) {
        unsigned long long key = 0ull;
        if (valid) {
            float c = acc[bb] * invl * sInvCn[bb];
            out[(size_t)bb * NLl + l] = c;
            key = pack_key(c, l);
        }
        #pragma unroll
        for (int o = 16; o > 0; o >>= 1) {
            unsigned long long other = __shfl_down_sync(0xffffffffu, key, o);
            key = (other > key) ? other : key;
        }
        if (lane == 0) atomicMax(&g_best[bb], key);
    }
}

__global__ void ids_out_kernel(float* __restrict__ out) {
    int b = threadIdx.x;
    if (b < Bb) {
        unsigned idpart = (unsigned)(g_best[b] & 0xFFFFFFFFull);
        out[(size_t)Bb * NLl + b] = (float)(0xFFFFFFFFu - idpart);
    }
}

// ---------------- host orchestration ----------------
extern "C" void kernel_launch(void* const* d_in, const int* in_sizes, int n_in,
                              void* d_out, int out_size) {
    const int*   ids  = (const int*)d_in[0];
    const int*   tys  = (const int*)d_in[1];
    const float* word = (const float*)d_in[2];
    const float* pos  = (const float*)d_in[3];
    const float* typ  = (const float*)d_in[4];
    const float* eg   = (const float*)d_in[5];
    const float* eb   = (const float*)d_in[6];
    const float* Wq   = (const float*)d_in[7];
    const float* bq   = (const float*)d_in[8];
    const float* Wk   = (const float*)d_in[9];
    const float* bk   = (const float*)d_in[10];
    const float* Wv   = (const float*)d_in[11];
    const float* bv   = (const float*)d_in[12];
    const float* Wo   = (const float*)d_in[13];
    const float* bo   = (const float*)d_in[14];
    const float* g1   = (const float*)d_in[15];
    const float* be1  = (const float*)d_in[16];
    const float* W1   = (const float*)d_in[17];
    const float* b1   = (const float*)d_in[18];
    const float* W2   = (const float*)d_in[19];
    const float* b2   = (const float*)d_in[20];
    const float* g2   = (const float*)d_in[21];
    const float* be2  = (const float*)d_in[22];
    const float* lab  = (const float*)d_in[23];
    float* out = (float*)d_out;

    float *px, *py, *py2, *pqkv, *pmbias, *pbqkv;
    __half *pxhi, *pxlo, *pchi, *pclo, *phhi, *phlo, *pwth;
    cudaGetSymbolAddress((void**)&px,    g_x);
    cudaGetSymbolAddress((void**)&py,    g_y);
    cudaGetSymbolAddress((void**)&py2,   g_y2);
    cudaGetSymbolAddress((void**)&pqkv,  g_qkv);
    cudaGetSymbolAddress((void**)&pmbias,g_mbias);
    cudaGetSymbolAddress((void**)&pbqkv, g_bqkv);
    cudaGetSymbolAddress((void**)&pxhi,  g_xhi);
    cudaGetSymbolAddress((void**)&pxlo,  g_xlo);
    cudaGetSymbolAddress((void**)&pchi,  g_chi);
    cudaGetSymbolAddress((void**)&pclo,  g_clo);
    cudaGetSymbolAddress((void**)&phhi,  g_hhi);
    cudaGetSymbolAddress((void**)&phlo,  g_hlo);
    cudaGetSymbolAddress((void**)&pwth,  g_wth);

    cudaFuncSetAttribute(attn_kernel, cudaFuncAttributeMaxDynamicSharedMemorySize, ATTN_SMEM);
    cudaFuncSetAttribute(gemm_mma<0>, cudaFuncAttributeMaxDynamicSharedMemorySize, GSMEM);
    cudaFuncSetAttribute(gemm_mma<1>, cudaFuncAttributeMaxDynamicSharedMemorySize, GSMEM);

    // minimal prefix before the first GEMM so the ncu capture window lands on it:
    // wsplit4(1), embed(2), pack_bias(3), QKV-GEMM(4) ...
    dim3 tb(32, 8);
    wsplit4_kernel<<<dim3(24, 24, 48), tb>>>(Wq, Wk, Wv, Wo);                 // 1
    embed_ln_kernel<<<NTOK, 256>>>(ids, tys, word, pos, typ, eg, eb);         // 2
    pack_bias_kernel<<<Ll, Hh>>>(bq, bk, bv);                                 // 3

    for (int l = 0; l < Ll; l++) {
        size_t wl = (size_t)l * LSTRIDE;
        // QKV: full K, single output
        gemm_mma<0><<<dim3(QKVN / 128, 32, 1), 256, GSMEM>>>(                 // 4 on l==0
            pxhi, pxlo, pwth + wl, pbqkv + l * QKVN,
            pqkv, nullptr, nullptr, nullptr, Hh, Hh, QKVN);
        attn_kernel<<<Bb * NHh, 128, ATTN_SMEM>>>(pqkv, pmbias, pchi, pclo);
        if (l == 0) {
            wsplit_kernel<<<dim3(FFf / 32, Hh / 32, Ll), tb>>>(W1, OFF_W1, Hh, FFf);
            wsplit_kernel<<<dim3(Hh / 32, FFf / 32, Ll), tb>>>(W2, OFF_W2, FFf, Hh);
        }
        // O projection: split-K=2 (z=0 -> y with bias, z=1 -> y2 zero-bias)
        gemm_mma<0><<<dim3(Hh / 128, 32, 2), 256, GSMEM>>>(
            pchi, pclo, pwth + wl + OFF_O, bo + (size_t)l * Hh,
            py, py2, nullptr, nullptr, Hh, Hh / 2, Hh);
        add_ln3_kernel<<<NTOK, 256>>>(px, py, py2,
                                      g1 + (size_t)l * Hh, be1 + (size_t)l * Hh);
        // FFN up + GELU: full K
        gemm_mma<1><<<dim3(FFf / 128, 32, 1), 256, GSMEM>>>(
            pxhi, pxlo, pwth + wl + OFF_W1, b1 + (size_t)l * FFf,
            nullptr, nullptr, phhi, phlo, Hh, Hh, FFf);
        // FFN down: split-K=2
        gemm_mma<0><<<dim3(Hh / 128, 32, 2), 256, GSMEM>>>(
            phhi, phlo, pwth + wl + OFF_W2, b2 + (size_t)l * Hh,
            py, py2, nullptr, nullptr, FFf, FFf / 2, Hh);
        add_ln3_kernel<<<NTOK, 256>>>(px, py, py2,
                                      g2 + (size_t)l * Hh, be2 + (size_t)l * Hh);
    }

    cls_kernel<<<Bb, 256>>>();
    reset_best_kernel<<<1, 32>>>();
    cos_kernel<<<(NLl + 127) / 128, 128>>>(lab, out);
    if (out_size >= Bb * NLl + Bb) ids_out_kernel<<<1, 32>>>(out);
}

// round 11
// speedup vs baseline: 1.2251x; 1.0286x over previous
#include <cuda_runtime.h>
#include <cuda_fp16.h>
#include <math.h>
#include <cstdint>

// ---------------- problem constants ----------------
#define Vv   30522
#define Hh   768
#define Ll   12
#define FFf  3072
#define NHh  12
#define DHh  64
#define Bb   32
#define Ss   128
#define NLl  10000
#define NTOK (Bb*Ss)          // 4096
#define QKVN (3*Hh)           // 2304
#define EPS_LN  1e-12f
#define EPS_COS 1e-8f

// transposed fp16 weight layout per layer (element offsets)
#define OFF_O   (QKVN*Hh)             // after packed qkv [2304][768]
#define OFF_W1  (OFF_O + Hh*Hh)       // [3072][768]
#define OFF_W2  (OFF_W1 + Hh*FFf)     // [768][3072]
#define LSTRIDE (OFF_W2 + FFf*Hh)     // 7,077,888

// ---------------- device scratch ----------------
__device__ __half g_wth[Ll*LSTRIDE];           // fp16 weights, transposed [N][K]
__device__ float  g_bqkv[Ll*QKVN];
__device__ float  g_zeros[Hh];                 // stays zero (module-load zero-init)

__device__ float  g_x  [NTOK*Hh];
__device__ __half g_xhi[NTOK*Hh];
__device__ __half g_xlo[NTOK*Hh];
__device__ float  g_qkv[NTOK*QKVN];
__device__ __half g_chi[NTOK*Hh];
__device__ __half g_clo[NTOK*Hh];
__device__ __half g_hhi[NTOK*FFf];
__device__ __half g_hlo[NTOK*FFf];
__device__ float  g_y  [NTOK*Hh];
__device__ float  g_y2 [NTOK*Hh];
__device__ float g_mbias[NTOK];
__device__ float g_cls[Bb*Hh];
__device__ float g_cn [Bb];
__device__ unsigned long long g_best[Bb];

// ---------------- PTX helpers (compute_100-safe) ----------------
__device__ __forceinline__ uint32_t smem_u32(const void* p) {
    uint32_t a;
    asm("{ .reg .u64 t; cvta.to.shared.u64 t, %1; cvt.u32.u64 %0, t; }" : "=r"(a) : "l"(p));
    return a;
}
__device__ __forceinline__ void cp_async16(uint32_t dst, const void* src) {
    asm volatile("cp.async.cg.shared.global [%0], [%1], 16;" :: "r"(dst), "l"(src) : "memory");
}
#define CP_COMMIT() asm volatile("cp.async.commit_group;" ::: "memory")
#define CP_WAIT(n)  asm volatile("cp.async.wait_group %0;" :: "n"(n) : "memory")

__device__ __forceinline__ void ldsm4(uint32_t& r0, uint32_t& r1, uint32_t& r2, uint32_t& r3,
                                      uint32_t addr) {
    asm volatile("ldmatrix.sync.aligned.m8n8.x4.shared.b16 {%0,%1,%2,%3}, [%4];"
                 : "=r"(r0), "=r"(r1), "=r"(r2), "=r"(r3) : "r"(addr));
}
__device__ __forceinline__ void mma16816(float* c, uint32_t a0, uint32_t a1, uint32_t a2,
                                         uint32_t a3, uint32_t b0, uint32_t b1) {
    asm volatile(
        "mma.sync.aligned.m16n8k16.row.col.f32.f16.f16.f32 "
        "{%0,%1,%2,%3}, {%4,%5,%6,%7}, {%8,%9}, {%0,%1,%2,%3};"
        : "+f"(c[0]), "+f"(c[1]), "+f"(c[2]), "+f"(c[3])
        : "r"(a0), "r"(a1), "r"(a2), "r"(a3), "r"(b0), "r"(b1));
}

// ---------------- misc helpers ----------------
__device__ __forceinline__ float blk_sum256(float v, volatile float* sred) {
    int lane = threadIdx.x & 31, w = threadIdx.x >> 5;
    #pragma unroll
    for (int o = 16; o > 0; o >>= 1) v += __shfl_down_sync(0xffffffffu, v, o);
    if (lane == 0) sred[w] = v;
    __syncthreads();
    if (threadIdx.x == 0) {
        float s = 0.f;
        #pragma unroll
        for (int i = 0; i < 8; i++) s += sred[i];
        sred[8] = s;
    }
    __syncthreads();
    float r = sred[8];
    __syncthreads();
    return r;
}
__device__ __forceinline__ float gelu_tanh(float x) {
    float x3 = x * x * x;
    float t = tanhf(0.7978845608028654f * (x + 0.044715f * x3));
    return 0.5f * x * (1.0f + t);
}
__device__ __forceinline__ unsigned long long pack_key(float c, int l) {
    unsigned u = __float_as_uint(c);
    u = (u & 0x80000000u) ? ~u : (u | 0x80000000u);
    return ((unsigned long long)u << 32) | (unsigned long long)(0xFFFFFFFFu - (unsigned)l);
}
__device__ __forceinline__ void split_store_h(float v, __half* hi, __half* lo) {
    __half h = __float2half(v);
    *hi = h;
    *lo = __float2half(v - __half2float(h));
}
__device__ __forceinline__ unsigned pack2h(float v0, float v1) {
    __half h0 = __float2half(v0), h1 = __float2half(v1);
    return (unsigned)__half_as_ushort(h0) | ((unsigned)__half_as_ushort(h1) << 16);
}

// ---------------- weight transpose to fp16 ----------------
__global__ void wsplit4_kernel(const float* __restrict__ W0, const float* __restrict__ W1m,
                               const float* __restrict__ W2m, const float* __restrict__ W3m) {
    __shared__ float t[32][33];
    int z = blockIdx.z;
    int m = z & 3, l = z >> 2;
    const float* Ws = (m == 0 ? W0 : m == 1 ? W1m : m == 2 ? W2m : W3m) + (size_t)l * Hh * Hh;
    long dstOff = (m < 3) ? (long)m * Hh * Hh : (long)OFF_O;
    __half* th = g_wth + (size_t)l * LSTRIDE + dstOff;
    int n = blockIdx.x * 32 + threadIdx.x;
    #pragma unroll
    for (int i = 0; i < 4; i++) {
        int k = blockIdx.y * 32 + threadIdx.y + i * 8;
        t[threadIdx.y + i * 8][threadIdx.x] = Ws[(size_t)k * Hh + n];
    }
    __syncthreads();
    int k2 = blockIdx.y * 32 + threadIdx.x;
    #pragma unroll
    for (int i = 0; i < 4; i++) {
        int n2 = blockIdx.x * 32 + threadIdx.y + i * 8;
        th[(size_t)n2 * Hh + k2] = __float2half(t[threadIdx.x][threadIdx.y + i * 8]);
    }
}

__global__ void wsplit_kernel(const float* __restrict__ W, long dstOff, int K, int N) {
    __shared__ float t[32][33];
    int l = blockIdx.z;
    const float* Ws = W + (size_t)l * K * N;
    __half* th = g_wth + (size_t)l * LSTRIDE + dstOff;
    int n = blockIdx.x * 32 + threadIdx.x;
    #pragma unroll
    for (int i = 0; i < 4; i++) {
        int k = blockIdx.y * 32 + threadIdx.y + i * 8;
        t[threadIdx.y + i * 8][threadIdx.x] = Ws[(size_t)k * N + n];
    }
    __syncthreads();
    int k2 = blockIdx.y * 32 + threadIdx.x;
    #pragma unroll
    for (int i = 0; i < 4; i++) {
        int n2 = blockIdx.x * 32 + threadIdx.y + i * 8;
        th[(size_t)n2 * K + k2] = __float2half(t[threadIdx.x][threadIdx.y + i * 8]);
    }
}

__global__ void pack_bias_kernel(const float* __restrict__ bq, const float* __restrict__ bk,
                                 const float* __restrict__ bv) {
    int l = blockIdx.x, j = threadIdx.x;
    g_bqkv[l * QKVN + j]          = bq[l * Hh + j];
    g_bqkv[l * QKVN + Hh + j]     = bk[l * Hh + j];
    g_bqkv[l * QKVN + 2 * Hh + j] = bv[l * Hh + j];
}

// ---------------- embeddings + LN + mask bias ----------------
__global__ void embed_ln_kernel(const int* __restrict__ ids, const int* __restrict__ tys,
                                const float* __restrict__ word, const float* __restrict__ pos,
                                const float* __restrict__ typ,
                                const float* __restrict__ eg, const float* __restrict__ eb) {
    __shared__ float sred[9];
    int t = blockIdx.x;
    int s = t & (Ss - 1);
    int id = ids[t], ty = tys[t];
    float v[3];
    float loc = 0.f;
    #pragma unroll
    for (int i = 0; i < 3; i++) {
        int j = threadIdx.x + i * 256;
        v[i] = word[(size_t)id * Hh + j] + pos[(size_t)s * Hh + j] + typ[(size_t)ty * Hh + j];
        loc += v[i];
    }
    float mu = blk_sum256(loc, sred) * (1.0f / Hh);
    float l2 = 0.f;
    #pragma unroll
    for (int i = 0; i < 3; i++) { float d = v[i] - mu; l2 += d * d; }
    float var = blk_sum256(l2, sred) * (1.0f / Hh);
    float rstd = rsqrtf(var + EPS_LN);
    #pragma unroll
    for (int i = 0; i < 3; i++) {
        int j = threadIdx.x + i * 256;
        size_t idx = (size_t)t * Hh + j;
        float o = (v[i] - mu) * rstd * eg[j] + eb[j];
        g_x[idx] = o;
        split_store_h(o, &g_xhi[idx], &g_xlo[idx]);
    }
    if (threadIdx.x == 0) g_mbias[t] = (id > 0) ? 0.f : -10000.0f;
}

// ---------------- residual add (3-way) + LN (in place on x), fused fp16 split ----------------
__global__ void add_ln3_kernel(float* __restrict__ x, const float* __restrict__ y,
                               const float* __restrict__ y2,
                               const float* __restrict__ g, const float* __restrict__ b) {
    __shared__ float sred[9];
    size_t base = (size_t)blockIdx.x * Hh;
    float v[3];
    float loc = 0.f;
    #pragma unroll
    for (int i = 0; i < 3; i++) {
        int j = threadIdx.x + i * 256;
        v[i] = x[base + j] + y[base + j] + y2[base + j];
        loc += v[i];
    }
    float mu = blk_sum256(loc, sred) * (1.0f / Hh);
    float l2 = 0.f;
    #pragma unroll
    for (int i = 0; i < 3; i++) { float d = v[i] - mu; l2 += d * d; }
    float var = blk_sum256(l2, sred) * (1.0f / Hh);
    float rstd = rsqrtf(var + EPS_LN);
    #pragma unroll
    for (int i = 0; i < 3; i++) {
        int j = threadIdx.x + i * 256;
        float o = (v[i] - mu) * rstd * g[j] + b[j];
        x[base + j] = o;
        split_store_h(o, &g_xhi[base + j], &g_xlo[base + j]);
    }
}

// ---------------- HMMA 2-term fp16 GEMM: C[4096, N] = (Ah+Al) @ Bh^T + bias ----------------
// Supports K-split via gridDim.z: block z computes K range [z*Klen, (z+1)*Klen),
// z=0 writes Cf with bias, z=1 writes Cf2 with zero bias (summed later in add_ln3).
// CTA 128x128, K-chunk 64 (rows 144B), 2-stage cp.async, 8 warps, 2 CTAs/SM.
#define GT_ROW   144
#define GT_TILE  (128 * GT_ROW)        // 18432 B per sub-tile
#define GT_STAGE (3 * GT_TILE)         // Ah | Al | Bh = 55296
#define GSMEM    (2 * GT_STAGE)        // 110592
template <int OUTMODE>
__global__ void __launch_bounds__(256, 2) gemm_mma(
    const __half* __restrict__ Ahi, const __half* __restrict__ Alo,
    const __half* __restrict__ Bh,
    const float* __restrict__ bias,
    float* __restrict__ Cf, float* __restrict__ Cf2,
    __half* __restrict__ Chi, __half* __restrict__ Clo,
    int Kfull, int Klen, int ldc)
{
    extern __shared__ char sm[];
    const uint32_t sb = smem_u32(sm);
    int tid = threadIdx.x, lane = tid & 31, wid = tid >> 5;
    int wm = wid >> 2, wn = wid & 3;              // warp tile rows wm*64, cols wn*32
    int m0 = blockIdx.y * 128, n0 = blockIdx.x * 128;
    int kz = blockIdx.z;
    int kbase = kz * Klen;
    const float* bsel = (OUTMODE == 0 && kz) ? g_zeros : bias;
    float* csel = (OUTMODE == 0 && kz) ? Cf2 : Cf;

    // ldmatrix lane offsets (row stride 144B)
    int q = lane >> 3, r = lane & 7;
    uint32_t aLane = (uint32_t)(((q & 1) * 8 + r) * GT_ROW + (q >> 1) * 16);
    uint32_t bLane = (uint32_t)(((q >> 1) * 8 + r) * GT_ROW + (q & 1) * 16);

    float acc[4][4][4];
    #pragma unroll
    for (int mi = 0; mi < 4; mi++)
        #pragma unroll
        for (int ni = 0; ni < 4; ni++)
            #pragma unroll
            for (int e = 0; e < 4; e++) acc[mi][ni][e] = 0.f;

    int nchunk = Klen >> 6;                       // K-chunk = 64

    // loader: 3 tiles x 128 rows x 8 segs of 16B = 3072 cp.async; 12 per thread
    auto load_stage = [&](int c) {
        int k0 = kbase + (c << 6);
        uint32_t base = sb + (uint32_t)(c & 1) * GT_STAGE;
        #pragma unroll
        for (int i = 0; i < 12; i++) {
            int lin = tid + i * 256;              // 0..3071
            int tile = lin >> 10;                 // 0=Ah 1=Al 2=Bh
            int within = lin & 1023;
            int row = within >> 3, seg = within & 7;
            uint32_t dst = base + (uint32_t)tile * GT_TILE + (uint32_t)(row * GT_ROW + seg * 16);
            const __half* src;
            if (tile == 0)      src = Ahi + (size_t)(m0 + row) * Kfull + k0 + seg * 8;
            else if (tile == 1) src = Alo + (size_t)(m0 + row) * Kfull + k0 + seg * 8;
            else                src = Bh  + (size_t)(n0 + row) * Kfull + k0 + seg * 8;
            cp_async16(dst, src);
        }
    };

    load_stage(0);
    CP_COMMIT();

    for (int c = 0; c < nchunk; c++) {
        if (c + 1 < nchunk) { load_stage(c + 1); CP_COMMIT(); CP_WAIT(1); }
        else { CP_WAIT(0); }
        __syncthreads();

        uint32_t base = sb + (uint32_t)(c & 1) * GT_STAGE;
        uint32_t aBaseH = base + (uint32_t)((wm * 64) * GT_ROW) + aLane;
        uint32_t aBaseL = aBaseH + GT_TILE;
        uint32_t bBase  = base + 2 * GT_TILE + (uint32_t)((wn * 32) * GT_ROW) + bLane;

        #pragma unroll
        for (int ks = 0; ks < 4; ks++) {
            uint32_t ko = (uint32_t)(ks * 32);
            uint32_t ah[4][4], al[4][4], bf[2][4];
            #pragma unroll
            for (int mi = 0; mi < 4; mi++)
                ldsm4(ah[mi][0], ah[mi][1], ah[mi][2], ah[mi][3],
                      aBaseH + (uint32_t)(mi * 16 * GT_ROW) + ko);
            #pragma unroll
            for (int mi = 0; mi < 4; mi++)
                ldsm4(al[mi][0], al[mi][1], al[mi][2], al[mi][3],
                      aBaseL + (uint32_t)(mi * 16 * GT_ROW) + ko);
            #pragma unroll
            for (int p = 0; p < 2; p++)
                ldsm4(bf[p][0], bf[p][1], bf[p][2], bf[p][3],
                      bBase + (uint32_t)(p * 16 * GT_ROW) + ko);
            #pragma unroll
            for (int mi = 0; mi < 4; mi++)
                #pragma unroll
                for (int ni = 0; ni < 4; ni++) {
                    int p = ni >> 1, su = ni & 1;
                    mma16816(acc[mi][ni], ah[mi][0], ah[mi][1], ah[mi][2], ah[mi][3],
                             bf[p][su * 2], bf[p][su * 2 + 1]);
                }
            #pragma unroll
            for (int mi = 0; mi < 4; mi++)
                #pragma unroll
                for (int ni = 0; ni < 4; ni++) {
                    int p = ni >> 1, su = ni & 1;
                    mma16816(acc[mi][ni], al[mi][0], al[mi][1], al[mi][2], al[mi][3],
                             bf[p][su * 2], bf[p][su * 2 + 1]);
                }
        }
        __syncthreads();
    }

    // ---------------- epilogue ----------------
    int rbase = m0 + wm * 64 + (lane >> 2);
    int cbase = n0 + wn * 32 + (lane & 3) * 2;
    #pragma unroll
    for (int mi = 0; mi < 4; mi++) {
        #pragma unroll
        for (int ni = 0; ni < 4; ni++) {
            int row = rbase + mi * 16;
            int col = cbase + ni * 8;
            float b0 = bsel[col], b1 = bsel[col + 1];
            float v0 = acc[mi][ni][0] + b0, v1 = acc[mi][ni][1] + b1;
            float v2 = acc[mi][ni][2] + b0, v3 = acc[mi][ni][3] + b1;
            if (OUTMODE == 0) {
                *(float2*)(csel + (size_t)row * ldc + col)       = make_float2(v0, v1);
                *(float2*)(csel + (size_t)(row + 8) * ldc + col) = make_float2(v2, v3);
            } else {
                v0 = gelu_tanh(v0); v1 = gelu_tanh(v1);
                v2 = gelu_tanh(v2); v3 = gelu_tanh(v3);
                __half h0 = __float2half(v0), h1 = __float2half(v1);
                __half h2 = __float2half(v2), h3 = __float2half(v3);
                *(unsigned*)(Chi + (size_t)row * ldc + col) =
                    (unsigned)__half_as_ushort(h0) | ((unsigned)__half_as_ushort(h1) << 16);
                *(unsigned*)(Clo + (size_t)row * ldc + col) =
                    pack2h(v0 - __half2float(h0), v1 - __half2float(h1));
                *(unsigned*)(Chi + (size_t)(row + 8) * ldc + col) =
                    (unsigned)__half_as_ushort(h2) | ((unsigned)__half_as_ushort(h3) << 16);
                *(unsigned*)(Clo + (size_t)(row + 8) * ldc + col) =
                    pack2h(v2 - __half2float(h2), v3 - __half2float(h3));
            }
        }
    }
}

// ---------------- attention: 256 threads, split j-range (QK) and d-range (PV) ----------------
// smem floats: Ks[128*64] Vs[128*64] S[128*129] biasS[128] pm[256] ps[256]
#define ATTN_SMEM ((2*Ss*DHh + Ss*129 + Ss + 2*256) * (int)sizeof(float))
__global__ void __launch_bounds__(256) attn_kernel(const float* __restrict__ Qkv,
                                                   const float* __restrict__ bias,
                                                   __half* __restrict__ chi,
                                                   __half* __restrict__ clo) {
    extern __shared__ float smf[];
    float* Ks = smf;                        // [128][64]
    float* Vs = smf + Ss * DHh;             // [128][64]
    float* S  = smf + 2 * Ss * DHh;         // [128][129]
    float* biasS = S + Ss * 129;            // [128]
    float* pm = biasS + Ss;                 // [256]
    float* ps = pm + 256;                   // [256]
    int bn = blockIdx.x;
    int b = bn / NHh, n = bn % NHh;
    int tid = threadIdx.x;
    int qi = tid & 127, h = tid >> 7;       // h: 0/1 half
    const float scale = 0.125f;

    // cooperative K/V load: 2048 float4's each of K and V; 8 iters x 256 threads
    #pragma unroll
    for (int i = 0; i < 8; i++) {
        int lin = tid + i * 256;            // 0..2047
        int j = lin >> 4, c4 = (lin & 15) * 4;
        size_t rowb = (size_t)(b * Ss + j) * QKVN + n * DHh + c4;
        *(float4*)&Ks[j * DHh + c4] = *(const float4*)(Qkv + rowb + Hh);
        *(float4*)&Vs[j * DHh + c4] = *(const float4*)(Qkv + rowb + 2 * Hh);
    }
    if (tid < Ss) biasS[tid] = bias[b * Ss + tid];
    __syncthreads();

    // full Q row per thread (both halves need all d for QK)
    float Qr[DHh];
    const float4* qp = (const float4*)(Qkv + (size_t)(b * Ss + qi) * QKVN + n * DHh);
    #pragma unroll
    for (int i = 0; i < 16; i++) {
        float4 v4 = qp[i];
        Qr[i * 4 + 0] = v4.x; Qr[i * 4 + 1] = v4.y; Qr[i * 4 + 2] = v4.z; Qr[i * 4 + 3] = v4.w;
    }

    float* Srow = S + qi * 129;
    int jbase = h * 64;
    float m = -1e30f;
    // QK over own half of j (explicit float4 K reads)
    #pragma unroll 1
    for (int jj = 0; jj < 64; jj += 4) {
        int j = jbase + jj;
        const float4* k0 = (const float4*)(Ks + j * DHh);
        float s0 = 0.f, s1 = 0.f, s2 = 0.f, s3 = 0.f;
        #pragma unroll
        for (int i = 0; i < 16; i++) {
            float4 kv0 = k0[i];
            float4 kv1 = k0[16 + i];
            float4 kv2 = k0[32 + i];
            float4 kv3 = k0[48 + i];
            float q0 = Qr[i * 4], q1 = Qr[i * 4 + 1], q2 = Qr[i * 4 + 2], q3 = Qr[i * 4 + 3];
            s0 = fmaf(q0, kv0.x, s0); s0 = fmaf(q1, kv0.y, s0);
            s0 = fmaf(q2, kv0.z, s0); s0 = fmaf(q3, kv0.w, s0);
            s1 = fmaf(q0, kv1.x, s1); s1 = fmaf(q1, kv1.y, s1);
            s1 = fmaf(q2, kv1.z, s1); s1 = fmaf(q3, kv1.w, s1);
            s2 = fmaf(q0, kv2.x, s2); s2 = fmaf(q1, kv2.y, s2);
            s2 = fmaf(q2, kv2.z, s2); s2 = fmaf(q3, kv2.w, s2);
            s3 = fmaf(q0, kv3.x, s3); s3 = fmaf(q1, kv3.y, s3);
            s3 = fmaf(q2, kv3.z, s3); s3 = fmaf(q3, kv3.w, s3);
        }
        s0 = fmaf(s0, scale, biasS[j]);
        s1 = fmaf(s1, scale, biasS[j + 1]);
        s2 = fmaf(s2, scale, biasS[j + 2]);
        s3 = fmaf(s3, scale, biasS[j + 3]);
        Srow[j] = s0; Srow[j + 1] = s1; Srow[j + 2] = s2; Srow[j + 3] = s3;
        m = fmaxf(m, fmaxf(fmaxf(s0, s1), fmaxf(s2, s3)));
    }
    pm[h * 128 + qi] = m;
    __syncthreads();
    m = fmaxf(pm[qi], pm[128 + qi]);

    // exp own half + partial sum
    float ls = 0.f;
    #pragma unroll 4
    for (int jj = 0; jj < 64; jj++) {
        int j = jbase + jj;
        float p = __expf(Srow[j] - m);
        Srow[j] = p;
        ls += p;
    }
    ps[h * 128 + qi] = ls;
    __syncthreads();
    float inv_l = 1.0f / (ps[qi] + ps[128 + qi]);

    // PV over own half of d (32 cols), explicit float4 V reads
    int dbase = h * 32;
    float acc[32];
    #pragma unroll
    for (int d = 0; d < 32; d++) acc[d] = 0.f;
    #pragma unroll 1
    for (int j = 0; j < Ss; j++) {
        float p = Srow[j];
        const float4* vr = (const float4*)(Vs + j * DHh + dbase);
        #pragma unroll
        for (int i = 0; i < 8; i++) {
            float4 v4 = vr[i];
            acc[i * 4 + 0] = fmaf(p, v4.x, acc[i * 4 + 0]);
            acc[i * 4 + 1] = fmaf(p, v4.y, acc[i * 4 + 1]);
            acc[i * 4 + 2] = fmaf(p, v4.z, acc[i * 4 + 2]);
            acc[i * 4 + 3] = fmaf(p, v4.w, acc[i * 4 + 3]);
        }
    }
    size_t obase = (size_t)(b * Ss + qi) * Hh + n * DHh + dbase;
    #pragma unroll
    for (int d = 0; d < 32; d += 2) {
        float v0 = acc[d] * inv_l, v1 = acc[d + 1] * inv_l;
        __half h0 = __float2half(v0), h1 = __float2half(v1);
        *(unsigned*)(chi + obase + d) =
            (unsigned)__half_as_ushort(h0) | ((unsigned)__half_as_ushort(h1) << 16);
        *(unsigned*)(clo + obase + d) =
            pack2h(v0 - __half2float(h0), v1 - __half2float(h1));
    }
}

// ---------------- CLS extraction + norm ----------------
__global__ void cls_kernel() {
    __shared__ float sred[9];
    int b = blockIdx.x;
    float loc = 0.f;
    #pragma unroll
    for (int i = 0; i < 3; i++) {
        int j = threadIdx.x + i * 256;
        float v = g_x[(size_t)(b * Ss) * Hh + j];
        g_cls[b * Hh + j] = v;
        loc += v * v;
    }
    float s = blk_sum256(loc, sred);
    if (threadIdx.x == 0) g_cn[b] = fmaxf(sqrtf(s), EPS_COS);
}

__global__ void reset_best_kernel() {
    if (threadIdx.x < Bb) g_best[threadIdx.x] = 0ull;
}

// ---------------- cosine + per-block argmax reduction ----------------
__global__ void __launch_bounds__(128) cos_kernel(const float* __restrict__ lab,
                                                  float* __restrict__ out) {
    __shared__ float clsS[Bb][33];
    __shared__ float sInvCn[Bb];
    int l = blockIdx.x * 128 + threadIdx.x;
    bool valid = (l < NLl);
    if (threadIdx.x < Bb) sInvCn[threadIdx.x] = 1.0f / g_cn[threadIdx.x];

    float acc[Bb];
    #pragma unroll
    for (int bb = 0; bb < Bb; bb++) acc[bb] = 0.f;

    for (int k0 = 0; k0 < Hh; k0 += 32) {
        #pragma unroll
        for (int i = 0; i < 8; i++) {
            int idx = threadIdx.x + i * 128;
            int bb = idx >> 5, kk = idx & 31;
            clsS[bb][kk] = g_cls[bb * Hh + k0 + kk];
        }
        __syncthreads();
        if (valid) {
            float lv[32];
            const float4* lp = (const float4*)(lab + (size_t)l * Hh + k0);
            #pragma unroll
            for (int i = 0; i < 8; i++) {
                float4 v4 = lp[i];
                lv[i * 4] = v4.x; lv[i * 4 + 1] = v4.y; lv[i * 4 + 2] = v4.z; lv[i * 4 + 3] = v4.w;
            }
            #pragma unroll
            for (int bb = 0; bb < Bb; bb++) {
                float a = acc[bb];
                #pragma unroll
                for (int kk = 0; kk < 32; kk++) a = fmaf(clsS[bb][kk], lv[kk], a);
                acc[bb] = a;
            }
        }
        __syncthreads();
    }

    float invl = 0.f;
    if (valid) {
        float s = 0.f;
        const float4* lp = (const float4*)(lab + (size_t)l * Hh);
        #pragma unroll 4
        for (int i = 0; i < Hh / 4; i++) {
            float4 v4 = lp[i];
            s += v4.x * v4.x + v4.y * v4.y + v4.z * v4.z + v4.w * v4.w;
        }
        invl = 1.0f / fmaxf(sqrtf(s), EPS_COS);
    }

    int lane = threadIdx.x & 31;
    #pragma unroll 1
    for (int bb = 0; bb < Bb; bb++) {
        unsigned long long key = 0ull;
        if (valid) {
            float c = acc[bb] * invl * sInvCn[bb];
            out[(size_t)bb * NLl + l] = c;
            key = pack_key(c, l);
        }
        #pragma unroll
        for (int o = 16; o > 0; o >>= 1) {
            unsigned long long other = __shfl_down_sync(0xffffffffu, key, o);
            key = (other > key) ? other : key;
        }
        if (lane == 0) atomicMax(&g_best[bb], key);
    }
}

__global__ void ids_out_kernel(float* __restrict__ out) {
    int b = threadIdx.x;
    if (b < Bb) {
        unsigned idpart = (unsigned)(g_best[b] & 0xFFFFFFFFull);
        out[(size_t)Bb * NLl + b] = (float)(0xFFFFFFFFu - idpart);
    }
}

// ---------------- host orchestration ----------------
extern "C" void kernel_launch(void* const* d_in, const int* in_sizes, int n_in,
                              void* d_out, int out_size) {
    const int*   ids  = (const int*)d_in[0];
    const int*   tys  = (const int*)d_in[1];
    const float* word = (const float*)d_in[2];
    const float* pos  = (const float*)d_in[3];
    const float* typ  = (const float*)d_in[4];
    const float* eg   = (const float*)d_in[5];
    const float* eb   = (const float*)d_in[6];
    const float* Wq   = (const float*)d_in[7];
    const float* bq   = (const float*)d_in[8];
    const float* Wk   = (const float*)d_in[9];
    const float* bk   = (const float*)d_in[10];
    const float* Wv   = (const float*)d_in[11];
    const float* bv   = (const float*)d_in[12];
    const float* Wo   = (const float*)d_in[13];
    const float* bo   = (const float*)d_in[14];
    const float* g1   = (const float*)d_in[15];
    const float* be1  = (const float*)d_in[16];
    const float* W1   = (const float*)d_in[17];
    const float* b1   = (const float*)d_in[18];
    const float* W2   = (const float*)d_in[19];
    const float* b2   = (const float*)d_in[20];
    const float* g2   = (const float*)d_in[21];
    const float* be2  = (const float*)d_in[22];
    const float* lab  = (const float*)d_in[23];
    float* out = (float*)d_out;

    float *px, *py, *py2, *pqkv, *pmbias, *pbqkv;
    __half *pxhi, *pxlo, *pchi, *pclo, *phhi, *phlo, *pwth;
    cudaGetSymbolAddress((void**)&px,    g_x);
    cudaGetSymbolAddress((void**)&py,    g_y);
    cudaGetSymbolAddress((void**)&py2,   g_y2);
    cudaGetSymbolAddress((void**)&pqkv,  g_qkv);
    cudaGetSymbolAddress((void**)&pmbias,g_mbias);
    cudaGetSymbolAddress((void**)&pbqkv, g_bqkv);
    cudaGetSymbolAddress((void**)&pxhi,  g_xhi);
    cudaGetSymbolAddress((void**)&pxlo,  g_xlo);
    cudaGetSymbolAddress((void**)&pchi,  g_chi);
    cudaGetSymbolAddress((void**)&pclo,  g_clo);
    cudaGetSymbolAddress((void**)&phhi,  g_hhi);
    cudaGetSymbolAddress((void**)&phlo,  g_hlo);
    cudaGetSymbolAddress((void**)&pwth,  g_wth);

    cudaFuncSetAttribute(attn_kernel, cudaFuncAttributeMaxDynamicSharedMemorySize, ATTN_SMEM);
    cudaFuncSetAttribute(gemm_mma<0>, cudaFuncAttributeMaxDynamicSharedMemorySize, GSMEM);
    cudaFuncSetAttribute(gemm_mma<1>, cudaFuncAttributeMaxDynamicSharedMemorySize, GSMEM);

    // minimal prefix before the first GEMM so the ncu capture window lands on it:
    // wsplit4(1), embed(2), pack_bias(3), QKV-GEMM(4) ...
    dim3 tb(32, 8);
    wsplit4_kernel<<<dim3(24, 24, 48), tb>>>(Wq, Wk, Wv, Wo);                 // 1
    embed_ln_kernel<<<NTOK, 256>>>(ids, tys, word, pos, typ, eg, eb);         // 2
    pack_bias_kernel<<<Ll, Hh>>>(bq, bk, bv);                                 // 3

    for (int l = 0; l < Ll; l++) {
        size_t wl = (size_t)l * LSTRIDE;
        // QKV: full K, single output
        gemm_mma<0><<<dim3(QKVN / 128, 32, 1), 256, GSMEM>>>(                 // 4 on l==0
            pxhi, pxlo, pwth + wl, pbqkv + l * QKVN,
            pqkv, nullptr, nullptr, nullptr, Hh, Hh, QKVN);
        attn_kernel<<<Bb * NHh, 256, ATTN_SMEM>>>(pqkv, pmbias, pchi, pclo);
        if (l == 0) {
            wsplit_kernel<<<dim3(FFf / 32, Hh / 32, Ll), tb>>>(W1, OFF_W1, Hh, FFf);
            wsplit_kernel<<<dim3(Hh / 32, FFf / 32, Ll), tb>>>(W2, OFF_W2, FFf, Hh);
        }
        // O projection: split-K=2 (z=0 -> y with bias, z=1 -> y2 zero-bias)
        gemm_mma<0><<<dim3(Hh / 128, 32, 2), 256, GSMEM>>>(
            pchi, pclo, pwth + wl + OFF_O, bo + (size_t)l * Hh,
            py, py2, nullptr, nullptr, Hh, Hh / 2, Hh);
        add_ln3_kernel<<<NTOK, 256>>>(px, py, py2,
                                      g1 + (size_t)l * Hh, be1 + (size_t)l * Hh);
        // FFN up + GELU: full K
        gemm_mma<1><<<dim3(FFf / 128, 32, 1), 256, GSMEM>>>(
            pxhi, pxlo, pwth + wl + OFF_W1, b1 + (size_t)l * FFf,
            nullptr, nullptr, phhi, phlo, Hh, Hh, FFf);
        // FFN down: split-K=2
        gemm_mma<0><<<dim3(Hh / 128, 32, 2), 256, GSMEM>>>(
            phhi, phlo, pwth + wl + OFF_W2, b2 + (size_t)l * Hh,
            py, py2, nullptr, nullptr, FFf, FFf / 2, Hh);
        add_ln3_kernel<<<NTOK, 256>>>(px, py, py2,
                                      g2 + (size_t)l * Hh, be2 + (size_t)l * Hh);
    }

    cls_kernel<<<Bb, 256>>>();
    reset_best_kernel<<<1, 32>>>();
    cos_kernel<<<(NLl + 127) / 128, 128>>>(lab, out);
    if (out_size >= Bb * NLl + Bb) ids_out_kernel<<<1, 32>>>(out);
}

// round 12
// speedup vs baseline: 1.4282x; 1.1658x over previous
#include <cuda_runtime.h>
#include <cuda_fp16.h>
#include <math.h>
#include <cstdint>

// ---------------- problem constants ----------------
#define Vv   30522
#define Hh   768
#define Ll   12
#define FFf  3072
#define NHh  12
#define DHh  64
#define Bb   32
#define Ss   128
#define NLl  10000
#define NTOK (Bb*Ss)          // 4096
#define QKVN (3*Hh)           // 2304
#define EPS_LN  1e-12f
#define EPS_COS 1e-8f

// transposed fp16 weight layout per layer (element offsets)
#define OFF_O   (QKVN*Hh)             // after packed qkv [2304][768]
#define OFF_W1  (OFF_O + Hh*Hh)       // [3072][768]
#define OFF_W2  (OFF_W1 + Hh*FFf)     // [768][3072]
#define LSTRIDE (OFF_W2 + FFf*Hh)     // 7,077,888

// ---------------- device scratch ----------------
__device__ __half g_wth[Ll*LSTRIDE];           // fp16 weights, transposed [N][K]
__device__ float  g_bqkv[Ll*QKVN];
__device__ float  g_zeros[Hh];                 // stays zero (module-load zero-init)

__device__ float  g_x  [NTOK*Hh];
__device__ __half g_xhi[NTOK*Hh];
__device__ float  g_qkv[NTOK*QKVN];
__device__ __half g_chi[NTOK*Hh];
__device__ __half g_clo[NTOK*Hh];
__device__ __half g_hhi[NTOK*FFf];
__device__ __half g_hlo[NTOK*FFf];
__device__ float  g_y  [NTOK*Hh];
__device__ float  g_y2 [NTOK*Hh];
__device__ float g_mbias[NTOK];
__device__ float g_cls[Bb*Hh];
__device__ float g_cn [Bb];
__device__ unsigned long long g_best[Bb];

// ---------------- PTX helpers (compute_100-safe) ----------------
__device__ __forceinline__ uint32_t smem_u32(const void* p) {
    uint32_t a;
    asm("{ .reg .u64 t; cvta.to.shared.u64 t, %1; cvt.u32.u64 %0, t; }" : "=r"(a) : "l"(p));
    return a;
}
__device__ __forceinline__ void cp_async16(uint32_t dst, const void* src) {
    asm volatile("cp.async.cg.shared.global [%0], [%1], 16;" :: "r"(dst), "l"(src) : "memory");
}
#define CP_COMMIT() asm volatile("cp.async.commit_group;" ::: "memory")
#define CP_WAIT(n)  asm volatile("cp.async.wait_group %0;" :: "n"(n) : "memory")

__device__ __forceinline__ void ldsm4(uint32_t& r0, uint32_t& r1, uint32_t& r2, uint32_t& r3,
                                      uint32_t addr) {
    asm volatile("ldmatrix.sync.aligned.m8n8.x4.shared.b16 {%0,%1,%2,%3}, [%4];"
                 : "=r"(r0), "=r"(r1), "=r"(r2), "=r"(r3) : "r"(addr));
}
__device__ __forceinline__ void mma16816(float* c, uint32_t a0, uint32_t a1, uint32_t a2,
                                         uint32_t a3, uint32_t b0, uint32_t b1) {
    asm volatile(
        "mma.sync.aligned.m16n8k16.row.col.f32.f16.f16.f32 "
        "{%0,%1,%2,%3}, {%4,%5,%6,%7}, {%8,%9}, {%0,%1,%2,%3};"
        : "+f"(c[0]), "+f"(c[1]), "+f"(c[2]), "+f"(c[3])
        : "r"(a0), "r"(a1), "r"(a2), "r"(a3), "r"(b0), "r"(b1));
}

// ---------------- misc helpers ----------------
__device__ __forceinline__ float blk_sum256(float v, volatile float* sred) {
    int lane = threadIdx.x & 31, w = threadIdx.x >> 5;
    #pragma unroll
    for (int o = 16; o > 0; o >>= 1) v += __shfl_down_sync(0xffffffffu, v, o);
    if (lane == 0) sred[w] = v;
    __syncthreads();
    if (threadIdx.x == 0) {
        float s = 0.f;
        #pragma unroll
        for (int i = 0; i < 8; i++) s += sred[i];
        sred[8] = s;
    }
    __syncthreads();
    float r = sred[8];
    __syncthreads();
    return r;
}
__device__ __forceinline__ float gelu_tanh(float x) {
    float x3 = x * x * x;
    float t = tanhf(0.7978845608028654f * (x + 0.044715f * x3));
    return 0.5f * x * (1.0f + t);
}
__device__ __forceinline__ unsigned long long pack_key(float c, int l) {
    unsigned u = __float_as_uint(c);
    u = (u & 0x80000000u) ? ~u : (u | 0x80000000u);
    return ((unsigned long long)u << 32) | (unsigned long long)(0xFFFFFFFFu - (unsigned)l);
}
__device__ __forceinline__ unsigned pack2h(float v0, float v1) {
    __half h0 = __float2half(v0), h1 = __float2half(v1);
    return (unsigned)__half_as_ushort(h0) | ((unsigned)__half_as_ushort(h1) << 16);
}

// ---------------- weight transpose to fp16 ----------------
__global__ void wsplit4_kernel(const float* __restrict__ W0, const float* __restrict__ W1m,
                               const float* __restrict__ W2m, const float* __restrict__ W3m) {
    __shared__ float t[32][33];
    int z = blockIdx.z;
    int m = z & 3, l = z >> 2;
    const float* Ws = (m == 0 ? W0 : m == 1 ? W1m : m == 2 ? W2m : W3m) + (size_t)l * Hh * Hh;
    long dstOff = (m < 3) ? (long)m * Hh * Hh : (long)OFF_O;
    __half* th = g_wth + (size_t)l * LSTRIDE + dstOff;
    int n = blockIdx.x * 32 + threadIdx.x;
    #pragma unroll
    for (int i = 0; i < 4; i++) {
        int k = blockIdx.y * 32 + threadIdx.y + i * 8;
        t[threadIdx.y + i * 8][threadIdx.x] = Ws[(size_t)k * Hh + n];
    }
    __syncthreads();
    int k2 = blockIdx.y * 32 + threadIdx.x;
    #pragma unroll
    for (int i = 0; i < 4; i++) {
        int n2 = blockIdx.x * 32 + threadIdx.y + i * 8;
        th[(size_t)n2 * Hh + k2] = __float2half(t[threadIdx.x][threadIdx.y + i * 8]);
    }
}

__global__ void wsplit_kernel(const float* __restrict__ W, long dstOff, int K, int N) {
    __shared__ float t[32][33];
    int l = blockIdx.z;
    const float* Ws = W + (size_t)l * K * N;
    __half* th = g_wth + (size_t)l * LSTRIDE + dstOff;
    int n = blockIdx.x * 32 + threadIdx.x;
    #pragma unroll
    for (int i = 0; i < 4; i++) {
        int k = blockIdx.y * 32 + threadIdx.y + i * 8;
        t[threadIdx.y + i * 8][threadIdx.x] = Ws[(size_t)k * N + n];
    }
    __syncthreads();
    int k2 = blockIdx.y * 32 + threadIdx.x;
    #pragma unroll
    for (int i = 0; i < 4; i++) {
        int n2 = blockIdx.x * 32 + threadIdx.y + i * 8;
        th[(size_t)n2 * K + k2] = __float2half(t[threadIdx.x][threadIdx.y + i * 8]);
    }
}

__global__ void pack_bias_kernel(const float* __restrict__ bq, const float* __restrict__ bk,
                                 const float* __restrict__ bv) {
    int l = blockIdx.x, j = threadIdx.x;
    g_bqkv[l * QKVN + j]          = bq[l * Hh + j];
    g_bqkv[l * QKVN + Hh + j]     = bk[l * Hh + j];
    g_bqkv[l * QKVN + 2 * Hh + j] = bv[l * Hh + j];
}

// ---------------- embeddings + LN + mask bias ----------------
__global__ void embed_ln_kernel(const int* __restrict__ ids, const int* __restrict__ tys,
                                const float* __restrict__ word, const float* __restrict__ pos,
                                const float* __restrict__ typ,
                                const float* __restrict__ eg, const float* __restrict__ eb) {
    __shared__ float sred[9];
    int t = blockIdx.x;
    int s = t & (Ss - 1);
    int id = ids[t], ty = tys[t];
    float v[3];
    float loc = 0.f;
    #pragma unroll
    for (int i = 0; i < 3; i++) {
        int j = threadIdx.x + i * 256;
        v[i] = word[(size_t)id * Hh + j] + pos[(size_t)s * Hh + j] + typ[(size_t)ty * Hh + j];
        loc += v[i];
    }
    float mu = blk_sum256(loc, sred) * (1.0f / Hh);
    float l2 = 0.f;
    #pragma unroll
    for (int i = 0; i < 3; i++) { float d = v[i] - mu; l2 += d * d; }
    float var = blk_sum256(l2, sred) * (1.0f / Hh);
    float rstd = rsqrtf(var + EPS_LN);
    #pragma unroll
    for (int i = 0; i < 3; i++) {
        int j = threadIdx.x + i * 256;
        size_t idx = (size_t)t * Hh + j;
        float o = (v[i] - mu) * rstd * eg[j] + eb[j];
        g_x[idx] = o;
        g_xhi[idx] = __float2half(o);
    }
    if (threadIdx.x == 0) g_mbias[t] = (id > 0) ? 0.f : -10000.0f;
}

// ---------------- residual add (3-way) + LN (in place on x) ----------------
__global__ void add_ln3_kernel(float* __restrict__ x, const float* __restrict__ y,
                               const float* __restrict__ y2,
                               const float* __restrict__ g, const float* __restrict__ b) {
    __shared__ float sred[9];
    size_t base = (size_t)blockIdx.x * Hh;
    float v[3];
    float loc = 0.f;
    #pragma unroll
    for (int i = 0; i < 3; i++) {
        int j = threadIdx.x + i * 256;
        v[i] = x[base + j] + y[base + j] + y2[base + j];
        loc += v[i];
    }
    float mu = blk_sum256(loc, sred) * (1.0f / Hh);
    float l2 = 0.f;
    #pragma unroll
    for (int i = 0; i < 3; i++) { float d = v[i] - mu; l2 += d * d; }
    float var = blk_sum256(l2, sred) * (1.0f / Hh);
    float rstd = rsqrtf(var + EPS_LN);
    #pragma unroll
    for (int i = 0; i < 3; i++) {
        int j = threadIdx.x + i * 256;
        float o = (v[i] - mu) * rstd * g[j] + b[j];
        x[base + j] = o;
        g_xhi[base + j] = __float2half(o);
    }
}

// ---------------- HMMA fp16 GEMM: C[4096, N] = (Ah [+Al]) @ Bh^T + bias ----------------
// ATERMS=1: C = Ah*Bh (activation fp16-hi only). ATERMS=2: C = (Ah+Al)*Bh.
// K-split via gridDim.z (OUTMODE 0): z=0 -> Cf with bias, z=1 -> Cf2 zero-bias.
// CTA 128x128, K-chunk 64 (rows 144B), 2-stage cp.async, 8 warps, 2 CTAs/SM.
#define GT_ROW   144
#define GT_TILE  (128 * GT_ROW)        // 18432 B per sub-tile
#define GT_STAGE (3 * GT_TILE)         // Ah | Al | Bh = 55296
#define GSMEM    (2 * GT_STAGE)        // 110592
template <int OUTMODE, int ATERMS>
__global__ void __launch_bounds__(256, 2) gemm_mma(
    const __half* __restrict__ Ahi, const __half* __restrict__ Alo,
    const __half* __restrict__ Bh,
    const float* __restrict__ bias,
    float* __restrict__ Cf, float* __restrict__ Cf2,
    __half* __restrict__ Chi, __half* __restrict__ Clo,
    int Kfull, int Klen, int ldc)
{
    extern __shared__ char sm[];
    const uint32_t sb = smem_u32(sm);
    int tid = threadIdx.x, lane = tid & 31, wid = tid >> 5;
    int wm = wid >> 2, wn = wid & 3;              // warp tile rows wm*64, cols wn*32
    int m0 = blockIdx.y * 128, n0 = blockIdx.x * 128;
    int kz = blockIdx.z;
    int kbase = kz * Klen;
    const float* bsel = (OUTMODE == 0 && kz) ? g_zeros : bias;
    float* csel = (OUTMODE == 0 && kz) ? Cf2 : Cf;

    // ldmatrix lane offsets (row stride 144B)
    int q = lane >> 3, r = lane & 7;
    uint32_t aLane = (uint32_t)(((q & 1) * 8 + r) * GT_ROW + (q >> 1) * 16);
    uint32_t bLane = (uint32_t)(((q >> 1) * 8 + r) * GT_ROW + (q & 1) * 16);

    float acc[4][4][4];
    #pragma unroll
    for (int mi = 0; mi < 4; mi++)
        #pragma unroll
        for (int ni = 0; ni < 4; ni++)
            #pragma unroll
            for (int e = 0; e < 4; e++) acc[mi][ni][e] = 0.f;

    int nchunk = Klen >> 6;                       // K-chunk = 64

    // loader: (2 or 3) tiles x 128 rows x 8 segs of 16B; 8 or 12 cp.async per thread
    auto load_stage = [&](int c) {
        int k0 = kbase + (c << 6);
        uint32_t base = sb + (uint32_t)(c & 1) * GT_STAGE;
        const int NIT = (ATERMS == 2) ? 12 : 8;
        #pragma unroll
        for (int i = 0; i < NIT; i++) {
            int lin = tid + i * 256;
            int tsel = lin >> 10;                 // 0..(NIT/4-1)
            int within = lin & 1023;
            int row = within >> 3, seg = within & 7;
            uint32_t dtile;
            const __half* src;
            if (ATERMS == 2) {
                dtile = (uint32_t)tsel;           // 0=Ah 1=Al 2=Bh
                src = (tsel == 0) ? Ahi + (size_t)(m0 + row) * Kfull + k0 + seg * 8
                    : (tsel == 1) ? Alo + (size_t)(m0 + row) * Kfull + k0 + seg * 8
                                  : Bh  + (size_t)(n0 + row) * Kfull + k0 + seg * 8;
            } else {
                dtile = (tsel == 0) ? 0u : 2u;    // 0=Ah 2=Bh
                src = (tsel == 0) ? Ahi + (size_t)(m0 + row) * Kfull + k0 + seg * 8
                                  : Bh  + (size_t)(n0 + row) * Kfull + k0 + seg * 8;
            }
            cp_async16(base + dtile * GT_TILE + (uint32_t)(row * GT_ROW + seg * 16), src);
        }
    };

    load_stage(0);
    CP_COMMIT();

    for (int c = 0; c < nchunk; c++) {
        if (c + 1 < nchunk) { load_stage(c + 1); CP_COMMIT(); CP_WAIT(1); }
        else { CP_WAIT(0); }
        __syncthreads();

        uint32_t base = sb + (uint32_t)(c & 1) * GT_STAGE;
        uint32_t aBaseH = base + (uint32_t)((wm * 64) * GT_ROW) + aLane;
        uint32_t aBaseL = aBaseH + GT_TILE;
        uint32_t bBase  = base + 2 * GT_TILE + (uint32_t)((wn * 32) * GT_ROW) + bLane;

        #pragma unroll
        for (int ks = 0; ks < 4; ks++) {
            uint32_t ko = (uint32_t)(ks * 32);
            uint32_t ah[4][4], al[4][4], bf[2][4];
            // B first, then A-hi: first mma depends on fewest trailing loads
            #pragma unroll
            for (int p = 0; p < 2; p++)
                ldsm4(bf[p][0], bf[p][1], bf[p][2], bf[p][3],
                      bBase + (uint32_t)(p * 16 * GT_ROW) + ko);
            #pragma unroll
            for (int mi = 0; mi < 4; mi++)
                ldsm4(ah[mi][0], ah[mi][1], ah[mi][2], ah[mi][3],
                      aBaseH + (uint32_t)(mi * 16 * GT_ROW) + ko);
            #pragma unroll
            for (int mi = 0; mi < 4; mi++)
                #pragma unroll
                for (int ni = 0; ni < 4; ni++) {
                    int p = ni >> 1, su = ni & 1;
                    mma16816(acc[mi][ni], ah[mi][0], ah[mi][1], ah[mi][2], ah[mi][3],
                             bf[p][su * 2], bf[p][su * 2 + 1]);
                }
            if (ATERMS == 2) {
                #pragma unroll
                for (int mi = 0; mi < 4; mi++)
                    ldsm4(al[mi][0], al[mi][1], al[mi][2], al[mi][3],
                          aBaseL + (uint32_t)(mi * 16 * GT_ROW) + ko);
                #pragma unroll
                for (int mi = 0; mi < 4; mi++)
                    #pragma unroll
                    for (int ni = 0; ni < 4; ni++) {
                        int p = ni >> 1, su = ni & 1;
                        mma16816(acc[mi][ni], al[mi][0], al[mi][1], al[mi][2], al[mi][3],
                                 bf[p][su * 2], bf[p][su * 2 + 1]);
                    }
            }
        }
        __syncthreads();
    }

    // ---------------- epilogue ----------------
    int rbase = m0 + wm * 64 + (lane >> 2);
    int cbase = n0 + wn * 32 + (lane & 3) * 2;
    #pragma unroll
    for (int mi = 0; mi < 4; mi++) {
        #pragma unroll
        for (int ni = 0; ni < 4; ni++) {
            int row = rbase + mi * 16;
            int col = cbase + ni * 8;
            float b0 = bsel[col], b1 = bsel[col + 1];
            float v0 = acc[mi][ni][0] + b0, v1 = acc[mi][ni][1] + b1;
            float v2 = acc[mi][ni][2] + b0, v3 = acc[mi][ni][3] + b1;
            if (OUTMODE == 0) {
                *(float2*)(csel + (size_t)row * ldc + col)       = make_float2(v0, v1);
                *(float2*)(csel + (size_t)(row + 8) * ldc + col) = make_float2(v2, v3);
            } else {
                v0 = gelu_tanh(v0); v1 = gelu_tanh(v1);
                v2 = gelu_tanh(v2); v3 = gelu_tanh(v3);
                __half h0 = __float2half(v0), h1 = __float2half(v1);
                __half h2 = __float2half(v2), h3 = __float2half(v3);
                *(unsigned*)(Chi + (size_t)row * ldc + col) =
                    (unsigned)__half_as_ushort(h0) | ((unsigned)__half_as_ushort(h1) << 16);
                *(unsigned*)(Clo + (size_t)row * ldc + col) =
                    pack2h(v0 - __half2float(h0), v1 - __half2float(h1));
                *(unsigned*)(Chi + (size_t)(row + 8) * ldc + col) =
                    (unsigned)__half_as_ushort(h2) | ((unsigned)__half_as_ushort(h3) << 16);
                *(unsigned*)(Clo + (size_t)(row + 8) * ldc + col) =
                    pack2h(v2 - __half2float(h2), v3 - __half2float(h3));
            }
        }
    }
}

// ---------------- attention: 256 threads, split j-range (QK) and d-range (PV) ----------------
#define ATTN_SMEM ((2*Ss*DHh + Ss*129 + Ss + 2*256) * (int)sizeof(float))
__global__ void __launch_bounds__(256) attn_kernel(const float* __restrict__ Qkv,
                                                   const float* __restrict__ bias,
                                                   __half* __restrict__ chi,
                                                   __half* __restrict__ clo) {
    extern __shared__ float smf[];
    float* Ks = smf;                        // [128][64]
    float* Vs = smf + Ss * DHh;             // [128][64]
    float* S  = smf + 2 * Ss * DHh;         // [128][129]
    float* biasS = S + Ss * 129;            // [128]
    float* pm = biasS + Ss;                 // [256]
    float* ps = pm + 256;                   // [256]
    int bn = blockIdx.x;
    int b = bn / NHh, n = bn % NHh;
    int tid = threadIdx.x;
    int qi = tid & 127, h = tid >> 7;
    const float scale = 0.125f;

    #pragma unroll
    for (int i = 0; i < 8; i++) {
        int lin = tid + i * 256;
        int j = lin >> 4, c4 = (lin & 15) * 4;
        size_t rowb = (size_t)(b * Ss + j) * QKVN + n * DHh + c4;
        *(float4*)&Ks[j * DHh + c4] = *(const float4*)(Qkv + rowb + Hh);
        *(float4*)&Vs[j * DHh + c4] = *(const float4*)(Qkv + rowb + 2 * Hh);
    }
    if (tid < Ss) biasS[tid] = bias[b * Ss + tid];
    __syncthreads();

    float Qr[DHh];
    const float4* qp = (const float4*)(Qkv + (size_t)(b * Ss + qi) * QKVN + n * DHh);
    #pragma unroll
    for (int i = 0; i < 16; i++) {
        float4 v4 = qp[i];
        Qr[i * 4 + 0] = v4.x; Qr[i * 4 + 1] = v4.y; Qr[i * 4 + 2] = v4.z; Qr[i * 4 + 3] = v4.w;
    }

    float* Srow = S + qi * 129;
    int jbase = h * 64;
    float m = -1e30f;
    #pragma unroll 1
    for (int jj = 0; jj < 64; jj += 4) {
        int j = jbase + jj;
        const float4* k0 = (const float4*)(Ks + j * DHh);
        float s0 = 0.f, s1 = 0.f, s2 = 0.f, s3 = 0.f;
        #pragma unroll
        for (int i = 0; i < 16; i++) {
            float4 kv0 = k0[i];
            float4 kv1 = k0[16 + i];
            float4 kv2 = k0[32 + i];
            float4 kv3 = k0[48 + i];
            float q0 = Qr[i * 4], q1 = Qr[i * 4 + 1], q2 = Qr[i * 4 + 2], q3 = Qr[i * 4 + 3];
            s0 = fmaf(q0, kv0.x, s0); s0 = fmaf(q1, kv0.y, s0);
            s0 = fmaf(q2, kv0.z, s0); s0 = fmaf(q3, kv0.w, s0);
            s1 = fmaf(q0, kv1.x, s1); s1 = fmaf(q1, kv1.y, s1);
            s1 = fmaf(q2, kv1.z, s1); s1 = fmaf(q3, kv1.w, s1);
            s2 = fmaf(q0, kv2.x, s2); s2 = fmaf(q1, kv2.y, s2);
            s2 = fmaf(q2, kv2.z, s2); s2 = fmaf(q3, kv2.w, s2);
            s3 = fmaf(q0, kv3.x, s3); s3 = fmaf(q1, kv3.y, s3);
            s3 = fmaf(q2, kv3.z, s3); s3 = fmaf(q3, kv3.w, s3);
        }
        s0 = fmaf(s0, scale, biasS[j]);
        s1 = fmaf(s1, scale, biasS[j + 1]);
        s2 = fmaf(s2, scale, biasS[j + 2]);
        s3 = fmaf(s3, scale, biasS[j + 3]);
        Srow[j] = s0; Srow[j + 1] = s1; Srow[j + 2] = s2; Srow[j + 3] = s3;
        m = fmaxf(m, fmaxf(fmaxf(s0, s1), fmaxf(s2, s3)));
    }
    pm[h * 128 + qi] = m;
    __syncthreads();
    m = fmaxf(pm[qi], pm[128 + qi]);

    float ls = 0.f;
    #pragma unroll 4
    for (int jj = 0; jj < 64; jj++) {
        int j = jbase + jj;
        float p = __expf(Srow[j] - m);
        Srow[j] = p;
        ls += p;
    }
    ps[h * 128 + qi] = ls;
    __syncthreads();
    float inv_l = 1.0f / (ps[qi] + ps[128 + qi]);

    int dbase = h * 32;
    float acc[32];
    #pragma unroll
    for (int d = 0; d < 32; d++) acc[d] = 0.f;
    #pragma unroll 1
    for (int j = 0; j < Ss; j++) {
        float p = Srow[j];
        const float4* vr = (const float4*)(Vs + j * DHh + dbase);
        #pragma unroll
        for (int i = 0; i < 8; i++) {
            float4 v4 = vr[i];
            acc[i * 4 + 0] = fmaf(p, v4.x, acc[i * 4 + 0]);
            acc[i * 4 + 1] = fmaf(p, v4.y, acc[i * 4 + 1]);
            acc[i * 4 + 2] = fmaf(p, v4.z, acc[i * 4 + 2]);
            acc[i * 4 + 3] = fmaf(p, v4.w, acc[i * 4 + 3]);
        }
    }
    size_t obase = (size_t)(b * Ss + qi) * Hh + n * DHh + dbase;
    #pragma unroll
    for (int d = 0; d < 32; d += 2) {
        float v0 = acc[d] * inv_l, v1 = acc[d + 1] * inv_l;
        __half h0 = __float2half(v0), h1 = __float2half(v1);
        *(unsigned*)(chi + obase + d) =
            (unsigned)__half_as_ushort(h0) | ((unsigned)__half_as_ushort(h1) << 16);
        *(unsigned*)(clo + obase + d) =
            pack2h(v0 - __half2float(h0), v1 - __half2float(h1));
    }
}

// ---------------- CLS extraction + norm ----------------
__global__ void cls_kernel() {
    __shared__ float sred[9];
    int b = blockIdx.x;
    float loc = 0.f;
    #pragma unroll
    for (int i = 0; i < 3; i++) {
        int j = threadIdx.x + i * 256;
        float v = g_x[(size_t)(b * Ss) * Hh + j];
        g_cls[b * Hh + j] = v;
        loc += v * v;
    }
    float s = blk_sum256(loc, sred);
    if (threadIdx.x == 0) g_cn[b] = fmaxf(sqrtf(s), EPS_COS);
}

__global__ void reset_best_kernel() {
    if (threadIdx.x < Bb) g_best[threadIdx.x] = 0ull;
}

// ---------------- cosine + per-block argmax reduction ----------------
__global__ void __launch_bounds__(128) cos_kernel(const float* __restrict__ lab,
                                                  float* __restrict__ out) {
    __shared__ float clsS[Bb][33];
    __shared__ float sInvCn[Bb];
    int l = blockIdx.x * 128 + threadIdx.x;
    bool valid = (l < NLl);
    if (threadIdx.x < Bb) sInvCn[threadIdx.x] = 1.0f / g_cn[threadIdx.x];

    float acc[Bb];
    #pragma unroll
    for (int bb = 0; bb < Bb; bb++) acc[bb] = 0.f;

    for (int k0 = 0; k0 < Hh; k0 += 32) {
        #pragma unroll
        for (int i = 0; i < 8; i++) {
            int idx = threadIdx.x + i * 128;
            int bb = idx >> 5, kk = idx & 31;
            clsS[bb][kk] = g_cls[bb * Hh + k0 + kk];
        }
        __syncthreads();
        if (valid) {
            float lv[32];
            const float4* lp = (const float4*)(lab + (size_t)l * Hh + k0);
            #pragma unroll
            for (int i = 0; i < 8; i++) {
                float4 v4 = lp[i];
                lv[i * 4] = v4.x; lv[i * 4 + 1] = v4.y; lv[i * 4 + 2] = v4.z; lv[i * 4 + 3] = v4.w;
            }
            #pragma unroll
            for (int bb = 0; bb < Bb; bb++) {
                float a = acc[bb];
                #pragma unroll
                for (int kk = 0; kk < 32; kk++) a = fmaf(clsS[bb][kk], lv[kk], a);
                acc[bb] = a;
            }
        }
        __syncthreads();
    }

    float invl = 0.f;
    if (valid) {
        float s = 0.f;
        const float4* lp = (const float4*)(lab + (size_t)l * Hh);
        #pragma unroll 4
        for (int i = 0; i < Hh / 4; i++) {
            float4 v4 = lp[i];
            s += v4.x * v4.x + v4.y * v4.y + v4.z * v4.z + v4.w * v4.w;
        }
        invl = 1.0f / fmaxf(sqrtf(s), EPS_COS);
    }

    int lane = threadIdx.x & 31;
    #pragma unroll 1
    for (int bb = 0; bb < Bb; bb++) {
        unsigned long long key = 0ull;
        if (valid) {
            float c = acc[bb] * invl * sInvCn[bb];
            out[(size_t)bb * NLl + l] = c;
            key = pack_key(c, l);
        }
        #pragma unroll
        for (int o = 16; o > 0; o >>= 1) {
            unsigned long long other = __shfl_down_sync(0xffffffffu, key, o);
            key = (other > key) ? other : key;
        }
        if (lane == 0) atomicMax(&g_best[bb], key);
    }
}

__global__ void ids_out_kernel(float* __restrict__ out) {
    int b = threadIdx.x;
    if (b < Bb) {
        unsigned idpart = (unsigned)(g_best[b] & 0xFFFFFFFFull);
        out[(size_t)Bb * NLl + b] = (float)(0xFFFFFFFFu - idpart);
    }
}

// ---------------- host orchestration ----------------
extern "C" void kernel_launch(void* const* d_in, const int* in_sizes, int n_in,
                              void* d_out, int out_size) {
    const int*   ids  = (const int*)d_in[0];
    const int*   tys  = (const int*)d_in[1];
    const float* word = (const float*)d_in[2];
    const float* pos  = (const float*)d_in[3];
    const float* typ  = (const float*)d_in[4];
    const float* eg   = (const float*)d_in[5];
    const float* eb   = (const float*)d_in[6];
    const float* Wq   = (const float*)d_in[7];
    const float* bq   = (const float*)d_in[8];
    const float* Wk   = (const float*)d_in[9];
    const float* bk   = (const float*)d_in[10];
    const float* Wv   = (const float*)d_in[11];
    const float* bv   = (const float*)d_in[12];
    const float* Wo   = (const float*)d_in[13];
    const float* bo   = (const float*)d_in[14];
    const float* g1   = (const float*)d_in[15];
    const float* be1  = (const float*)d_in[16];
    const float* W1   = (const float*)d_in[17];
    const float* b1   = (const float*)d_in[18];
    const float* W2   = (const float*)d_in[19];
    const float* b2   = (const float*)d_in[20];
    const float* g2   = (const float*)d_in[21];
    const float* be2  = (const float*)d_in[22];
    const float* lab  = (const float*)d_in[23];
    float* out = (float*)d_out;

    float *px, *py, *py2, *pqkv, *pmbias, *pbqkv;
    __half *pxhi, *pchi, *pclo, *phhi, *phlo, *pwth;
    cudaGetSymbolAddress((void**)&px,    g_x);
    cudaGetSymbolAddress((void**)&py,    g_y);
    cudaGetSymbolAddress((void**)&py2,   g_y2);
    cudaGetSymbolAddress((void**)&pqkv,  g_qkv);
    cudaGetSymbolAddress((void**)&pmbias,g_mbias);
    cudaGetSymbolAddress((void**)&pbqkv, g_bqkv);
    cudaGetSymbolAddress((void**)&pxhi,  g_xhi);
    cudaGetSymbolAddress((void**)&pchi,  g_chi);
    cudaGetSymbolAddress((void**)&pclo,  g_clo);
    cudaGetSymbolAddress((void**)&phhi,  g_hhi);
    cudaGetSymbolAddress((void**)&phlo,  g_hlo);
    cudaGetSymbolAddress((void**)&pwth,  g_wth);

    cudaFuncSetAttribute(attn_kernel, cudaFuncAttributeMaxDynamicSharedMemorySize, ATTN_SMEM);
    cudaFuncSetAttribute(gemm_mma<0, 1>, cudaFuncAttributeMaxDynamicSharedMemorySize, GSMEM);
    cudaFuncSetAttribute(gemm_mma<0, 2>, cudaFuncAttributeMaxDynamicSharedMemorySize, GSMEM);
    cudaFuncSetAttribute(gemm_mma<1, 1>, cudaFuncAttributeMaxDynamicSharedMemorySize, GSMEM);

    dim3 tb(32, 8);
    wsplit4_kernel<<<dim3(24, 24, 48), tb>>>(Wq, Wk, Wv, Wo);                 // 1
    embed_ln_kernel<<<NTOK, 256>>>(ids, tys, word, pos, typ, eg, eb);         // 2
    pack_bias_kernel<<<Ll, Hh>>>(bq, bk, bv);                                 // 3

    for (int l = 0; l < Ll; l++) {
        size_t wl = (size_t)l * LSTRIDE;
        // QKV: 1-term (activation fp16-hi only)
        gemm_mma<0, 1><<<dim3(QKVN / 128, 32, 1), 256, GSMEM>>>(              // 4 on l==0
            pxhi, nullptr, pwth + wl, pbqkv + l * QKVN,
            pqkv, nullptr, nullptr, nullptr, Hh, Hh, QKVN);
        attn_kernel<<<Bb * NHh, 256, ATTN_SMEM>>>(pqkv, pmbias, pchi, pclo);
        if (l == 0) {
            wsplit_kernel<<<dim3(FFf / 32, Hh / 32, Ll), tb>>>(W1, OFF_W1, Hh, FFf);
            wsplit_kernel<<<dim3(Hh / 32, FFf / 32, Ll), tb>>>(W2, OFF_W2, FFf, Hh);
        }
        // O projection: 2-term, split-K=2
        gemm_mma<0, 2><<<dim3(Hh / 128, 32, 2), 256, GSMEM>>>(
            pchi, pclo, pwth + wl + OFF_O, bo + (size_t)l * Hh,
            py, py2, nullptr, nullptr, Hh, Hh / 2, Hh);
        add_ln3_kernel<<<NTOK, 256>>>(px, py, py2,
                                      g1 + (size_t)l * Hh, be1 + (size_t)l * Hh);
        // FFN up + GELU: 1-term
        gemm_mma<1, 1><<<dim3(FFf / 128, 32, 1), 256, GSMEM>>>(
            pxhi, nullptr, pwth + wl + OFF_W1, b1 + (size_t)l * FFf,
            nullptr, nullptr, phhi, phlo, Hh, Hh, FFf);
        // FFN down: 2-term, split-K=2
        gemm_mma<0, 2><<<dim3(Hh / 128, 32, 2), 256, GSMEM>>>(
            phhi, phlo, pwth + wl + OFF_W2, b2 + (size_t)l * Hh,
            py, py2, nullptr, nullptr, FFf, FFf / 2, Hh);
        add_ln3_kernel<<<NTOK, 256>>>(px, py, py2,
                                      g2 + (size_t)l * Hh, be2 + (size_t)l * Hh);
    }

    cls_kernel<<<Bb, 256>>>();
    reset_best_kernel<<<1, 32>>>();
    cos_kernel<<<(NLl + 127) / 128, 128>>>(lab, out);
    if (out_size >= Bb * NLl + Bb) ids_out_kernel<<<1, 32>>>(out);
}

// round 13
// speedup vs baseline: 1.8018x; 1.2616x over previous
#include <cuda_runtime.h>
#include <cuda_fp16.h>
#include <math.h>
#include <cstdint>

// ---------------- problem constants ----------------
#define Vv   30522
#define Hh   768
#define Ll   12
#define FFf  3072
#define NHh  12
#define DHh  64
#define Bb   32
#define Ss   128
#define NLl  10000
#define NTOK (Bb*Ss)          // 4096
#define QKVN (3*Hh)           // 2304
#define EPS_LN  1e-12f
#define EPS_COS 1e-8f

// transposed fp16 weight layout per layer (element offsets)
#define OFF_O   (QKVN*Hh)             // after packed qkv [2304][768]
#define OFF_W1  (OFF_O + Hh*Hh)       // [3072][768]
#define OFF_W2  (OFF_W1 + Hh*FFf)     // [768][3072]
#define LSTRIDE (OFF_W2 + FFf*Hh)     // 7,077,888

// ---------------- device scratch ----------------
__device__ __half g_wth[Ll*LSTRIDE];           // fp16 weights, transposed [N][K]
__device__ float  g_bqkv[Ll*QKVN];
__device__ float  g_zeros[Hh];                 // stays zero (module-load zero-init)

__device__ float  g_x  [NTOK*Hh];
__device__ __half g_xhi[NTOK*Hh];
__device__ float  g_qkv[NTOK*QKVN];
__device__ __half g_chi[NTOK*Hh];
__device__ __half g_hhi[NTOK*FFf];
__device__ float  g_y  [NTOK*Hh];
__device__ float  g_y2 [NTOK*Hh];
__device__ float g_mbias[NTOK];
__device__ float g_cls[Bb*Hh];
__device__ float g_cn [Bb];
__device__ unsigned long long g_best[Bb];

// ---------------- PTX helpers (compute_100-safe) ----------------
__device__ __forceinline__ uint32_t smem_u32(const void* p) {
    uint32_t a;
    asm("{ .reg .u64 t; cvta.to.shared.u64 t, %1; cvt.u32.u64 %0, t; }" : "=r"(a) : "l"(p));
    return a;
}
__device__ __forceinline__ void cp_async16(uint32_t dst, const void* src) {
    asm volatile("cp.async.cg.shared.global [%0], [%1], 16;" :: "r"(dst), "l"(src) : "memory");
}
#define CP_COMMIT() asm volatile("cp.async.commit_group;" ::: "memory")
#define CP_WAIT(n)  asm volatile("cp.async.wait_group %0;" :: "n"(n) : "memory")

__device__ __forceinline__ void ldsm4(uint32_t& r0, uint32_t& r1, uint32_t& r2, uint32_t& r3,
                                      uint32_t addr) {
    asm volatile("ldmatrix.sync.aligned.m8n8.x4.shared.b16 {%0,%1,%2,%3}, [%4];"
                 : "=r"(r0), "=r"(r1), "=r"(r2), "=r"(r3) : "r"(addr));
}
__device__ __forceinline__ void mma16816(float* c, uint32_t a0, uint32_t a1, uint32_t a2,
                                         uint32_t a3, uint32_t b0, uint32_t b1) {
    asm volatile(
        "mma.sync.aligned.m16n8k16.row.col.f32.f16.f16.f32 "
        "{%0,%1,%2,%3}, {%4,%5,%6,%7}, {%8,%9}, {%0,%1,%2,%3};"
        : "+f"(c[0]), "+f"(c[1]), "+f"(c[2]), "+f"(c[3])
        : "r"(a0), "r"(a1), "r"(a2), "r"(a3), "r"(b0), "r"(b1));
}

// ---------------- misc helpers ----------------
__device__ __forceinline__ float blk_sum256(float v, volatile float* sred) {
    int lane = threadIdx.x & 31, w = threadIdx.x >> 5;
    #pragma unroll
    for (int o = 16; o > 0; o >>= 1) v += __shfl_down_sync(0xffffffffu, v, o);
    if (lane == 0) sred[w] = v;
    __syncthreads();
    if (threadIdx.x == 0) {
        float s = 0.f;
        #pragma unroll
        for (int i = 0; i < 8; i++) s += sred[i];
        sred[8] = s;
    }
    __syncthreads();
    float r = sred[8];
    __syncthreads();
    return r;
}
__device__ __forceinline__ float gelu_tanh(float x) {
    float x3 = x * x * x;
    float t = tanhf(0.7978845608028654f * (x + 0.044715f * x3));
    return 0.5f * x * (1.0f + t);
}
__device__ __forceinline__ unsigned long long pack_key(float c, int l) {
    unsigned u = __float_as_uint(c);
    u = (u & 0x80000000u) ? ~u : (u | 0x80000000u);
    return ((unsigned long long)u << 32) | (unsigned long long)(0xFFFFFFFFu - (unsigned)l);
}
__device__ __forceinline__ unsigned pack2h(float v0, float v1) {
    __half h0 = __float2half(v0), h1 = __float2half(v1);
    return (unsigned)__half_as_ushort(h0) | ((unsigned)__half_as_ushort(h1) << 16);
}

// ---------------- weight transpose to fp16 ----------------
__global__ void wsplit4_kernel(const float* __restrict__ W0, const float* __restrict__ W1m,
                               const float* __restrict__ W2m, const float* __restrict__ W3m) {
    __shared__ float t[32][33];
    int z = blockIdx.z;
    int m = z & 3, l = z >> 2;
    const float* Ws = (m == 0 ? W0 : m == 1 ? W1m : m == 2 ? W2m : W3m) + (size_t)l * Hh * Hh;
    long dstOff = (m < 3) ? (long)m * Hh * Hh : (long)OFF_O;
    __half* th = g_wth + (size_t)l * LSTRIDE + dstOff;
    int n = blockIdx.x * 32 + threadIdx.x;
    #pragma unroll
    for (int i = 0; i < 4; i++) {
        int k = blockIdx.y * 32 + threadIdx.y + i * 8;
        t[threadIdx.y + i * 8][threadIdx.x] = Ws[(size_t)k * Hh + n];
    }
    __syncthreads();
    int k2 = blockIdx.y * 32 + threadIdx.x;
    #pragma unroll
    for (int i = 0; i < 4; i++) {
        int n2 = blockIdx.x * 32 + threadIdx.y + i * 8;
        th[(size_t)n2 * Hh + k2] = __float2half(t[threadIdx.x][threadIdx.y + i * 8]);
    }
}

__global__ void wsplit_kernel(const float* __restrict__ W, long dstOff, int K, int N) {
    __shared__ float t[32][33];
    int l = blockIdx.z;
    const float* Ws = W + (size_t)l * K * N;
    __half* th = g_wth + (size_t)l * LSTRIDE + dstOff;
    int n = blockIdx.x * 32 + threadIdx.x;
    #pragma unroll
    for (int i = 0; i < 4; i++) {
        int k = blockIdx.y * 32 + threadIdx.y + i * 8;
        t[threadIdx.y + i * 8][threadIdx.x] = Ws[(size_t)k * N + n];
    }
    __syncthreads();
    int k2 = blockIdx.y * 32 + threadIdx.x;
    #pragma unroll
    for (int i = 0; i < 4; i++) {
        int n2 = blockIdx.x * 32 + threadIdx.y + i * 8;
        th[(size_t)n2 * K + k2] = __float2half(t[threadIdx.x][threadIdx.y + i * 8]);
    }
}

__global__ void pack_bias_kernel(const float* __restrict__ bq, const float* __restrict__ bk,
                                 const float* __restrict__ bv) {
    int l = blockIdx.x, j = threadIdx.x;
    g_bqkv[l * QKVN + j]          = bq[l * Hh + j];
    g_bqkv[l * QKVN + Hh + j]     = bk[l * Hh + j];
    g_bqkv[l * QKVN + 2 * Hh + j] = bv[l * Hh + j];
}

// ---------------- embeddings + LN + mask bias ----------------
__global__ void embed_ln_kernel(const int* __restrict__ ids, const int* __restrict__ tys,
                                const float* __restrict__ word, const float* __restrict__ pos,
                                const float* __restrict__ typ,
                                const float* __restrict__ eg, const float* __restrict__ eb) {
    __shared__ float sred[9];
    int t = blockIdx.x;
    int s = t & (Ss - 1);
    int id = ids[t], ty = tys[t];
    float v[3];
    float loc = 0.f;
    #pragma unroll
    for (int i = 0; i < 3; i++) {
        int j = threadIdx.x + i * 256;
        v[i] = word[(size_t)id * Hh + j] + pos[(size_t)s * Hh + j] + typ[(size_t)ty * Hh + j];
        loc += v[i];
    }
    float mu = blk_sum256(loc, sred) * (1.0f / Hh);
    float l2 = 0.f;
    #pragma unroll
    for (int i = 0; i < 3; i++) { float d = v[i] - mu; l2 += d * d; }
    float var = blk_sum256(l2, sred) * (1.0f / Hh);
    float rstd = rsqrtf(var + EPS_LN);
    #pragma unroll
    for (int i = 0; i < 3; i++) {
        int j = threadIdx.x + i * 256;
        size_t idx = (size_t)t * Hh + j;
        float o = (v[i] - mu) * rstd * eg[j] + eb[j];
        g_x[idx] = o;
        g_xhi[idx] = __float2half(o);
    }
    if (threadIdx.x == 0) g_mbias[t] = (id > 0) ? 0.f : -10000.0f;
}

// ---------------- residual add (3-way) + LN (in place on x) ----------------
__global__ void add_ln3_kernel(float* __restrict__ x, const float* __restrict__ y,
                               const float* __restrict__ y2,
                               const float* __restrict__ g, const float* __restrict__ b) {
    __shared__ float sred[9];
    size_t base = (size_t)blockIdx.x * Hh;
    float v[3];
    float loc = 0.f;
    #pragma unroll
    for (int i = 0; i < 3; i++) {
        int j = threadIdx.x + i * 256;
        v[i] = x[base + j] + y[base + j] + y2[base + j];
        loc += v[i];
    }
    float mu = blk_sum256(loc, sred) * (1.0f / Hh);
    float l2 = 0.f;
    #pragma unroll
    for (int i = 0; i < 3; i++) { float d = v[i] - mu; l2 += d * d; }
    float var = blk_sum256(l2, sred) * (1.0f / Hh);
    float rstd = rsqrtf(var + EPS_LN);
    #pragma unroll
    for (int i = 0; i < 3; i++) {
        int j = threadIdx.x + i * 256;
        float o = (v[i] - mu) * rstd * g[j] + b[j];
        x[base + j] = o;
        g_xhi[base + j] = __float2half(o);
    }
}

// ---------------- HMMA fp16 GEMM: C[4096, N] = Ah @ Bh^T + bias ----------------
// K-split via gridDim.z (OUTMODE 0): z=0 -> Cf with bias, z=1 -> Cf2 zero-bias.
// OUTMODE 1: gelu -> fp16 out. CTA 128x128, K-chunk 64 (rows 144B), 2-stage
// cp.async, 8 warps, 2 CTAs/SM.
#define GT_ROW   144
#define GT_TILE  (128 * GT_ROW)        // 18432 B per sub-tile
#define GT_STAGE (2 * GT_TILE)         // Ah | Bh = 36864
#define GSMEM    (2 * GT_STAGE)        // 73728
template <int OUTMODE>
__global__ void __launch_bounds__(256, 2) gemm_mma(
    const __half* __restrict__ Ahi,
    const __half* __restrict__ Bh,
    const float* __restrict__ bias,
    float* __restrict__ Cf, float* __restrict__ Cf2,
    __half* __restrict__ Chi,
    int Kfull, int Klen, int ldc)
{
    extern __shared__ char sm[];
    const uint32_t sb = smem_u32(sm);
    int tid = threadIdx.x, lane = tid & 31, wid = tid >> 5;
    int wm = wid >> 2, wn = wid & 3;              // warp tile rows wm*64, cols wn*32
    int m0 = blockIdx.y * 128, n0 = blockIdx.x * 128;
    int kz = blockIdx.z;
    int kbase = kz * Klen;
    const float* bsel = (OUTMODE == 0 && kz) ? g_zeros : bias;
    float* csel = (OUTMODE == 0 && kz) ? Cf2 : Cf;

    // ldmatrix lane offsets (row stride 144B)
    int q = lane >> 3, r = lane & 7;
    uint32_t aLane = (uint32_t)(((q & 1) * 8 + r) * GT_ROW + (q >> 1) * 16);
    uint32_t bLane = (uint32_t)(((q >> 1) * 8 + r) * GT_ROW + (q & 1) * 16);

    float acc[4][4][4];
    #pragma unroll
    for (int mi = 0; mi < 4; mi++)
        #pragma unroll
        for (int ni = 0; ni < 4; ni++)
            #pragma unroll
            for (int e = 0; e < 4; e++) acc[mi][ni][e] = 0.f;

    int nchunk = Klen >> 6;                       // K-chunk = 64

    // loader: 2 tiles x 128 rows x 8 segs of 16B = 2048 cp.async; 8 per thread
    auto load_stage = [&](int c) {
        int k0 = kbase + (c << 6);
        uint32_t base = sb + (uint32_t)(c & 1) * GT_STAGE;
        #pragma unroll
        for (int i = 0; i < 8; i++) {
            int lin = tid + i * 256;              // 0..2047
            int tsel = lin >> 10;                 // 0=Ah 1=Bh
            int within = lin & 1023;
            int row = within >> 3, seg = within & 7;
            const __half* src = (tsel == 0)
                ? Ahi + (size_t)(m0 + row) * Kfull + k0 + seg * 8
                : Bh  + (size_t)(n0 + row) * Kfull + k0 + seg * 8;
            cp_async16(base + (uint32_t)tsel * GT_TILE + (uint32_t)(row * GT_ROW + seg * 16),
                       src);
        }
    };

    load_stage(0);
    CP_COMMIT();

    for (int c = 0; c < nchunk; c++) {
        if (c + 1 < nchunk) { load_stage(c + 1); CP_COMMIT(); CP_WAIT(1); }
        else { CP_WAIT(0); }
        __syncthreads();

        uint32_t base = sb + (uint32_t)(c & 1) * GT_STAGE;
        uint32_t aBase = base + (uint32_t)((wm * 64) * GT_ROW) + aLane;
        uint32_t bBase = base + GT_TILE + (uint32_t)((wn * 32) * GT_ROW) + bLane;

        #pragma unroll
        for (int ks = 0; ks < 4; ks++) {
            uint32_t ko = (uint32_t)(ks * 32);
            uint32_t ah[4][4], bf[2][4];
            #pragma unroll
            for (int p = 0; p < 2; p++)
                ldsm4(bf[p][0], bf[p][1], bf[p][2], bf[p][3],
                      bBase + (uint32_t)(p * 16 * GT_ROW) + ko);
            #pragma unroll
            for (int mi = 0; mi < 4; mi++)
                ldsm4(ah[mi][0], ah[mi][1], ah[mi][2], ah[mi][3],
                      aBase + (uint32_t)(mi * 16 * GT_ROW) + ko);
            #pragma unroll
            for (int mi = 0; mi < 4; mi++)
                #pragma unroll
                for (int ni = 0; ni < 4; ni++) {
                    int p = ni >> 1, su = ni & 1;
                    mma16816(acc[mi][ni], ah[mi][0], ah[mi][1], ah[mi][2], ah[mi][3],
                             bf[p][su * 2], bf[p][su * 2 + 1]);
                }
        }
        __syncthreads();
    }

    // ---------------- epilogue ----------------
    int rbase = m0 + wm * 64 + (lane >> 2);
    int cbase = n0 + wn * 32 + (lane & 3) * 2;
    #pragma unroll
    for (int mi = 0; mi < 4; mi++) {
        #pragma unroll
        for (int ni = 0; ni < 4; ni++) {
            int row = rbase + mi * 16;
            int col = cbase + ni * 8;
            float b0 = bsel[col], b1 = bsel[col + 1];
            float v0 = acc[mi][ni][0] + b0, v1 = acc[mi][ni][1] + b1;
            float v2 = acc[mi][ni][2] + b0, v3 = acc[mi][ni][3] + b1;
            if (OUTMODE == 0) {
                *(float2*)(csel + (size_t)row * ldc + col)       = make_float2(v0, v1);
                *(float2*)(csel + (size_t)(row + 8) * ldc + col) = make_float2(v2, v3);
            } else {
                *(unsigned*)(Chi + (size_t)row * ldc + col) =
                    pack2h(gelu_tanh(v0), gelu_tanh(v1));
                *(unsigned*)(Chi + (size_t)(row + 8) * ldc + col) =
                    pack2h(gelu_tanh(v2), gelu_tanh(v3));
            }
        }
    }
}

// ---------------- attention: 256 threads, split j-range (QK) and d-range (PV) ----------------
#define ATTN_SMEM ((2*Ss*DHh + Ss*129 + Ss + 2*256) * (int)sizeof(float))
__global__ void __launch_bounds__(256) attn_kernel(const float* __restrict__ Qkv,
                                                   const float* __restrict__ bias,
                                                   __half* __restrict__ chi) {
    extern __shared__ float smf[];
    float* Ks = smf;                        // [128][64]
    float* Vs = smf + Ss * DHh;             // [128][64]
    float* S  = smf + 2 * Ss * DHh;         // [128][129]
    float* biasS = S + Ss * 129;            // [128]
    float* pm = biasS + Ss;                 // [256]
    float* ps = pm + 256;                   // [256]
    int bn = blockIdx.x;
    int b = bn / NHh, n = bn % NHh;
    int tid = threadIdx.x;
    int qi = tid & 127, h = tid >> 7;
    const float scale = 0.125f;

    #pragma unroll
    for (int i = 0; i < 8; i++) {
        int lin = tid + i * 256;
        int j = lin >> 4, c4 = (lin & 15) * 4;
        size_t rowb = (size_t)(b * Ss + j) * QKVN + n * DHh + c4;
        *(float4*)&Ks[j * DHh + c4] = *(const float4*)(Qkv + rowb + Hh);
        *(float4*)&Vs[j * DHh + c4] = *(const float4*)(Qkv + rowb + 2 * Hh);
    }
    if (tid < Ss) biasS[tid] = bias[b * Ss + tid];
    __syncthreads();

    float Qr[DHh];
    const float4* qp = (const float4*)(Qkv + (size_t)(b * Ss + qi) * QKVN + n * DHh);
    #pragma unroll
    for (int i = 0; i < 16; i++) {
        float4 v4 = qp[i];
        Qr[i * 4 + 0] = v4.x; Qr[i * 4 + 1] = v4.y; Qr[i * 4 + 2] = v4.z; Qr[i * 4 + 3] = v4.w;
    }

    float* Srow = S + qi * 129;
    int jbase = h * 64;
    float m = -1e30f;
    #pragma unroll 1
    for (int jj = 0; jj < 64; jj += 4) {
        int j = jbase + jj;
        const float4* k0 = (const float4*)(Ks + j * DHh);
        float s0 = 0.f, s1 = 0.f, s2 = 0.f, s3 = 0.f;
        #pragma unroll
        for (int i = 0; i < 16; i++) {
            float4 kv0 = k0[i];
            float4 kv1 = k0[16 + i];
            float4 kv2 = k0[32 + i];
            float4 kv3 = k0[48 + i];
            float q0 = Qr[i * 4], q1 = Qr[i * 4 + 1], q2 = Qr[i * 4 + 2], q3 = Qr[i * 4 + 3];
            s0 = fmaf(q0, kv0.x, s0); s0 = fmaf(q1, kv0.y, s0);
            s0 = fmaf(q2, kv0.z, s0); s0 = fmaf(q3, kv0.w, s0);
            s1 = fmaf(q0, kv1.x, s1); s1 = fmaf(q1, kv1.y, s1);
            s1 = fmaf(q2, kv1.z, s1); s1 = fmaf(q3, kv1.w, s1);
            s2 = fmaf(q0, kv2.x, s2); s2 = fmaf(q1, kv2.y, s2);
            s2 = fmaf(q2, kv2.z, s2); s2 = fmaf(q3, kv2.w, s2);
            s3 = fmaf(q0, kv3.x, s3); s3 = fmaf(q1, kv3.y, s3);
            s3 = fmaf(q2, kv3.z, s3); s3 = fmaf(q3, kv3.w, s3);
        }
        s0 = fmaf(s0, scale, biasS[j]);
        s1 = fmaf(s1, scale, biasS[j + 1]);
        s2 = fmaf(s2, scale, biasS[j + 2]);
        s3 = fmaf(s3, scale, biasS[j + 3]);
        Srow[j] = s0; Srow[j + 1] = s1; Srow[j + 2] = s2; Srow[j + 3] = s3;
        m = fmaxf(m, fmaxf(fmaxf(s0, s1), fmaxf(s2, s3)));
    }
    pm[h * 128 + qi] = m;
    __syncthreads();
    m = fmaxf(pm[qi], pm[128 + qi]);

    float ls = 0.f;
    #pragma unroll 4
    for (int jj = 0; jj < 64; jj++) {
        int j = jbase + jj;
        float p = __expf(Srow[j] - m);
        Srow[j] = p;
        ls += p;
    }
    ps[h * 128 + qi] = ls;
    __syncthreads();
    float inv_l = 1.0f / (ps[qi] + ps[128 + qi]);

    int dbase = h * 32;
    float acc[32];
    #pragma unroll
    for (int d = 0; d < 32; d++) acc[d] = 0.f;
    #pragma unroll 1
    for (int j = 0; j < Ss; j++) {
        float p = Srow[j];
        const float4* vr = (const float4*)(Vs + j * DHh + dbase);
        #pragma unroll
        for (int i = 0; i < 8; i++) {
            float4 v4 = vr[i];
            acc[i * 4 + 0] = fmaf(p, v4.x, acc[i * 4 + 0]);
            acc[i * 4 + 1] = fmaf(p, v4.y, acc[i * 4 + 1]);
            acc[i * 4 + 2] = fmaf(p, v4.z, acc[i * 4 + 2]);
            acc[i * 4 + 3] = fmaf(p, v4.w, acc[i * 4 + 3]);
        }
    }
    size_t obase = (size_t)(b * Ss + qi) * Hh + n * DHh + dbase;
    #pragma unroll
    for (int d = 0; d < 32; d += 2) {
        *(unsigned*)(chi + obase + d) = pack2h(acc[d] * inv_l, acc[d + 1] * inv_l);
    }
}

// ---------------- CLS extraction + norm ----------------
__global__ void cls_kernel() {
    __shared__ float sred[9];
    int b = blockIdx.x;
    float loc = 0.f;
    #pragma unroll
    for (int i = 0; i < 3; i++) {
        int j = threadIdx.x + i * 256;
        float v = g_x[(size_t)(b * Ss) * Hh + j];
        g_cls[b * Hh + j] = v;
        loc += v * v;
    }
    float s = blk_sum256(loc, sred);
    if (threadIdx.x == 0) g_cn[b] = fmaxf(sqrtf(s), EPS_COS);
}

__global__ void reset_best_kernel() {
    if (threadIdx.x < Bb) g_best[threadIdx.x] = 0ull;
}

// ---------------- cosine + per-block argmax reduction ----------------
__global__ void __launch_bounds__(128) cos_kernel(const float* __restrict__ lab,
                                                  float* __restrict__ out) {
    __shared__ float clsS[Bb][33];
    __shared__ float sInvCn[Bb];
    int l = blockIdx.x * 128 + threadIdx.x;
    bool valid = (l < NLl);
    if (threadIdx.x < Bb) sInvCn[threadIdx.x] = 1.0f / g_cn[threadIdx.x];

    float acc[Bb];
    #pragma unroll
    for (int bb = 0; bb < Bb; bb++) acc[bb] = 0.f;

    for (int k0 = 0; k0 < Hh; k0 += 32) {
        #pragma unroll
        for (int i = 0; i < 8; i++) {
            int idx = threadIdx.x + i * 128;
            int bb = idx >> 5, kk = idx & 31;
            clsS[bb][kk] = g_cls[bb * Hh + k0 + kk];
        }
        __syncthreads();
        if (valid) {
            float lv[32];
            const float4* lp = (const float4*)(lab + (size_t)l * Hh + k0);
            #pragma unroll
            for (int i = 0; i < 8; i++) {
                float4 v4 = lp[i];
                lv[i * 4] = v4.x; lv[i * 4 + 1] = v4.y; lv[i * 4 + 2] = v4.z; lv[i * 4 + 3] = v4.w;
            }
            #pragma unroll
            for (int bb = 0; bb < Bb; bb++) {
                float a = acc[bb];
                #pragma unroll
                for (int kk = 0; kk < 32; kk++) a = fmaf(clsS[bb][kk], lv[kk], a);
                acc[bb] = a;
            }
        }
        __syncthreads();
    }

    float invl = 0.f;
    if (valid) {
        float s = 0.f;
        const float4* lp = (const float4*)(lab + (size_t)l * Hh);
        #pragma unroll 4
        for (int i = 0; i < Hh / 4; i++) {
            float4 v4 = lp[i];
            s += v4.x * v4.x + v4.y * v4.y + v4.z * v4.z + v4.w * v4.w;
        }
        invl = 1.0f / fmaxf(sqrtf(s), EPS_COS);
    }

    int lane = threadIdx.x & 31;
    #pragma unroll 1
    for (int bb = 0; bb < Bb; bb++) {
        unsigned long long key = 0ull;
        if (valid) {
            float c = acc[bb] * invl * sInvCn[bb];
            out[(size_t)bb * NLl + l] = c;
            key = pack_key(c, l);
        }
        #pragma unroll
        for (int o = 16; o > 0; o >>= 1) {
            unsigned long long other = __shfl_down_sync(0xffffffffu, key, o);
            key = (other > key) ? other : key;
        }
        if (lane == 0) atomicMax(&g_best[bb], key);
    }
}

__global__ void ids_out_kernel(float* __restrict__ out) {
    int b = threadIdx.x;
    if (b < Bb) {
        unsigned idpart = (unsigned)(g_best[b] & 0xFFFFFFFFull);
        out[(size_t)Bb * NLl + b] = (float)(0xFFFFFFFFu - idpart);
    }
}

// ---------------- host orchestration ----------------
extern "C" void kernel_launch(void* const* d_in, const int* in_sizes, int n_in,
                              void* d_out, int out_size) {
    const int*   ids  = (const int*)d_in[0];
    const int*   tys  = (const int*)d_in[1];
    const float* word = (const float*)d_in[2];
    const float* pos  = (const float*)d_in[3];
    const float* typ  = (const float*)d_in[4];
    const float* eg   = (const float*)d_in[5];
    const float* eb   = (const float*)d_in[6];
    const float* Wq   = (const float*)d_in[7];
    const float* bq   = (const float*)d_in[8];
    const float* Wk   = (const float*)d_in[9];
    const float* bk   = (const float*)d_in[10];
    const float* Wv   = (const float*)d_in[11];
    const float* bv   = (const float*)d_in[12];
    const float* Wo   = (const float*)d_in[13];
    const float* bo   = (const float*)d_in[14];
    const float* g1   = (const float*)d_in[15];
    const float* be1  = (const float*)d_in[16];
    const float* W1   = (const float*)d_in[17];
    const float* b1   = (const float*)d_in[18];
    const float* W2   = (const float*)d_in[19];
    const float* b2   = (const float*)d_in[20];
    const float* g2   = (const float*)d_in[21];
    const float* be2  = (const float*)d_in[22];
    const float* lab  = (const float*)d_in[23];
    float* out = (float*)d_out;

    float *px, *py, *py2, *pqkv, *pmbias, *pbqkv;
    __half *pxhi, *pchi, *phhi, *pwth;
    cudaGetSymbolAddress((void**)&px,    g_x);
    cudaGetSymbolAddress((void**)&py,    g_y);
    cudaGetSymbolAddress((void**)&py2,   g_y2);
    cudaGetSymbolAddress((void**)&pqkv,  g_qkv);
    cudaGetSymbolAddress((void**)&pmbias,g_mbias);
    cudaGetSymbolAddress((void**)&pbqkv, g_bqkv);
    cudaGetSymbolAddress((void**)&pxhi,  g_xhi);
    cudaGetSymbolAddress((void**)&pchi,  g_chi);
    cudaGetSymbolAddress((void**)&phhi,  g_hhi);
    cudaGetSymbolAddress((void**)&pwth,  g_wth);

    cudaFuncSetAttribute(attn_kernel, cudaFuncAttributeMaxDynamicSharedMemorySize, ATTN_SMEM);
    cudaFuncSetAttribute(gemm_mma<0>, cudaFuncAttributeMaxDynamicSharedMemorySize, GSMEM);
    cudaFuncSetAttribute(gemm_mma<1>, cudaFuncAttributeMaxDynamicSharedMemorySize, GSMEM);

    dim3 tb(32, 8);
    wsplit4_kernel<<<dim3(24, 24, 48), tb>>>(Wq, Wk, Wv, Wo);                 // 1
    embed_ln_kernel<<<NTOK, 256>>>(ids, tys, word, pos, typ, eg, eb);         // 2
    pack_bias_kernel<<<Ll, Hh>>>(bq, bk, bv);                                 // 3

    for (int l = 0; l < Ll; l++) {
        size_t wl = (size_t)l * LSTRIDE;
        // QKV
        gemm_mma<0><<<dim3(QKVN / 128, 32, 1), 256, GSMEM>>>(                 // 4 on l==0
            pxhi, pwth + wl, pbqkv + l * QKVN,
            pqkv, nullptr, nullptr, Hh, Hh, QKVN);
        attn_kernel<<<Bb * NHh, 256, ATTN_SMEM>>>(pqkv, pmbias, pchi);
        if (l == 0) {
            wsplit_kernel<<<dim3(FFf / 32, Hh / 32, Ll), tb>>>(W1, OFF_W1, Hh, FFf);
            wsplit_kernel<<<dim3(Hh / 32, FFf / 32, Ll), tb>>>(W2, OFF_W2, FFf, Hh);
        }
        // O projection: split-K=2
        gemm_mma<0><<<dim3(Hh / 128, 32, 2), 256, GSMEM>>>(
            pchi, pwth + wl + OFF_O, bo + (size_t)l * Hh,
            py, py2, nullptr, Hh, Hh / 2, Hh);
        add_ln3_kernel<<<NTOK, 256>>>(px, py, py2,
                                      g1 + (size_t)l * Hh, be1 + (size_t)l * Hh);
        // FFN up + GELU
        gemm_mma<1><<<dim3(FFf / 128, 32, 1), 256, GSMEM>>>(
            pxhi, pwth + wl + OFF_W1, b1 + (size_t)l * FFf,
            nullptr, nullptr, phhi, Hh, Hh, FFf);
        // FFN down: split-K=2
        gemm_mma<0><<<dim3(Hh / 128, 32, 2), 256, GSMEM>>>(
            phhi, pwth + wl + OFF_W2, b2 + (size_t)l * Hh,
            py, py2, nullptr, FFf, FFf / 2, Hh);
        add_ln3_kernel<<<NTOK, 256>>>(px, py, py2,
                                      g2 + (size_t)l * Hh, be2 + (size_t)l * Hh);
    }

    cls_kernel<<<Bb, 256>>>();
    reset_best_kernel<<<1, 32>>>();
    cos_kernel<<<(NLl + 127) / 128, 128>>>(lab, out);
    if (out_size >= Bb * NLl + Bb) ids_out_kernel<<<1, 32>>>(out);
}